// round 4
// baseline (speedup 1.0000x reference)
#include <cuda_runtime.h>
#include <cstdint>

// ---------------------------------------------------------------------------
// Padded layouts: every intermediate is [C][H+2][WP] with a 1-px zero halo.
// Borders are NEVER written; __device__ globals are zero-initialized at load,
// so halos stay zero across graph replays -> no bounds checks anywhere.
// ---------------------------------------------------------------------------
#define NIMG 98
#define PL1 (66 * 100)   // plane for 64x96 (WP=100)
#define PL2 (34 * 52)    // plane for 32x48 (WP=52)

__device__ float g_mvol[NIMG * 64 * PL1];
__device__ float g_x1 [NIMG * 96 * PL1];
__device__ float g_x2 [NIMG * 128 * PL2];
__device__ float g_x3 [NIMG * 128 * PL2];
__device__ float g_x4 [NIMG * 64 * PL2];
__device__ float g_x5 [NIMG * 32 * PL1];

// ---- packed f32x2 helpers (Blackwell: fma.rn.f32x2, 2 FMAs / issue slot) ----
typedef unsigned long long u64;
__device__ __forceinline__ u64 pk2(float lo, float hi) {
  u64 r; asm("mov.b64 %0, {%1, %2};" : "=l"(r) : "f"(lo), "f"(hi)); return r;
}
__device__ __forceinline__ void fma2(u64& d, u64 a, u64 b) {
  asm("fma.rn.f32x2 %0, %1, %2, %0;" : "+l"(d) : "l"(a), "l"(b));
}
__device__ __forceinline__ void unpk2(float& lo, float& hi, u64 v) {
  asm("mov.b64 {%0, %1}, %2;" : "=f"(lo), "=f"(hi) : "l"(v));
}

// ---------------------------------------------------------------------------
// 1) Correlation volume -> padded mvol. n=(b*7+i)*7+j, di=i-3 (x), dj=j-3 (y)
// ---------------------------------------------------------------------------
__global__ void build_mvol_k(const float* __restrict__ f1,
                             const float* __restrict__ f2) {
  int idx = blockIdx.x * blockDim.x + threadIdx.x;
  if (idx >= NIMG * 64 * 64 * 96) return;
  int x = idx % 96;
  int y = (idx / 96) % 64;
  int c = (idx / 6144) % 64;
  int n = idx / (6144 * 64);
  int b = n / 49, d = n % 49;
  int di = d / 7 - 3;
  int dj = d % 7 - 3;
  int yy = y + dj, xx = x + di;
  float v = 0.f;
  if (yy >= 0 && yy < 64 && xx >= 0 && xx < 96) {
    if (c < 32) v = f1[((b * 32 + c) * 64 + y) * 96 + x];
    else        v = f2[((b * 32 + (c - 32)) * 64 + yy) * 96 + xx];
  }
  g_mvol[((size_t)(n * 64 + c)) * PL1 + (y + 1) * 100 + (x + 1)] = v;
}

// ---------------------------------------------------------------------------
// 2) 3x3 s1 conv, f32x2 core. Thread = 4 px (2 packed pairs) x 4 co.
// ---------------------------------------------------------------------------
template <int TW, int H, int W, int WP>
__global__ void __launch_bounds__(8 * TW)
conv3x3_s1_k(const float* __restrict__ in, const float* __restrict__ w,
             float* __restrict__ out, int Cin, int Cout) {
  constexpr int PXG = TW / 4;
  constexpr int NT  = 8 * TW;
  constexpr int RS  = 37;
  constexpr int PLS = 10 * RS;
  constexpr int F4  = (TW + 4) / 4;
  constexpr int PLANE = (H + 2) * WP;

  __shared__ float s_in[8 * PLS];
  __shared__ __align__(16) u64 s_w2[8 * 9 * 16];   // [ci][k][co16] dup {w,w}

  const int tid = threadIdx.x;
  const int cg  = tid / (8 * PXG);      // warp-uniform for both TW=32 and 16
  const int pid = tid % (8 * PXG);
  const int py  = pid / PXG;
  const int pxg = pid % PXG;

  const int tilesX = W / TW;
  const int tx = blockIdx.x % tilesX;
  const int ty = blockIdx.x / tilesX;
  const int n  = blockIdx.z;
  const int coB = blockIdx.y * 16;
  const int y0 = ty * 8, x0 = tx * TW;

  const float* inN = in + (size_t)n * Cin * PLANE;

  u64 acc[4][2];   // [co-sub][pair]: pair0 = px{0,1}, pair1 = px{2,3}
  const u64 z = 0;
#pragma unroll
  for (int q = 0; q < 4; q++) { acc[q][0] = z; acc[q][1] = z; }

  for (int cb = 0; cb < Cin; cb += 8) {
    __syncthreads();
#pragma unroll
    for (int t = tid; t < 8 * 10 * F4; t += NT) {
      int c   = t / (10 * F4);
      int rem = t - c * (10 * F4);
      int r   = rem / F4;
      int q   = rem - r * F4;
      const float4 v = *reinterpret_cast<const float4*>(
          inN + (size_t)(cb + c) * PLANE + (y0 + r) * WP + x0 + 4 * q);
      float* dst = &s_in[c * PLS + r * RS + 4 * q];
      dst[0] = v.x; dst[1] = v.y; dst[2] = v.z; dst[3] = v.w;
    }
    // weights, duplicated {w,w} for packed math
    for (int t = tid; t < 16 * 8 * 9; t += NT) {
      int lco = t & 15;
      int rem = t >> 4;
      int k   = rem % 9;
      int lci = rem / 9;
      float wv = w[((size_t)(coB + lco) * Cin + (cb + lci)) * 9 + k];
      reinterpret_cast<float2*>(s_w2)[(lci * 9 + k) * 16 + lco] =
          make_float2(wv, wv);
    }
    __syncthreads();

#pragma unroll
    for (int ci = 0; ci < 8; ci++) {
#pragma unroll
      for (int ky = 0; ky < 3; ky++) {
        const float* row = &s_in[ci * PLS + (py + ky) * RS + pxg * 4];
        float r0 = row[0], r1 = row[1], r2 = row[2],
              r3 = row[3], r4 = row[4], r5 = row[5];
        u64 pa[3], pb[3];
        pa[0] = pk2(r0, r1); pb[0] = pk2(r2, r3);
        pa[1] = pk2(r1, r2); pb[1] = pk2(r3, r4);
        pa[2] = pb[0];       pb[2] = pk2(r4, r5);
#pragma unroll
        for (int kx = 0; kx < 3; kx++) {
          const u64* wq = &s_w2[(ci * 9 + ky * 3 + kx) * 16 + cg * 4];
          u64 w0 = wq[0], w1 = wq[1], w2 = wq[2], w3 = wq[3];
          fma2(acc[0][0], w0, pa[kx]); fma2(acc[0][1], w0, pb[kx]);
          fma2(acc[1][0], w1, pa[kx]); fma2(acc[1][1], w1, pb[kx]);
          fma2(acc[2][0], w2, pa[kx]); fma2(acc[2][1], w2, pb[kx]);
          fma2(acc[3][0], w3, pa[kx]); fma2(acc[3][1], w3, pb[kx]);
        }
      }
    }
  }

  float* outN = out + (size_t)n * Cout * PLANE;
  const int gy = y0 + py + 1;
#pragma unroll
  for (int q = 0; q < 4; q++) {
    int co = coB + cg * 4 + q;
    float a0, a1, a2, a3;
    unpk2(a0, a1, acc[q][0]);
    unpk2(a2, a3, acc[q][1]);
    float* o = outN + (size_t)co * PLANE + gy * WP + x0 + pxg * 4 + 1;
    o[0] = a0; o[1] = a1; o[2] = a2; o[3] = a3;
  }
}

// ---------------------------------------------------------------------------
// 3) 3x3 s2 conv, f32x2 core. Pairs are output px (p,p+1) -> inputs 2 apart.
// ---------------------------------------------------------------------------
__global__ void __launch_bounds__(128)
conv3x3_s2_k(const float* __restrict__ in, const float* __restrict__ w,
             float* __restrict__ out, int Cin, int Cout) {
  constexpr int RS = 37;
  constexpr int PLS = 17 * RS;

  __shared__ float s_in[8 * PLS];
  __shared__ __align__(16) u64 s_w2[8 * 9 * 16];

  const int tid = threadIdx.x;
  const int cg  = tid >> 5;       // warp-uniform
  const int py  = (tid & 31) >> 2;
  const int pxg = tid & 3;

  const int tx = blockIdx.x % 3;
  const int ty = blockIdx.x / 3;
  const int n  = blockIdx.z;
  const int coB = blockIdx.y * 16;
  const int y0 = ty * 8, x0 = tx * 16;

  const float* inN = in + (size_t)n * Cin * PL1;

  u64 acc[4][2];
#pragma unroll
  for (int q = 0; q < 4; q++) { acc[q][0] = 0; acc[q][1] = 0; }

  for (int cb = 0; cb < Cin; cb += 8) {
    __syncthreads();
#pragma unroll
    for (int c = 0; c < 8; c++) {
      for (int t = tid; t < 17 * 9; t += 128) {
        int r = t / 9;
        int q = t - r * 9;
        const float4 v = *reinterpret_cast<const float4*>(
            inN + (size_t)(cb + c) * PL1 + (2 * y0 + r) * 100 + 2 * x0 + 4 * q);
        float* dst = &s_in[c * PLS + r * RS + 4 * q];
        dst[0] = v.x; dst[1] = v.y; dst[2] = v.z; dst[3] = v.w;
      }
    }
    for (int t = tid; t < 16 * 8 * 9; t += 128) {
      int lco = t & 15;
      int rem = t >> 4;
      int k   = rem % 9;
      int lci = rem / 9;
      float wv = w[((size_t)(coB + lco) * Cin + (cb + lci)) * 9 + k];
      reinterpret_cast<float2*>(s_w2)[(lci * 9 + k) * 16 + lco] =
          make_float2(wv, wv);
    }
    __syncthreads();

#pragma unroll
    for (int ci = 0; ci < 8; ci++) {
#pragma unroll
      for (int ky = 0; ky < 3; ky++) {
        const float* row = &s_in[ci * PLS + (2 * py + ky) * RS + pxg * 8];
        float r0 = row[0], r1 = row[1], r2 = row[2], r3 = row[3], r4 = row[4],
              r5 = row[5], r6 = row[6], r7 = row[7], r8 = row[8];
        // pair (p,p+1): inputs {r[2p+kx], r[2p+2+kx]}
        u64 pa[3], pb[3];
        pa[0] = pk2(r0, r2); pb[0] = pk2(r4, r6);
        pa[1] = pk2(r1, r3); pb[1] = pk2(r5, r7);
        pa[2] = pk2(r2, r4); pb[2] = pk2(r6, r8);
#pragma unroll
        for (int kx = 0; kx < 3; kx++) {
          const u64* wq = &s_w2[(ci * 9 + ky * 3 + kx) * 16 + cg * 4];
          u64 w0 = wq[0], w1 = wq[1], w2 = wq[2], w3 = wq[3];
          fma2(acc[0][0], w0, pa[kx]); fma2(acc[0][1], w0, pb[kx]);
          fma2(acc[1][0], w1, pa[kx]); fma2(acc[1][1], w1, pb[kx]);
          fma2(acc[2][0], w2, pa[kx]); fma2(acc[2][1], w2, pb[kx]);
          fma2(acc[3][0], w3, pa[kx]); fma2(acc[3][1], w3, pb[kx]);
        }
      }
    }
  }

  float* outN = out + (size_t)n * Cout * PL2;
  const int gy = y0 + py + 1;
#pragma unroll
  for (int q = 0; q < 4; q++) {
    int co = coB + cg * 4 + q;
    float a0, a1, a2, a3;
    unpk2(a0, a1, acc[q][0]);
    unpk2(a2, a3, acc[q][1]);
    float* o = outN + (size_t)co * PL2 + gy * 52 + x0 + pxg * 4 + 1;
    o[0] = a0; o[1] = a1; o[2] = a2; o[3] = a3;
  }
}

// ---------------------------------------------------------------------------
// 4) Instance norm + leaky, padded in-place.
// ---------------------------------------------------------------------------
template <int H, int W, int WP>
__global__ void __launch_bounds__(256)
inorm_leaky_k(float* __restrict__ x) {
  constexpr int PLANE = (H + 2) * WP;
  float* p = x + (size_t)blockIdx.x * PLANE;
  const int wid = threadIdx.x >> 5, ln = threadIdx.x & 31;

  float s = 0.f, q = 0.f;
  for (int y = wid; y < H; y += 8)
    for (int xx = ln; xx < W; xx += 32) {
      float v = p[(y + 1) * WP + xx + 1];
      s += v; q += v * v;
    }
#pragma unroll
  for (int o = 16; o > 0; o >>= 1) {
    s += __shfl_xor_sync(0xffffffffu, s, o);
    q += __shfl_xor_sync(0xffffffffu, q, o);
  }
  __shared__ float ss[8], sq[8];
  if (ln == 0) { ss[wid] = s; sq[wid] = q; }
  __syncthreads();
  if (threadIdx.x == 0) {
    float S = 0.f, Q = 0.f;
#pragma unroll
    for (int i = 0; i < 8; i++) { S += ss[i]; Q += sq[i]; }
    float m = S / (float)(H * W);
    float var = Q / (float)(H * W) - m * m;
    ss[0] = m;
    sq[0] = rsqrtf(var + 1e-5f);
  }
  __syncthreads();
  const float m = ss[0], inv = sq[0];
  for (int y = wid; y < H; y += 8)
    for (int xx = ln; xx < W; xx += 32) {
      float v = (p[(y + 1) * WP + xx + 1] - m) * inv;
      p[(y + 1) * WP + xx + 1] = v >= 0.f ? v : 0.01f * v;
    }
}

// ---------------------------------------------------------------------------
// 5) 4x4 s2 deconv, f32x2 over channel pairs.
//    out[co][2y'+a][2x'+b] = sum_{ci,s,t} w5[ci][co][3-(a+2s)][3-(b+2t)]
//                                        * in[ci][y'+a+s-1][x'+b+t-1]
// ---------------------------------------------------------------------------
__global__ void __launch_bounds__(256)
deconv4x4_k(const float* __restrict__ in, const float* __restrict__ w5,
            float* __restrict__ out) {
  constexpr int RS = 20, PLS = 18 * RS;

  __shared__ float s_in[16 * PLS];
  __shared__ __align__(16) float s_w[16 * 4 * 32];  // [ci][tap][co32]

  const int parity = blockIdx.y;
  const int a = parity >> 1, b = parity & 1;
  const int n = blockIdx.z;
  const int tx = blockIdx.x % 3;
  const int ty = blockIdx.x / 3;
  const int tid = threadIdx.x;
  const int ly = tid >> 4, lx = tid & 15;
  const int ybase = ty * 16, xbase = tx * 16;

  const float* inN = in + (size_t)n * 64 * PL2;

  u64 acc[16];   // co pairs {2c, 2c+1}
#pragma unroll
  for (int c = 0; c < 16; c++) acc[c] = 0;

  for (int cb = 0; cb < 64; cb += 16) {
    __syncthreads();
#pragma unroll
    for (int t = tid; t < 16 * 18 * 5; t += 256) {
      int c   = t / 90;
      int rem = t - c * 90;
      int r   = rem / 5;
      int q   = rem - r * 5;
      const float4 v = *reinterpret_cast<const float4*>(
          inN + (size_t)(cb + c) * PL2 + (ybase + r) * 52 + xbase + 4 * q);
      float* dst = &s_in[c * PLS + r * RS + 4 * q];
      dst[0] = v.x; dst[1] = v.y; dst[2] = v.z; dst[3] = v.w;
    }
    for (int t = tid; t < 16 * 4 * 32; t += 256) {
      int co  = t & 31;
      int tap = (t >> 5) & 3;
      int lci = t >> 7;
      int s  = tap >> 1, tt = tap & 1;
      s_w[t] = w5[(((size_t)(cb + lci) * 32 + co) * 4 + (3 - (a + 2 * s))) * 4 +
                  (3 - (b + 2 * tt))];
    }
    __syncthreads();

#pragma unroll 4
    for (int ci = 0; ci < 16; ci++) {
      float i00 = s_in[ci * PLS + (ly + a + 0) * RS + lx + b + 0];
      float i01 = s_in[ci * PLS + (ly + a + 0) * RS + lx + b + 1];
      float i10 = s_in[ci * PLS + (ly + a + 1) * RS + lx + b + 0];
      float i11 = s_in[ci * PLS + (ly + a + 1) * RS + lx + b + 1];
      u64 I00 = pk2(i00, i00), I01 = pk2(i01, i01);
      u64 I10 = pk2(i10, i10), I11 = pk2(i11, i11);
      const u64* wp = reinterpret_cast<const u64*>(s_w + ci * 128);
#pragma unroll
      for (int cp = 0; cp < 16; cp++) {
        fma2(acc[cp], wp[cp],      I00);
        fma2(acc[cp], wp[16 + cp], I01);
        fma2(acc[cp], wp[32 + cp], I10);
        fma2(acc[cp], wp[48 + cp], I11);
      }
    }
  }

  const int oy = 2 * (ybase + ly) + a + 1;
  const int ox = 2 * (xbase + lx) + b + 1;
  float* outN = out + (size_t)n * 32 * PL1;
#pragma unroll
  for (int cp = 0; cp < 16; cp++) {
    float lo, hi;
    unpk2(lo, hi, acc[cp]);
    outN[(size_t)(2 * cp)     * PL1 + oy * 100 + ox] = lo;
    outN[(size_t)(2 * cp + 1) * PL1 + oy * 100 + ox] = hi;
  }
}

// ---------------------------------------------------------------------------
// 6) Final 3x3 conv 32 -> 1 + bias: padded x5 -> unpadded d_out.
// ---------------------------------------------------------------------------
__global__ void __launch_bounds__(256)
conv_final_k(const float* __restrict__ in, const float* __restrict__ w6,
             const float* __restrict__ b6, float* __restrict__ out) {
  constexpr int RS = 37, PLS = 10 * RS;
  __shared__ float s_in[8 * PLS];
  __shared__ float sw[288];
  __shared__ float sb;

  const int tid = threadIdx.x;
  const int tx = blockIdx.x % 3;
  const int ty = blockIdx.x / 3;
  const int n  = blockIdx.y;
  const int y0 = ty * 8, x0 = tx * 32;
  const int px = tid & 31, py = tid >> 5;

  for (int t = tid; t < 288; t += 256) sw[t] = w6[t];
  if (tid == 0) sb = b6[0];

  const float* inN = in + (size_t)n * 32 * PL1;
  float acc = 0.f;

  for (int cb = 0; cb < 32; cb += 8) {
    __syncthreads();
#pragma unroll
    for (int t = tid; t < 8 * 10 * 9; t += 256) {
      int c   = t / 90;
      int rem = t - c * 90;
      int r   = rem / 9;
      int q   = rem - r * 9;
      const float4 v = *reinterpret_cast<const float4*>(
          inN + (size_t)(cb + c) * PL1 + (y0 + r) * 100 + x0 + 4 * q);
      float* dst = &s_in[c * PLS + r * RS + 4 * q];
      dst[0] = v.x; dst[1] = v.y; dst[2] = v.z; dst[3] = v.w;
    }
    __syncthreads();
#pragma unroll
    for (int c = 0; c < 8; c++)
#pragma unroll
      for (int ky = 0; ky < 3; ky++)
#pragma unroll
        for (int kx = 0; kx < 3; kx++)
          acc += sw[(cb + c) * 9 + ky * 3 + kx] *
                 s_in[c * PLS + (py + ky) * RS + px + kx];
  }

  out[(size_t)n * 6144 + (y0 + py) * 96 + x0 + px] = acc + sb;
}

// ---------------------------------------------------------------------------
// Launch
// ---------------------------------------------------------------------------
extern "C" void kernel_launch(void* const* d_in, const int* in_sizes, int n_in,
                              void* d_out, int out_size) {
  const float* f1 = (const float*)d_in[0];
  const float* f2 = (const float*)d_in[1];
  const float* w1 = (const float*)d_in[2];
  const float* w2 = (const float*)d_in[3];
  const float* w3 = (const float*)d_in[4];
  const float* w4 = (const float*)d_in[5];
  const float* w5 = (const float*)d_in[6];
  const float* w6 = (const float*)d_in[7];
  const float* b6 = (const float*)d_in[8];
  float* out = (float*)d_out;

  float *mvol, *x1, *x2, *x3, *x4, *x5;
  cudaGetSymbolAddress((void**)&mvol, g_mvol);
  cudaGetSymbolAddress((void**)&x1, g_x1);
  cudaGetSymbolAddress((void**)&x2, g_x2);
  cudaGetSymbolAddress((void**)&x3, g_x3);
  cudaGetSymbolAddress((void**)&x4, g_x4);
  cudaGetSymbolAddress((void**)&x5, g_x5);

  build_mvol_k<<<(NIMG * 64 * 6144 + 255) / 256, 256>>>(f1, f2);

  conv3x3_s1_k<32, 64, 96, 100><<<dim3(24, 6, NIMG), 256>>>(mvol, w1, x1, 64, 96);
  inorm_leaky_k<64, 96, 100><<<NIMG * 96, 256>>>(x1);

  conv3x3_s2_k<<<dim3(12, 8, NIMG), 128>>>(x1, w2, x2, 96, 128);
  inorm_leaky_k<32, 48, 52><<<NIMG * 128, 256>>>(x2);

  conv3x3_s1_k<16, 32, 48, 52><<<dim3(12, 8, NIMG), 128>>>(x2, w3, x3, 128, 128);
  inorm_leaky_k<32, 48, 52><<<NIMG * 128, 256>>>(x3);

  conv3x3_s1_k<16, 32, 48, 52><<<dim3(12, 4, NIMG), 128>>>(x3, w4, x4, 128, 64);
  inorm_leaky_k<32, 48, 52><<<NIMG * 64, 256>>>(x4);

  deconv4x4_k<<<dim3(6, 4, NIMG), 256>>>(x4, w5, x5);
  inorm_leaky_k<64, 96, 100><<<NIMG * 32, 256>>>(x5);

  conv_final_k<<<dim3(24, NIMG), 256>>>(x5, w6, b6, out);
}

// round 5
// speedup vs baseline: 1.1531x; 1.1531x over previous
#include <cuda_runtime.h>
#include <cstdint>

// ---------------------------------------------------------------------------
// Padded layouts: every intermediate is [C][H+2][WP] with a 1-px zero halo.
// Borders are NEVER written; __device__ globals are zero-initialized at load,
// so halos stay zero across graph replays -> no bounds checks anywhere.
// ---------------------------------------------------------------------------
#define NIMG 98
#define PL1 (66 * 100)   // plane for 64x96 (WP=100)
#define PL2 (34 * 52)    // plane for 32x48 (WP=52)

__device__ float g_mvol[NIMG * 64 * PL1];
__device__ float g_x1 [NIMG * 96 * PL1];
__device__ float g_x2 [NIMG * 128 * PL2];
__device__ float g_x3 [NIMG * 128 * PL2];
__device__ float g_x4 [NIMG * 64 * PL2];
__device__ float g_x5 [NIMG * 32 * PL1];

// ---------------------------------------------------------------------------
// 1) Correlation volume -> padded mvol. n=(b*7+i)*7+j, di=i-3 (x), dj=j-3 (y)
// ---------------------------------------------------------------------------
__global__ void build_mvol_k(const float* __restrict__ f1,
                             const float* __restrict__ f2) {
  int idx = blockIdx.x * blockDim.x + threadIdx.x;
  if (idx >= NIMG * 64 * 64 * 96) return;
  int x = idx % 96;
  int y = (idx / 96) % 64;
  int c = (idx / 6144) % 64;
  int n = idx / (6144 * 64);
  int b = n / 49, d = n % 49;
  int di = d / 7 - 3;
  int dj = d % 7 - 3;
  int yy = y + dj, xx = x + di;
  float v = 0.f;
  if (yy >= 0 && yy < 64 && xx >= 0 && xx < 96) {
    if (c < 32) v = f1[((b * 32 + c) * 64 + y) * 96 + x];
    else        v = f2[((b * 32 + (c - 32)) * 64 + yy) * 96 + xx];
  }
  g_mvol[((size_t)(n * 64 + c)) * PL1 + (y + 1) * 100 + (x + 1)] = v;
}

// ---------------------------------------------------------------------------
// 2) 3x3 s1 conv. Thread = 4 px x 8 co (32 fp32 accumulators).
//    Block tile = 32 co x 8 rows x TW cols; 4 co-groups x 8 py x (TW/4) pxg.
//    Same input LDS as the 4-co version but 2x FMAs -> 1.5x less L1/FMA.
// ---------------------------------------------------------------------------
template <int TW, int H, int W, int WP>
__global__ void __launch_bounds__(8 * TW)
conv3x3_s1_k(const float* __restrict__ in, const float* __restrict__ w,
             float* __restrict__ out, int Cin, int Cout) {
  constexpr int PXG = TW / 4;
  constexpr int NT  = 8 * TW;            // 4 * 8 * PXG
  constexpr int RS  = 37;
  constexpr int PLS = 10 * RS;
  constexpr int F4  = (TW + 4) / 4;
  constexpr int PLANE = (H + 2) * WP;

  __shared__ float s_in[8 * PLS];
  __shared__ __align__(16) float s_w[8 * 9 * 32];  // [ci][k][co32]

  const int tid = threadIdx.x;
  const int cg  = tid / (8 * PXG);      // 0..3, warp-uniform
  const int pid = tid % (8 * PXG);
  const int py  = pid / PXG;
  const int pxg = pid % PXG;

  const int tilesX = W / TW;
  const int tx = blockIdx.x % tilesX;
  const int ty = blockIdx.x / tilesX;
  const int n  = blockIdx.z;
  const int coB = blockIdx.y * 32;
  const int y0 = ty * 8, x0 = tx * TW;

  const float* inN = in + (size_t)n * Cin * PLANE;

  float acc[8][4];
#pragma unroll
  for (int q = 0; q < 8; q++)
#pragma unroll
    for (int p = 0; p < 4; p++) acc[q][p] = 0.f;

  for (int cb = 0; cb < Cin; cb += 8) {
    __syncthreads();
#pragma unroll
    for (int t = tid; t < 8 * 10 * F4; t += NT) {
      int c   = t / (10 * F4);
      int rem = t - c * (10 * F4);
      int r   = rem / F4;
      int q   = rem - r * F4;
      const float4 v = *reinterpret_cast<const float4*>(
          inN + (size_t)(cb + c) * PLANE + (y0 + r) * WP + x0 + 4 * q);
      float* dst = &s_in[c * PLS + r * RS + 4 * q];
      dst[0] = v.x; dst[1] = v.y; dst[2] = v.z; dst[3] = v.w;
    }
    // weights: s_w[(lci*9+k)*32 + lco] = w[(coB+lco)*Cin + cb+lci][k]
    for (int t = tid; t < 32 * 8 * 9; t += NT) {
      int lco = t & 31;
      int rem = t >> 5;
      int k   = rem % 9;
      int lci = rem / 9;
      s_w[(lci * 9 + k) * 32 + lco] =
          w[((size_t)(coB + lco) * Cin + (cb + lci)) * 9 + k];
    }
    __syncthreads();

#pragma unroll
    for (int ci = 0; ci < 8; ci++) {
#pragma unroll
      for (int ky = 0; ky < 3; ky++) {
        const float* row = &s_in[ci * PLS + (py + ky) * RS + pxg * 4];
        float r[6];
#pragma unroll
        for (int j = 0; j < 6; j++) r[j] = row[j];
#pragma unroll
        for (int kx = 0; kx < 3; kx++) {
          const float4* wq = reinterpret_cast<const float4*>(
              &s_w[(ci * 9 + ky * 3 + kx) * 32 + cg * 8]);
          float4 wa = wq[0], wb = wq[1];
#pragma unroll
          for (int p = 0; p < 4; p++) {
            float iv = r[p + kx];
            acc[0][p] += wa.x * iv;
            acc[1][p] += wa.y * iv;
            acc[2][p] += wa.z * iv;
            acc[3][p] += wa.w * iv;
            acc[4][p] += wb.x * iv;
            acc[5][p] += wb.y * iv;
            acc[6][p] += wb.z * iv;
            acc[7][p] += wb.w * iv;
          }
        }
      }
    }
  }

  float* outN = out + (size_t)n * Cout * PLANE;
  const int gy = y0 + py + 1;
#pragma unroll
  for (int q = 0; q < 8; q++) {
    int co = coB + cg * 8 + q;
    float* o = outN + (size_t)co * PLANE + gy * WP + x0 + pxg * 4 + 1;
#pragma unroll
    for (int p = 0; p < 4; p++) o[p] = acc[q][p];
  }
}

// ---------------------------------------------------------------------------
// 3) 3x3 s2 conv, padded 66x100 -> padded 34x52. Thread = 4 px x 8 co.
// ---------------------------------------------------------------------------
__global__ void __launch_bounds__(128)
conv3x3_s2_k(const float* __restrict__ in, const float* __restrict__ w,
             float* __restrict__ out, int Cin, int Cout) {
  constexpr int RS = 37;
  constexpr int PLS = 17 * RS;

  __shared__ float s_in[8 * PLS];
  __shared__ __align__(16) float s_w[8 * 9 * 32];

  const int tid = threadIdx.x;
  const int cg  = tid >> 5;        // 0..3, warp-uniform
  const int py  = (tid & 31) >> 2;
  const int pxg = tid & 3;

  const int tx = blockIdx.x % 3;
  const int ty = blockIdx.x / 3;
  const int n  = blockIdx.z;
  const int coB = blockIdx.y * 32;
  const int y0 = ty * 8, x0 = tx * 16;

  const float* inN = in + (size_t)n * Cin * PL1;

  float acc[8][4];
#pragma unroll
  for (int q = 0; q < 8; q++)
#pragma unroll
    for (int p = 0; p < 4; p++) acc[q][p] = 0.f;

  for (int cb = 0; cb < Cin; cb += 8) {
    __syncthreads();
#pragma unroll
    for (int c = 0; c < 8; c++) {
      for (int t = tid; t < 17 * 9; t += 128) {
        int r = t / 9;
        int q = t - r * 9;
        const float4 v = *reinterpret_cast<const float4*>(
            inN + (size_t)(cb + c) * PL1 + (2 * y0 + r) * 100 + 2 * x0 + 4 * q);
        float* dst = &s_in[c * PLS + r * RS + 4 * q];
        dst[0] = v.x; dst[1] = v.y; dst[2] = v.z; dst[3] = v.w;
      }
    }
    for (int t = tid; t < 32 * 8 * 9; t += 128) {
      int lco = t & 31;
      int rem = t >> 5;
      int k   = rem % 9;
      int lci = rem / 9;
      s_w[(lci * 9 + k) * 32 + lco] =
          w[((size_t)(coB + lco) * Cin + (cb + lci)) * 9 + k];
    }
    __syncthreads();

#pragma unroll
    for (int ci = 0; ci < 8; ci++) {
#pragma unroll
      for (int ky = 0; ky < 3; ky++) {
        const float* row = &s_in[ci * PLS + (2 * py + ky) * RS + pxg * 8];
        float r[9];
#pragma unroll
        for (int m = 0; m < 9; m++) r[m] = row[m];
#pragma unroll
        for (int kx = 0; kx < 3; kx++) {
          const float4* wq = reinterpret_cast<const float4*>(
              &s_w[(ci * 9 + ky * 3 + kx) * 32 + cg * 8]);
          float4 wa = wq[0], wb = wq[1];
#pragma unroll
          for (int p = 0; p < 4; p++) {
            float iv = r[2 * p + kx];
            acc[0][p] += wa.x * iv;
            acc[1][p] += wa.y * iv;
            acc[2][p] += wa.z * iv;
            acc[3][p] += wa.w * iv;
            acc[4][p] += wb.x * iv;
            acc[5][p] += wb.y * iv;
            acc[6][p] += wb.z * iv;
            acc[7][p] += wb.w * iv;
          }
        }
      }
    }
  }

  float* outN = out + (size_t)n * Cout * PL2;
  const int gy = y0 + py + 1;
#pragma unroll
  for (int q = 0; q < 8; q++) {
    int co = coB + cg * 8 + q;
    float* o = outN + (size_t)co * PL2 + gy * 52 + x0 + pxg * 4 + 1;
#pragma unroll
    for (int p = 0; p < 4; p++) o[p] = acc[q][p];
  }
}

// ---------------------------------------------------------------------------
// 4) Instance norm + leaky, padded in-place.
// ---------------------------------------------------------------------------
template <int H, int W, int WP>
__global__ void __launch_bounds__(256)
inorm_leaky_k(float* __restrict__ x) {
  constexpr int PLANE = (H + 2) * WP;
  float* p = x + (size_t)blockIdx.x * PLANE;
  const int wid = threadIdx.x >> 5, ln = threadIdx.x & 31;

  float s = 0.f, q = 0.f;
  for (int y = wid; y < H; y += 8)
    for (int xx = ln; xx < W; xx += 32) {
      float v = p[(y + 1) * WP + xx + 1];
      s += v; q += v * v;
    }
#pragma unroll
  for (int o = 16; o > 0; o >>= 1) {
    s += __shfl_xor_sync(0xffffffffu, s, o);
    q += __shfl_xor_sync(0xffffffffu, q, o);
  }
  __shared__ float ss[8], sq[8];
  if (ln == 0) { ss[wid] = s; sq[wid] = q; }
  __syncthreads();
  if (threadIdx.x == 0) {
    float S = 0.f, Q = 0.f;
#pragma unroll
    for (int i = 0; i < 8; i++) { S += ss[i]; Q += sq[i]; }
    float m = S / (float)(H * W);
    float var = Q / (float)(H * W) - m * m;
    ss[0] = m;
    sq[0] = rsqrtf(var + 1e-5f);
  }
  __syncthreads();
  const float m = ss[0], inv = sq[0];
  for (int y = wid; y < H; y += 8)
    for (int xx = ln; xx < W; xx += 32) {
      float v = (p[(y + 1) * WP + xx + 1] - m) * inv;
      p[(y + 1) * WP + xx + 1] = v >= 0.f ? v : 0.01f * v;
    }
}

// ---------------------------------------------------------------------------
// 5) 4x4 s2 deconv, 4 parity classes (R3 form).
//    out[co][2y'+a][2x'+b] = sum_{ci,s,t} w5[ci][co][3-(a+2s)][3-(b+2t)]
//                                        * in[ci][y'+a+s-1][x'+b+t-1]
// ---------------------------------------------------------------------------
__global__ void __launch_bounds__(256)
deconv4x4_k(const float* __restrict__ in, const float* __restrict__ w5,
            float* __restrict__ out) {
  constexpr int RS = 20, PLS = 18 * RS;

  __shared__ float s_in[16 * PLS];
  __shared__ __align__(16) float s_w[16 * 4 * 32];

  const int parity = blockIdx.y;
  const int a = parity >> 1, b = parity & 1;
  const int n = blockIdx.z;
  const int tx = blockIdx.x % 3;
  const int ty = blockIdx.x / 3;
  const int tid = threadIdx.x;
  const int ly = tid >> 4, lx = tid & 15;
  const int ybase = ty * 16, xbase = tx * 16;

  const float* inN = in + (size_t)n * 64 * PL2;

  float acc[32];
#pragma unroll
  for (int c = 0; c < 32; c++) acc[c] = 0.f;

  for (int cb = 0; cb < 64; cb += 16) {
    __syncthreads();
#pragma unroll
    for (int t = tid; t < 16 * 18 * 5; t += 256) {
      int c   = t / 90;
      int rem = t - c * 90;
      int r   = rem / 5;
      int q   = rem - r * 5;
      const float4 v = *reinterpret_cast<const float4*>(
          inN + (size_t)(cb + c) * PL2 + (ybase + r) * 52 + xbase + 4 * q);
      float* dst = &s_in[c * PLS + r * RS + 4 * q];
      dst[0] = v.x; dst[1] = v.y; dst[2] = v.z; dst[3] = v.w;
    }
    for (int t = tid; t < 16 * 4 * 32; t += 256) {
      int co  = t & 31;
      int tap = (t >> 5) & 3;
      int lci = t >> 7;
      int s  = tap >> 1, tt = tap & 1;
      s_w[t] = w5[(((size_t)(cb + lci) * 32 + co) * 4 + (3 - (a + 2 * s))) * 4 +
                  (3 - (b + 2 * tt))];
    }
    __syncthreads();

#pragma unroll 4
    for (int ci = 0; ci < 16; ci++) {
      float i00 = s_in[ci * PLS + (ly + a + 0) * RS + lx + b + 0];
      float i01 = s_in[ci * PLS + (ly + a + 0) * RS + lx + b + 1];
      float i10 = s_in[ci * PLS + (ly + a + 1) * RS + lx + b + 0];
      float i11 = s_in[ci * PLS + (ly + a + 1) * RS + lx + b + 1];
      const float4* wp = reinterpret_cast<const float4*>(s_w + ci * 128);
#pragma unroll
      for (int cq = 0; cq < 8; cq++) {
        float4 w0 = wp[cq];
        float4 w1 = wp[8 + cq];
        float4 w2 = wp[16 + cq];
        float4 w3 = wp[24 + cq];
        acc[4 * cq + 0] += w0.x * i00 + w1.x * i01 + w2.x * i10 + w3.x * i11;
        acc[4 * cq + 1] += w0.y * i00 + w1.y * i01 + w2.y * i10 + w3.y * i11;
        acc[4 * cq + 2] += w0.z * i00 + w1.z * i01 + w2.z * i10 + w3.z * i11;
        acc[4 * cq + 3] += w0.w * i00 + w1.w * i01 + w2.w * i10 + w3.w * i11;
      }
    }
  }

  const int oy = 2 * (ybase + ly) + a + 1;
  const int ox = 2 * (xbase + lx) + b + 1;
  float* outN = out + (size_t)n * 32 * PL1;
#pragma unroll
  for (int co = 0; co < 32; co++)
    outN[(size_t)co * PL1 + oy * 100 + ox] = acc[co];
}

// ---------------------------------------------------------------------------
// 6) Final 3x3 conv 32 -> 1 + bias: padded x5 -> unpadded d_out.
// ---------------------------------------------------------------------------
__global__ void __launch_bounds__(256)
conv_final_k(const float* __restrict__ in, const float* __restrict__ w6,
             const float* __restrict__ b6, float* __restrict__ out) {
  constexpr int RS = 37, PLS = 10 * RS;
  __shared__ float s_in[8 * PLS];
  __shared__ float sw[288];
  __shared__ float sb;

  const int tid = threadIdx.x;
  const int tx = blockIdx.x % 3;
  const int ty = blockIdx.x / 3;
  const int n  = blockIdx.y;
  const int y0 = ty * 8, x0 = tx * 32;
  const int px = tid & 31, py = tid >> 5;

  for (int t = tid; t < 288; t += 256) sw[t] = w6[t];
  if (tid == 0) sb = b6[0];

  const float* inN = in + (size_t)n * 32 * PL1;
  float acc = 0.f;

  for (int cb = 0; cb < 32; cb += 8) {
    __syncthreads();
#pragma unroll
    for (int t = tid; t < 8 * 10 * 9; t += 256) {
      int c   = t / 90;
      int rem = t - c * 90;
      int r   = rem / 9;
      int q   = rem - r * 9;
      const float4 v = *reinterpret_cast<const float4*>(
          inN + (size_t)(cb + c) * PL1 + (y0 + r) * 100 + x0 + 4 * q);
      float* dst = &s_in[c * PLS + r * RS + 4 * q];
      dst[0] = v.x; dst[1] = v.y; dst[2] = v.z; dst[3] = v.w;
    }
    __syncthreads();
#pragma unroll
    for (int c = 0; c < 8; c++)
#pragma unroll
      for (int ky = 0; ky < 3; ky++)
#pragma unroll
        for (int kx = 0; kx < 3; kx++)
          acc += sw[(cb + c) * 9 + ky * 3 + kx] *
                 s_in[c * PLS + (py + ky) * RS + px + kx];
  }

  out[(size_t)n * 6144 + (y0 + py) * 96 + x0 + px] = acc + sb;
}

// ---------------------------------------------------------------------------
// Launch
// ---------------------------------------------------------------------------
extern "C" void kernel_launch(void* const* d_in, const int* in_sizes, int n_in,
                              void* d_out, int out_size) {
  const float* f1 = (const float*)d_in[0];
  const float* f2 = (const float*)d_in[1];
  const float* w1 = (const float*)d_in[2];
  const float* w2 = (const float*)d_in[3];
  const float* w3 = (const float*)d_in[4];
  const float* w4 = (const float*)d_in[5];
  const float* w5 = (const float*)d_in[6];
  const float* w6 = (const float*)d_in[7];
  const float* b6 = (const float*)d_in[8];
  float* out = (float*)d_out;

  float *mvol, *x1, *x2, *x3, *x4, *x5;
  cudaGetSymbolAddress((void**)&mvol, g_mvol);
  cudaGetSymbolAddress((void**)&x1, g_x1);
  cudaGetSymbolAddress((void**)&x2, g_x2);
  cudaGetSymbolAddress((void**)&x3, g_x3);
  cudaGetSymbolAddress((void**)&x4, g_x4);
  cudaGetSymbolAddress((void**)&x5, g_x5);

  build_mvol_k<<<(NIMG * 64 * 6144 + 255) / 256, 256>>>(f1, f2);

  // conv1 64->96 @64x96 : co-blocks of 32 -> grid.y = 3
  conv3x3_s1_k<32, 64, 96, 100><<<dim3(24, 3, NIMG), 256>>>(mvol, w1, x1, 64, 96);
  inorm_leaky_k<64, 96, 100><<<NIMG * 96, 256>>>(x1);

  // conv2 s2 96->128 : grid.y = 4
  conv3x3_s2_k<<<dim3(12, 4, NIMG), 128>>>(x1, w2, x2, 96, 128);
  inorm_leaky_k<32, 48, 52><<<NIMG * 128, 256>>>(x2);

  // conv3 128->128 @32x48 : grid.y = 4
  conv3x3_s1_k<16, 32, 48, 52><<<dim3(12, 4, NIMG), 128>>>(x2, w3, x3, 128, 128);
  inorm_leaky_k<32, 48, 52><<<NIMG * 128, 256>>>(x3);

  // conv4 128->64 @32x48 : grid.y = 2
  conv3x3_s1_k<16, 32, 48, 52><<<dim3(12, 2, NIMG), 128>>>(x3, w4, x4, 128, 64);
  inorm_leaky_k<32, 48, 52><<<NIMG * 64, 256>>>(x4);

  deconv4x4_k<<<dim3(6, 4, NIMG), 256>>>(x4, w5, x5);
  inorm_leaky_k<64, 96, 100><<<NIMG * 32, 256>>>(x5);

  conv_final_k<<<dim3(24, NIMG), 256>>>(x5, w6, b6, out);
}

// round 6
// speedup vs baseline: 1.3034x; 1.1304x over previous
#include <cuda_runtime.h>
#include <cstdint>

// ---------------------------------------------------------------------------
// Padded layouts: intermediates are [C][H+2][WP] with a 1-px zero halo.
// Halos never written; __device__ globals zero-initialized -> stay zero.
// ---------------------------------------------------------------------------
#define NIMG 98
#define PL1 (66 * 100)   // plane for 64x96  (WP=100)
#define PL2 (34 * 52)    // plane for 32x48  (WP=52)
#define PLV (72 * 112)   // V plane          (WP=112)
#define PLC (80 * 120)   // f2 canvas plane  (WP=120)

__device__ float g_x1 [NIMG * 96 * PL1];
__device__ float g_x2 [NIMG * 128 * PL2];
__device__ float g_x3 [NIMG * 128 * PL2];
__device__ float g_x4 [NIMG * 64 * PL2];
__device__ float g_x5 [NIMG * 32 * PL1];

// conv1 factorization scratch
__device__ float g_f1p[2 * 32 * PL1];    // padded f1
__device__ float g_f2c[2 * 32 * PLC];    // f2 in big zero canvas at (+8,+8)
__device__ float g_U  [2 * 96 * PL1];    // conv(f1), padded layout
__device__ float g_V  [2 * 96 * PLV];    // conv(zp f2) on extended grid
__device__ float g_w1a[96 * 32 * 9];     // w1[:, 0:32]
__device__ float g_w1b[96 * 32 * 9];     // w1[:, 32:64]

// strip-fix segment table (y0, x0, h, w); 20 segments, 1216 px total
__device__ const int c_segy[20] = {0,0,0, 60,60,60, 4,12,20,28,36,44,52, 4,12,20,28,36,44,52};
__device__ const int c_segx[20] = {0,32,64, 0,32,64, 0,0,0,0,0,0,0, 92,92,92,92,92,92,92};
__device__ const int c_segh[20] = {4,4,4, 4,4,4, 8,8,8,8,8,8,8, 8,8,8,8,8,8,8};
__device__ const int c_segw[20] = {32,32,32, 32,32,32, 4,4,4,4,4,4,4, 4,4,4,4,4,4,4};

// ---------------------------------------------------------------------------
// 0) prep: pad f1 -> f1p, embed f2 -> canvas, split w1 into a/b halves.
// ---------------------------------------------------------------------------
__global__ void prep_k(const float* __restrict__ f1, const float* __restrict__ f2,
                       const float* __restrict__ w1) {
  int idx = blockIdx.x * blockDim.x + threadIdx.x;
  if (idx < 2 * 32 * 6144) {
    int x = idx % 96, y = (idx / 96) % 64, c = idx / 6144;   // c = b*32+ch
    g_f1p[(size_t)c * PL1 + (y + 1) * 100 + x + 1] = f1[idx];
    g_f2c[(size_t)c * PLC + (y + 8) * 120 + x + 8] = f2[idx];
  }
  if (idx < 96 * 64 * 9) {
    int co = idx / 576, rem = idx % 576, ci = rem / 9, k = rem % 9;
    if (ci < 32) g_w1a[(co * 32 + ci) * 9 + k] = w1[idx];
    else         g_w1b[(co * 32 + (ci - 32)) * 9 + k] = w1[idx];
  }
}

// ---------------------------------------------------------------------------
// 1) 3x3 s1 conv (R3 form). Thread = 4 px x 4 co.
// ---------------------------------------------------------------------------
template <int TW, int H, int W, int WP>
__global__ void __launch_bounds__(8 * TW)
conv3x3_s1_k(const float* __restrict__ in, const float* __restrict__ w,
             float* __restrict__ out, int Cin, int Cout) {
  constexpr int PXG = TW / 4;
  constexpr int NT  = 8 * TW;
  constexpr int RS  = 37;
  constexpr int PLS = 10 * RS;
  constexpr int F4  = (TW + 4) / 4;
  constexpr int PLANE = (H + 2) * WP;

  __shared__ float s_in[8 * PLS];
  __shared__ __align__(16) float s_w[8 * 9 * 16];

  const int tid = threadIdx.x;
  const int cg  = tid / (8 * PXG);
  const int pid = tid % (8 * PXG);
  const int py  = pid / PXG;
  const int pxg = pid % PXG;

  const int tilesX = W / TW;
  const int tx = blockIdx.x % tilesX;
  const int ty = blockIdx.x / tilesX;
  const int n  = blockIdx.z;
  const int coB = blockIdx.y * 16;
  const int y0 = ty * 8, x0 = tx * TW;

  const float* inN = in + (size_t)n * Cin * PLANE;

  float acc[4][4];
#pragma unroll
  for (int q = 0; q < 4; q++)
#pragma unroll
    for (int p = 0; p < 4; p++) acc[q][p] = 0.f;

  for (int cb = 0; cb < Cin; cb += 8) {
    __syncthreads();
#pragma unroll
    for (int t = tid; t < 8 * 10 * F4; t += NT) {
      int c   = t / (10 * F4);
      int rem = t - c * (10 * F4);
      int r   = rem / F4;
      int q   = rem - r * F4;
      const float4 v = *reinterpret_cast<const float4*>(
          inN + (size_t)(cb + c) * PLANE + (y0 + r) * WP + x0 + 4 * q);
      float* dst = &s_in[c * PLS + r * RS + 4 * q];
      dst[0] = v.x; dst[1] = v.y; dst[2] = v.z; dst[3] = v.w;
    }
    for (int t = tid; t < 16 * 8 * 9; t += NT) {
      int lco = t & 15;
      int rem = t >> 4;
      int k   = rem % 9;
      int lci = rem / 9;
      s_w[(lci * 9 + k) * 16 + lco] =
          w[((size_t)(coB + lco) * Cin + (cb + lci)) * 9 + k];
    }
    __syncthreads();

#pragma unroll
    for (int ci = 0; ci < 8; ci++) {
#pragma unroll
      for (int ky = 0; ky < 3; ky++) {
        float r[6];
#pragma unroll
        for (int j = 0; j < 6; j++)
          r[j] = s_in[ci * PLS + (py + ky) * RS + pxg * 4 + j];
#pragma unroll
        for (int kx = 0; kx < 3; kx++) {
          float4 wv =
              reinterpret_cast<const float4*>(s_w)[(ci * 9 + ky * 3 + kx) * 4 + cg];
#pragma unroll
          for (int p = 0; p < 4; p++) {
            float iv = r[p + kx];
            acc[0][p] += wv.x * iv;
            acc[1][p] += wv.y * iv;
            acc[2][p] += wv.z * iv;
            acc[3][p] += wv.w * iv;
          }
        }
      }
    }
  }

  float* outN = out + (size_t)n * Cout * PLANE;
  const int gy = y0 + py + 1;
#pragma unroll
  for (int q = 0; q < 4; q++) {
    int co = coB + cg * 4 + q;
#pragma unroll
    for (int p = 0; p < 4; p++)
      outN[(size_t)co * PLANE + gy * WP + x0 + pxg * 4 + p + 1] = acc[q][p];
  }
}

// ---------------------------------------------------------------------------
// 1b) V = conv3x3(zero-padded f2) on extended 72x112 grid.
//     Vbuf[rv][cv] = V(y'=rv-3, x'=cv-3); canvas taps at (+4,+4) offsets.
// ---------------------------------------------------------------------------
__global__ void __launch_bounds__(128)
conv_v_k(const float* __restrict__ in /*f2c*/, const float* __restrict__ w /*w1b*/,
         float* __restrict__ out /*V*/) {
  constexpr int RS = 37, PLS = 10 * RS;
  __shared__ float s_in[8 * PLS];
  __shared__ __align__(16) float s_w[8 * 9 * 16];

  const int tid = threadIdx.x;
  const int cg  = tid >> 5;
  const int pid = tid & 31;
  const int py  = pid >> 2;
  const int pxg = pid & 3;

  const int tx = blockIdx.x % 7;   // 112/16
  const int ty = blockIdx.x / 7;   // 72/8 = 9
  const int n  = blockIdx.z;       // batch
  const int coB = blockIdx.y * 16;
  const int y0 = ty * 8, x0 = tx * 16;

  const float* inN = in + (size_t)n * 32 * PLC;

  float acc[4][4];
#pragma unroll
  for (int q = 0; q < 4; q++)
#pragma unroll
    for (int p = 0; p < 4; p++) acc[q][p] = 0.f;

  for (int cb = 0; cb < 32; cb += 8) {
    __syncthreads();
#pragma unroll
    for (int t = tid; t < 8 * 10 * 5; t += 128) {
      int c   = t / 50;
      int rem = t - c * 50;
      int r   = rem / 5;
      int q   = rem - r * 5;
      const float4 v = *reinterpret_cast<const float4*>(
          inN + (size_t)(cb + c) * PLC + (y0 + r + 4) * 120 + x0 + 4 * q + 4);
      float* dst = &s_in[c * PLS + r * RS + 4 * q];
      dst[0] = v.x; dst[1] = v.y; dst[2] = v.z; dst[3] = v.w;
    }
    for (int t = tid; t < 16 * 8 * 9; t += 128) {
      int lco = t & 15;
      int rem = t >> 4;
      int k   = rem % 9;
      int lci = rem / 9;
      s_w[(lci * 9 + k) * 16 + lco] =
          w[((coB + lco) * 32 + cb + lci) * 9 + k];
    }
    __syncthreads();

#pragma unroll
    for (int ci = 0; ci < 8; ci++) {
#pragma unroll
      for (int ky = 0; ky < 3; ky++) {
        float r[6];
#pragma unroll
        for (int j = 0; j < 6; j++)
          r[j] = s_in[ci * PLS + (py + ky) * RS + pxg * 4 + j];
#pragma unroll
        for (int kx = 0; kx < 3; kx++) {
          float4 wv =
              reinterpret_cast<const float4*>(s_w)[(ci * 9 + ky * 3 + kx) * 4 + cg];
#pragma unroll
          for (int p = 0; p < 4; p++) {
            float iv = r[p + kx];
            acc[0][p] += wv.x * iv;
            acc[1][p] += wv.y * iv;
            acc[2][p] += wv.z * iv;
            acc[3][p] += wv.w * iv;
          }
        }
      }
    }
  }

  float* outN = out + (size_t)n * 96 * PLV;
  const int gy = y0 + py;
#pragma unroll
  for (int q = 0; q < 4; q++) {
    int co = coB + cg * 4 + q;
#pragma unroll
    for (int p = 0; p < 4; p++)
      outN[(size_t)co * PLV + gy * 112 + x0 + pxg * 4 + p] = acc[q][p];
  }
}

// ---------------------------------------------------------------------------
// 1c) combine: x1[n,co,y,x] = U[b,co,y,x] + V[b,co,y+dj,x+di]   (interior-exact)
// ---------------------------------------------------------------------------
__global__ void combine_k() {
  int idx = blockIdx.x * blockDim.x + threadIdx.x;
  if (idx >= NIMG * 96 * 6144) return;
  int x  = idx % 96;
  int y  = (idx / 96) % 64;
  int co = (idx / 6144) % 96;
  int n  = idx / (6144 * 96);
  int b = n / 49, d = n % 49;
  int di = d / 7 - 3;
  int dj = d % 7 - 3;
  float u = g_U[((size_t)(b * 96 + co)) * PL1 + (y + 1) * 100 + x + 1];
  float v = g_V[((size_t)(b * 96 + co)) * PLV + (y + dj + 3) * 112 + (x + di + 3)];
  g_x1[((size_t)(n * 96 + co)) * PL1 + (y + 1) * 100 + x + 1] = u + v;
}

// ---------------------------------------------------------------------------
// 1d) strip fix: exact conv1 on the 1216-px border region, mvol on the fly.
// ---------------------------------------------------------------------------
__global__ void __launch_bounds__(128)
stripfix_k(const float* __restrict__ f1, const float* __restrict__ f2,
           const float* __restrict__ w1) {
  const int sid = blockIdx.x;
  const int n   = blockIdx.y;
  const int y0 = c_segy[sid], x0 = c_segx[sid];
  const int h  = c_segh[sid], w = c_segw[sid];
  const int b = n / 49, d = n % 49;
  const int di = d / 7 - 3;
  const int dj = d % 7 - 3;
  const int H2 = h + 2, W2 = w + 2;

  __shared__ float s_in[8 * 10 * 34];              // [ci][r<=10][c<=34]
  __shared__ __align__(16) float s_w[8 * 9 * 32];  // [(ci*9+k)*32 + co]

  const int tid = threadIdx.x;
  const bool act = tid < h * w;
  const int py = act ? tid / w : 0;
  const int px = act ? tid % w : 0;

  const float* f1b = f1 + (size_t)b * 32 * 6144;
  const float* f2b = f2 + (size_t)b * 32 * 6144;

  for (int coc = 0; coc < 3; coc++) {
    float acc[32];
#pragma unroll
    for (int c = 0; c < 32; c++) acc[c] = 0.f;

    for (int cb = 0; cb < 64; cb += 8) {
      __syncthreads();
      // input patch: mvol values computed on the fly
      for (int t = tid; t < 8 * H2 * W2; t += 128) {
        int ci  = t / (H2 * W2);
        int rem = t - ci * (H2 * W2);
        int r   = rem / W2;
        int c   = rem - r * W2;
        int yy = y0 - 1 + r, xx = x0 - 1 + c;
        int cic = cb + ci;
        float v = 0.f;
        bool ok = (unsigned)yy < 64u && (unsigned)xx < 96u &&
                  (unsigned)(yy + dj) < 64u && (unsigned)(xx + di) < 96u;
        if (ok)
          v = (cic < 32) ? f1b[cic * 6144 + yy * 96 + xx]
                         : f2b[(cic - 32) * 6144 + (yy + dj) * 96 + (xx + di)];
        s_in[ci * 340 + r * 34 + c] = v;
      }
      // weights for this (coc, cb)
      for (int t = tid; t < 32 * 8 * 9; t += 128) {
        int co  = t & 31;
        int rem = t >> 5;
        int k   = rem % 9;
        int ci  = rem / 9;
        s_w[(ci * 9 + k) * 32 + co] =
            w1[((coc * 32 + co) * 64 + cb + ci) * 9 + k];
      }
      __syncthreads();

      if (act) {
#pragma unroll
        for (int ci = 0; ci < 8; ci++)
#pragma unroll
          for (int ky = 0; ky < 3; ky++)
#pragma unroll
            for (int kx = 0; kx < 3; kx++) {
              float v = s_in[ci * 340 + (py + ky) * 34 + (px + kx)];
              const float4* wv = reinterpret_cast<const float4*>(
                  &s_w[(ci * 9 + ky * 3 + kx) * 32]);
#pragma unroll
              for (int q = 0; q < 8; q++) {
                float4 ww = wv[q];
                acc[4 * q + 0] += ww.x * v;
                acc[4 * q + 1] += ww.y * v;
                acc[4 * q + 2] += ww.z * v;
                acc[4 * q + 3] += ww.w * v;
              }
            }
      }
    }
    if (act) {
#pragma unroll
      for (int c = 0; c < 32; c++)
        g_x1[((size_t)n * 96 + coc * 32 + c) * PL1 +
             (y0 + py + 1) * 100 + (x0 + px + 1)] = acc[c];
    }
    __syncthreads();
  }
}

// ---------------------------------------------------------------------------
// 2) 3x3 s2 conv (R3 form), padded 66x100 -> padded 34x52.
// ---------------------------------------------------------------------------
__global__ void __launch_bounds__(128)
conv3x3_s2_k(const float* __restrict__ in, const float* __restrict__ w,
             float* __restrict__ out, int Cin, int Cout) {
  constexpr int RS = 37;
  constexpr int PLS = 17 * RS;

  __shared__ float s_in[8 * PLS];
  __shared__ __align__(16) float s_w[8 * 9 * 16];

  const int tid = threadIdx.x;
  const int cg  = tid >> 5;
  const int py  = (tid & 31) >> 2;
  const int pxg = tid & 3;

  const int tx = blockIdx.x % 3;
  const int ty = blockIdx.x / 3;
  const int n  = blockIdx.z;
  const int coB = blockIdx.y * 16;
  const int y0 = ty * 8, x0 = tx * 16;

  const float* inN = in + (size_t)n * Cin * PL1;

  float acc[4][4];
#pragma unroll
  for (int q = 0; q < 4; q++)
#pragma unroll
    for (int p = 0; p < 4; p++) acc[q][p] = 0.f;

  for (int cb = 0; cb < Cin; cb += 8) {
    __syncthreads();
#pragma unroll
    for (int c = 0; c < 8; c++) {
      for (int t = tid; t < 17 * 9; t += 128) {
        int r = t / 9;
        int q = t - r * 9;
        const float4 v = *reinterpret_cast<const float4*>(
            inN + (size_t)(cb + c) * PL1 + (2 * y0 + r) * 100 + 2 * x0 + 4 * q);
        float* dst = &s_in[c * PLS + r * RS + 4 * q];
        dst[0] = v.x; dst[1] = v.y; dst[2] = v.z; dst[3] = v.w;
      }
    }
    for (int t = tid; t < 16 * 8 * 9; t += 128) {
      int lco = t & 15;
      int rem = t >> 4;
      int k   = rem % 9;
      int lci = rem / 9;
      s_w[(lci * 9 + k) * 16 + lco] =
          w[((size_t)(coB + lco) * Cin + (cb + lci)) * 9 + k];
    }
    __syncthreads();

#pragma unroll
    for (int ci = 0; ci < 8; ci++) {
#pragma unroll
      for (int ky = 0; ky < 3; ky++) {
        float r[9];
#pragma unroll
        for (int m = 0; m < 9; m++)
          r[m] = s_in[ci * PLS + (2 * py + ky) * RS + pxg * 8 + m];
#pragma unroll
        for (int kx = 0; kx < 3; kx++) {
          float4 wv =
              reinterpret_cast<const float4*>(s_w)[(ci * 9 + ky * 3 + kx) * 4 + cg];
#pragma unroll
          for (int p = 0; p < 4; p++) {
            float iv = r[2 * p + kx];
            acc[0][p] += wv.x * iv;
            acc[1][p] += wv.y * iv;
            acc[2][p] += wv.z * iv;
            acc[3][p] += wv.w * iv;
          }
        }
      }
    }
  }

  float* outN = out + (size_t)n * Cout * PL2;
  const int gy = y0 + py + 1;
#pragma unroll
  for (int q = 0; q < 4; q++) {
    int co = coB + cg * 4 + q;
#pragma unroll
    for (int p = 0; p < 4; p++)
      outN[(size_t)co * PL2 + gy * 52 + x0 + pxg * 4 + p + 1] = acc[q][p];
  }
}

// ---------------------------------------------------------------------------
// 3) Instance norm + leaky, padded in-place.
// ---------------------------------------------------------------------------
template <int H, int W, int WP>
__global__ void __launch_bounds__(256)
inorm_leaky_k(float* __restrict__ x) {
  constexpr int PLANE = (H + 2) * WP;
  float* p = x + (size_t)blockIdx.x * PLANE;
  const int wid = threadIdx.x >> 5, ln = threadIdx.x & 31;

  float s = 0.f, q = 0.f;
  for (int y = wid; y < H; y += 8)
    for (int xx = ln; xx < W; xx += 32) {
      float v = p[(y + 1) * WP + xx + 1];
      s += v; q += v * v;
    }
#pragma unroll
  for (int o = 16; o > 0; o >>= 1) {
    s += __shfl_xor_sync(0xffffffffu, s, o);
    q += __shfl_xor_sync(0xffffffffu, q, o);
  }
  __shared__ float ss[8], sq[8];
  if (ln == 0) { ss[wid] = s; sq[wid] = q; }
  __syncthreads();
  if (threadIdx.x == 0) {
    float S = 0.f, Q = 0.f;
#pragma unroll
    for (int i = 0; i < 8; i++) { S += ss[i]; Q += sq[i]; }
    float m = S / (float)(H * W);
    float var = Q / (float)(H * W) - m * m;
    ss[0] = m;
    sq[0] = rsqrtf(var + 1e-5f);
  }
  __syncthreads();
  const float m = ss[0], inv = sq[0];
  for (int y = wid; y < H; y += 8)
    for (int xx = ln; xx < W; xx += 32) {
      float v = (p[(y + 1) * WP + xx + 1] - m) * inv;
      p[(y + 1) * WP + xx + 1] = v >= 0.f ? v : 0.01f * v;
    }
}

// ---------------------------------------------------------------------------
// 4) 4x4 s2 deconv (R3 form), 4 parity classes.
// ---------------------------------------------------------------------------
__global__ void __launch_bounds__(256)
deconv4x4_k(const float* __restrict__ in, const float* __restrict__ w5,
            float* __restrict__ out) {
  constexpr int RS = 20, PLS = 18 * RS;

  __shared__ float s_in[16 * PLS];
  __shared__ __align__(16) float s_w[16 * 4 * 32];

  const int parity = blockIdx.y;
  const int a = parity >> 1, b = parity & 1;
  const int n = blockIdx.z;
  const int tx = blockIdx.x % 3;
  const int ty = blockIdx.x / 3;
  const int tid = threadIdx.x;
  const int ly = tid >> 4, lx = tid & 15;
  const int ybase = ty * 16, xbase = tx * 16;

  const float* inN = in + (size_t)n * 64 * PL2;

  float acc[32];
#pragma unroll
  for (int c = 0; c < 32; c++) acc[c] = 0.f;

  for (int cb = 0; cb < 64; cb += 16) {
    __syncthreads();
#pragma unroll
    for (int t = tid; t < 16 * 18 * 5; t += 256) {
      int c   = t / 90;
      int rem = t - c * 90;
      int r   = rem / 5;
      int q   = rem - r * 5;
      const float4 v = *reinterpret_cast<const float4*>(
          inN + (size_t)(cb + c) * PL2 + (ybase + r) * 52 + xbase + 4 * q);
      float* dst = &s_in[c * PLS + r * RS + 4 * q];
      dst[0] = v.x; dst[1] = v.y; dst[2] = v.z; dst[3] = v.w;
    }
    for (int t = tid; t < 16 * 4 * 32; t += 256) {
      int co  = t & 31;
      int tap = (t >> 5) & 3;
      int lci = t >> 7;
      int s  = tap >> 1, tt = tap & 1;
      s_w[t] = w5[(((size_t)(cb + lci) * 32 + co) * 4 + (3 - (a + 2 * s))) * 4 +
                  (3 - (b + 2 * tt))];
    }
    __syncthreads();

#pragma unroll 4
    for (int ci = 0; ci < 16; ci++) {
      float i00 = s_in[ci * PLS + (ly + a + 0) * RS + lx + b + 0];
      float i01 = s_in[ci * PLS + (ly + a + 0) * RS + lx + b + 1];
      float i10 = s_in[ci * PLS + (ly + a + 1) * RS + lx + b + 0];
      float i11 = s_in[ci * PLS + (ly + a + 1) * RS + lx + b + 1];
      const float4* wp = reinterpret_cast<const float4*>(s_w + ci * 128);
#pragma unroll
      for (int cq = 0; cq < 8; cq++) {
        float4 w0 = wp[cq];
        float4 w1 = wp[8 + cq];
        float4 w2 = wp[16 + cq];
        float4 w3 = wp[24 + cq];
        acc[4 * cq + 0] += w0.x * i00 + w1.x * i01 + w2.x * i10 + w3.x * i11;
        acc[4 * cq + 1] += w0.y * i00 + w1.y * i01 + w2.y * i10 + w3.y * i11;
        acc[4 * cq + 2] += w0.z * i00 + w1.z * i01 + w2.z * i10 + w3.z * i11;
        acc[4 * cq + 3] += w0.w * i00 + w1.w * i01 + w2.w * i10 + w3.w * i11;
      }
    }
  }

  const int oy = 2 * (ybase + ly) + a + 1;
  const int ox = 2 * (xbase + lx) + b + 1;
  float* outN = out + (size_t)n * 32 * PL1;
#pragma unroll
  for (int co = 0; co < 32; co++)
    outN[(size_t)co * PL1 + oy * 100 + ox] = acc[co];
}

// ---------------------------------------------------------------------------
// 5) Final 3x3 conv 32 -> 1 + bias (R3 form).
// ---------------------------------------------------------------------------
__global__ void __launch_bounds__(256)
conv_final_k(const float* __restrict__ in, const float* __restrict__ w6,
             const float* __restrict__ b6, float* __restrict__ out) {
  constexpr int RS = 37, PLS = 10 * RS;
  __shared__ float s_in[8 * PLS];
  __shared__ float sw[288];
  __shared__ float sb;

  const int tid = threadIdx.x;
  const int tx = blockIdx.x % 3;
  const int ty = blockIdx.x / 3;
  const int n  = blockIdx.y;
  const int y0 = ty * 8, x0 = tx * 32;
  const int px = tid & 31, py = tid >> 5;

  for (int t = tid; t < 288; t += 256) sw[t] = w6[t];
  if (tid == 0) sb = b6[0];

  const float* inN = in + (size_t)n * 32 * PL1;
  float acc = 0.f;

  for (int cb = 0; cb < 32; cb += 8) {
    __syncthreads();
#pragma unroll
    for (int t = tid; t < 8 * 10 * 9; t += 256) {
      int c   = t / 90;
      int rem = t - c * 90;
      int r   = rem / 9;
      int q   = rem - r * 9;
      const float4 v = *reinterpret_cast<const float4*>(
          inN + (size_t)(cb + c) * PL1 + (y0 + r) * 100 + x0 + 4 * q);
      float* dst = &s_in[c * PLS + r * RS + 4 * q];
      dst[0] = v.x; dst[1] = v.y; dst[2] = v.z; dst[3] = v.w;
    }
    __syncthreads();
#pragma unroll
    for (int c = 0; c < 8; c++)
#pragma unroll
      for (int ky = 0; ky < 3; ky++)
#pragma unroll
        for (int kx = 0; kx < 3; kx++)
          acc += sw[(cb + c) * 9 + ky * 3 + kx] *
                 s_in[c * PLS + (py + ky) * RS + px + kx];
  }

  out[(size_t)n * 6144 + (y0 + py) * 96 + x0 + px] = acc + sb;
}

// ---------------------------------------------------------------------------
// Launch
// ---------------------------------------------------------------------------
extern "C" void kernel_launch(void* const* d_in, const int* in_sizes, int n_in,
                              void* d_out, int out_size) {
  const float* f1 = (const float*)d_in[0];
  const float* f2 = (const float*)d_in[1];
  const float* w1 = (const float*)d_in[2];
  const float* w2 = (const float*)d_in[3];
  const float* w3 = (const float*)d_in[4];
  const float* w4 = (const float*)d_in[5];
  const float* w5 = (const float*)d_in[6];
  const float* w6 = (const float*)d_in[7];
  const float* b6 = (const float*)d_in[8];
  float* out = (float*)d_out;

  float *x1, *x2, *x3, *x4, *x5, *f1p, *f2c, *U, *V, *w1a, *w1b;
  cudaGetSymbolAddress((void**)&x1, g_x1);
  cudaGetSymbolAddress((void**)&x2, g_x2);
  cudaGetSymbolAddress((void**)&x3, g_x3);
  cudaGetSymbolAddress((void**)&x4, g_x4);
  cudaGetSymbolAddress((void**)&x5, g_x5);
  cudaGetSymbolAddress((void**)&f1p, g_f1p);
  cudaGetSymbolAddress((void**)&f2c, g_f2c);
  cudaGetSymbolAddress((void**)&U, g_U);
  cudaGetSymbolAddress((void**)&V, g_V);
  cudaGetSymbolAddress((void**)&w1a, g_w1a);
  cudaGetSymbolAddress((void**)&w1b, g_w1b);

  // conv1 via factorization
  prep_k<<<(2 * 32 * 6144 + 255) / 256, 256>>>(f1, f2, w1);
  conv3x3_s1_k<32, 64, 96, 100><<<dim3(24, 6, 2), 256>>>(f1p, w1a, U, 32, 96);
  conv_v_k<<<dim3(63, 6, 2), 128>>>(f2c, w1b, V);
  combine_k<<<(NIMG * 96 * 6144 + 255) / 256, 256>>>();
  stripfix_k<<<dim3(20, NIMG), 128>>>(f1, f2, w1);
  inorm_leaky_k<64, 96, 100><<<NIMG * 96, 256>>>(x1);

  // conv2 s2 96->128
  conv3x3_s2_k<<<dim3(12, 8, NIMG), 128>>>(x1, w2, x2, 96, 128);
  inorm_leaky_k<32, 48, 52><<<NIMG * 128, 256>>>(x2);

  // conv3 128->128 @32x48
  conv3x3_s1_k<16, 32, 48, 52><<<dim3(12, 8, NIMG), 128>>>(x2, w3, x3, 128, 128);
  inorm_leaky_k<32, 48, 52><<<NIMG * 128, 256>>>(x3);

  // conv4 128->64 @32x48
  conv3x3_s1_k<16, 32, 48, 52><<<dim3(12, 4, NIMG), 128>>>(x3, w4, x4, 128, 64);
  inorm_leaky_k<32, 48, 52><<<NIMG * 64, 256>>>(x4);

  // deconv 64->32
  deconv4x4_k<<<dim3(6, 4, NIMG), 256>>>(x4, w5, x5);
  inorm_leaky_k<64, 96, 100><<<NIMG * 32, 256>>>(x5);

  // final conv
  conv_final_k<<<dim3(24, NIMG), 256>>>(x5, w6, b6, out);
}

// round 8
// speedup vs baseline: 1.5304x; 1.1741x over previous
#include <cuda_runtime.h>
#include <cuda_bf16.h>
#include <cstdint>

// ---------------------------------------------------------------------------
// Padded planar layouts [C][H+2][WP], 1-px zero halo (globals zero-init).
// ---------------------------------------------------------------------------
#define NIMG 98
#define PL1 (66 * 100)
#define PL2 (34 * 52)
#define PLV (72 * 112)
#define PLC (80 * 120)

__device__ float g_x1 [NIMG * 96 * PL1];
__device__ float g_x2 [NIMG * 128 * PL2];
__device__ float g_x3 [NIMG * 128 * PL2];
__device__ float g_x4 [NIMG * 64 * PL2];
__device__ float g_x5 [NIMG * 32 * PL1];

// conv1 factorization scratch
__device__ float g_f1p[2 * 32 * PL1];
__device__ float g_f2c[2 * 32 * PLC];
__device__ float g_U  [2 * 96 * PL1];
__device__ float g_V  [2 * 96 * PLV];
__device__ float g_w1a[96 * 32 * 9];
__device__ float g_w1b[96 * 32 * 9];

// conv3 tensor-core path scratch (mma.sync, compute_100-legal)
__device__ unsigned short g_Xh[(size_t)NIMG * 1768 * 128];  // x2 channel-last bf16 hi (padded 34x52)
__device__ unsigned short g_Xl[(size_t)NIMG * 1768 * 128];  // lo
__device__ unsigned short g_B3h[9 * 128 * 128];             // w3 hi [tap][co][ci]
__device__ unsigned short g_B3l[9 * 128 * 128];             // lo
__device__ float g_x3cl[(size_t)NIMG * 1536 * 128];         // conv3 out, channel-last

// strip-fix segment table
__device__ const int c_segy[20] = {0,0,0, 60,60,60, 4,12,20,28,36,44,52, 4,12,20,28,36,44,52};
__device__ const int c_segx[20] = {0,32,64, 0,32,64, 0,0,0,0,0,0,0, 92,92,92,92,92,92,92};
__device__ const int c_segh[20] = {4,4,4, 4,4,4, 8,8,8,8,8,8,8, 8,8,8,8,8,8,8};
__device__ const int c_segw[20] = {32,32,32, 32,32,32, 4,4,4,4,4,4,4, 4,4,4,4,4,4,4};

// ---------------------------------------------------------------------------
// mma.sync helpers (sm_80+, legal under compute_100)
// ---------------------------------------------------------------------------
__device__ __forceinline__ uint32_t smem_u32(const void* p) {
  uint32_t a;
  asm("{ .reg .u64 t; cvta.to.shared.u64 t, %1; cvt.u32.u64 %0, t; }"
      : "=r"(a) : "l"(p));
  return a;
}
__device__ __forceinline__ void ldsm_x4(unsigned r[4], uint32_t addr) {
  asm volatile("ldmatrix.sync.aligned.m8n8.x4.shared.b16 {%0,%1,%2,%3}, [%4];"
               : "=r"(r[0]), "=r"(r[1]), "=r"(r[2]), "=r"(r[3]) : "r"(addr));
}
__device__ __forceinline__ void ldsm_x2(unsigned r[2], uint32_t addr) {
  asm volatile("ldmatrix.sync.aligned.m8n8.x2.shared.b16 {%0,%1}, [%2];"
               : "=r"(r[0]), "=r"(r[1]) : "r"(addr));
}
__device__ __forceinline__ void mma_bf16(float d[4], const unsigned a[4],
                                         const unsigned b[2]) {
  asm volatile(
      "mma.sync.aligned.m16n8k16.row.col.f32.bf16.bf16.f32 "
      "{%0,%1,%2,%3}, {%4,%5,%6,%7}, {%8,%9}, {%0,%1,%2,%3};"
      : "+f"(d[0]), "+f"(d[1]), "+f"(d[2]), "+f"(d[3])
      : "r"(a[0]), "r"(a[1]), "r"(a[2]), "r"(a[3]), "r"(b[0]), "r"(b[1]));
}

// ---------------------------------------------------------------------------
// prep: pad f1, embed f2, split w1
// ---------------------------------------------------------------------------
__global__ void prep_k(const float* __restrict__ f1, const float* __restrict__ f2,
                       const float* __restrict__ w1) {
  int idx = blockIdx.x * blockDim.x + threadIdx.x;
  if (idx < 2 * 32 * 6144) {
    int x = idx % 96, y = (idx / 96) % 64, c = idx / 6144;
    g_f1p[(size_t)c * PL1 + (y + 1) * 100 + x + 1] = f1[idx];
    g_f2c[(size_t)c * PLC + (y + 8) * 120 + x + 8] = f2[idx];
  }
  if (idx < 96 * 64 * 9) {
    int co = idx / 576, rem = idx % 576, ci = rem / 9, k = rem % 9;
    if (ci < 32) g_w1a[(co * 32 + ci) * 9 + k] = w1[idx];
    else         g_w1b[(co * 32 + (ci - 32)) * 9 + k] = w1[idx];
  }
}

// w3 -> bf16 hi/lo, layout [tap][co][ci]
__global__ void wprep3_k(const float* __restrict__ w3) {
  int idx = blockIdx.x * blockDim.x + threadIdx.x;
  if (idx >= 9 * 128 * 128) return;
  int ci  = idx & 127;
  int co  = (idx >> 7) & 127;
  int tap = idx >> 14;
  float v = w3[(co * 128 + ci) * 9 + tap];
  __nv_bfloat16 h = __float2bfloat16(v);
  __nv_bfloat16 l = __float2bfloat16(v - __bfloat162float(h));
  g_B3h[idx] = __bfloat16_as_ushort(h);
  g_B3l[idx] = __bfloat16_as_ushort(l);
}

// ---------------------------------------------------------------------------
// 3x3 s1 conv (scalar, R3 form)
// ---------------------------------------------------------------------------
template <int TW, int H, int W, int WP>
__global__ void __launch_bounds__(8 * TW)
conv3x3_s1_k(const float* __restrict__ in, const float* __restrict__ w,
             float* __restrict__ out, int Cin, int Cout) {
  constexpr int PXG = TW / 4;
  constexpr int NT  = 8 * TW;
  constexpr int RS  = 37;
  constexpr int PLS = 10 * RS;
  constexpr int F4  = (TW + 4) / 4;
  constexpr int PLANE = (H + 2) * WP;

  __shared__ float s_in[8 * PLS];
  __shared__ __align__(16) float s_w[8 * 9 * 16];

  const int tid = threadIdx.x;
  const int cg  = tid / (8 * PXG);
  const int pid = tid % (8 * PXG);
  const int py  = pid / PXG;
  const int pxg = pid % PXG;

  const int tilesX = W / TW;
  const int tx = blockIdx.x % tilesX;
  const int ty = blockIdx.x / tilesX;
  const int n  = blockIdx.z;
  const int coB = blockIdx.y * 16;
  const int y0 = ty * 8, x0 = tx * TW;

  const float* inN = in + (size_t)n * Cin * PLANE;

  float acc[4][4];
#pragma unroll
  for (int q = 0; q < 4; q++)
#pragma unroll
    for (int p = 0; p < 4; p++) acc[q][p] = 0.f;

  for (int cb = 0; cb < Cin; cb += 8) {
    __syncthreads();
#pragma unroll
    for (int t = tid; t < 8 * 10 * F4; t += NT) {
      int c   = t / (10 * F4);
      int rem = t - c * (10 * F4);
      int r   = rem / F4;
      int q   = rem - r * F4;
      const float4 v = *reinterpret_cast<const float4*>(
          inN + (size_t)(cb + c) * PLANE + (y0 + r) * WP + x0 + 4 * q);
      float* dst = &s_in[c * PLS + r * RS + 4 * q];
      dst[0] = v.x; dst[1] = v.y; dst[2] = v.z; dst[3] = v.w;
    }
    for (int t = tid; t < 16 * 8 * 9; t += NT) {
      int lco = t & 15;
      int rem = t >> 4;
      int k   = rem % 9;
      int lci = rem / 9;
      s_w[(lci * 9 + k) * 16 + lco] =
          w[((size_t)(coB + lco) * Cin + (cb + lci)) * 9 + k];
    }
    __syncthreads();

#pragma unroll
    for (int ci = 0; ci < 8; ci++) {
#pragma unroll
      for (int ky = 0; ky < 3; ky++) {
        float r[6];
#pragma unroll
        for (int j = 0; j < 6; j++)
          r[j] = s_in[ci * PLS + (py + ky) * RS + pxg * 4 + j];
#pragma unroll
        for (int kx = 0; kx < 3; kx++) {
          float4 wv =
              reinterpret_cast<const float4*>(s_w)[(ci * 9 + ky * 3 + kx) * 4 + cg];
#pragma unroll
          for (int p = 0; p < 4; p++) {
            float iv = r[p + kx];
            acc[0][p] += wv.x * iv;
            acc[1][p] += wv.y * iv;
            acc[2][p] += wv.z * iv;
            acc[3][p] += wv.w * iv;
          }
        }
      }
    }
  }

  float* outN = out + (size_t)n * Cout * PLANE;
  const int gy = y0 + py + 1;
#pragma unroll
  for (int q = 0; q < 4; q++) {
    int co = coB + cg * 4 + q;
#pragma unroll
    for (int p = 0; p < 4; p++)
      outN[(size_t)co * PLANE + gy * WP + x0 + pxg * 4 + p + 1] = acc[q][p];
  }
}

// ---------------------------------------------------------------------------
// V = conv3x3(zero-padded f2) on extended 72x112 grid
// ---------------------------------------------------------------------------
__global__ void __launch_bounds__(128)
conv_v_k(const float* __restrict__ in, const float* __restrict__ w,
         float* __restrict__ out) {
  constexpr int RS = 37, PLS = 10 * RS;
  __shared__ float s_in[8 * PLS];
  __shared__ __align__(16) float s_w[8 * 9 * 16];

  const int tid = threadIdx.x;
  const int cg  = tid >> 5;
  const int pid = tid & 31;
  const int py  = pid >> 2;
  const int pxg = pid & 3;

  const int tx = blockIdx.x % 7;
  const int ty = blockIdx.x / 7;
  const int n  = blockIdx.z;
  const int coB = blockIdx.y * 16;
  const int y0 = ty * 8, x0 = tx * 16;

  const float* inN = in + (size_t)n * 32 * PLC;

  float acc[4][4];
#pragma unroll
  for (int q = 0; q < 4; q++)
#pragma unroll
    for (int p = 0; p < 4; p++) acc[q][p] = 0.f;

  for (int cb = 0; cb < 32; cb += 8) {
    __syncthreads();
#pragma unroll
    for (int t = tid; t < 8 * 10 * 5; t += 128) {
      int c   = t / 50;
      int rem = t - c * 50;
      int r   = rem / 5;
      int q   = rem - r * 5;
      const float4 v = *reinterpret_cast<const float4*>(
          inN + (size_t)(cb + c) * PLC + (y0 + r + 4) * 120 + x0 + 4 * q + 4);
      float* dst = &s_in[c * PLS + r * RS + 4 * q];
      dst[0] = v.x; dst[1] = v.y; dst[2] = v.z; dst[3] = v.w;
    }
    for (int t = tid; t < 16 * 8 * 9; t += 128) {
      int lco = t & 15;
      int rem = t >> 4;
      int k   = rem % 9;
      int lci = rem / 9;
      s_w[(lci * 9 + k) * 16 + lco] =
          w[((coB + lco) * 32 + cb + lci) * 9 + k];
    }
    __syncthreads();

#pragma unroll
    for (int ci = 0; ci < 8; ci++) {
#pragma unroll
      for (int ky = 0; ky < 3; ky++) {
        float r[6];
#pragma unroll
        for (int j = 0; j < 6; j++)
          r[j] = s_in[ci * PLS + (py + ky) * RS + pxg * 4 + j];
#pragma unroll
        for (int kx = 0; kx < 3; kx++) {
          float4 wv =
              reinterpret_cast<const float4*>(s_w)[(ci * 9 + ky * 3 + kx) * 4 + cg];
#pragma unroll
          for (int p = 0; p < 4; p++) {
            float iv = r[p + kx];
            acc[0][p] += wv.x * iv;
            acc[1][p] += wv.y * iv;
            acc[2][p] += wv.z * iv;
            acc[3][p] += wv.w * iv;
          }
        }
      }
    }
  }

  float* outN = out + (size_t)n * 96 * PLV;
  const int gy = y0 + py;
#pragma unroll
  for (int q = 0; q < 4; q++) {
    int co = coB + cg * 4 + q;
#pragma unroll
    for (int p = 0; p < 4; p++)
      outN[(size_t)co * PLV + gy * 112 + x0 + pxg * 4 + p] = acc[q][p];
  }
}

// ---------------------------------------------------------------------------
// combine: x1 = U + shift(V)
// ---------------------------------------------------------------------------
__global__ void __launch_bounds__(256) combine_k() {
  const int bid = blockIdx.x;           // n*96 + co
  const int co = bid % 96, n = bid / 96;
  const int b = n / 49, d = n % 49;
  const int di = d / 7 - 3, dj = d % 7 - 3;

  const float* U = g_U + ((size_t)(b * 96 + co)) * PL1;
  const float* V = g_V + ((size_t)(b * 96 + co)) * PLV + (dj + 3) * 112 + (di + 3);
  float* X = g_x1 + ((size_t)(n * 96 + co)) * PL1;

  const int y0 = threadIdx.x >> 5, xl = threadIdx.x & 31;
  for (int y = y0; y < 64; y += 8) {
    const int ro = (y + 1) * 100 + 1;
    const int rv = y * 112;
#pragma unroll
    for (int x = xl; x < 96; x += 32)
      X[ro + x] = U[ro + x] + V[rv + x];
  }
}

// ---------------------------------------------------------------------------
// strip fix (exact conv1 on 1216 border px)
// ---------------------------------------------------------------------------
__global__ void __launch_bounds__(128)
stripfix_k(const float* __restrict__ f1, const float* __restrict__ f2,
           const float* __restrict__ w1) {
  const int sid = blockIdx.x;
  const int n   = blockIdx.y;
  const int y0 = c_segy[sid], x0 = c_segx[sid];
  const int h  = c_segh[sid], w = c_segw[sid];
  const int b = n / 49, d = n % 49;
  const int di = d / 7 - 3;
  const int dj = d % 7 - 3;
  const int H2 = h + 2, W2 = w + 2;

  __shared__ float s_in[8 * 10 * 34];
  __shared__ __align__(16) float s_w[8 * 9 * 32];

  const int tid = threadIdx.x;
  const bool act = tid < h * w;
  const int py = act ? tid / w : 0;
  const int px = act ? tid % w : 0;

  const float* f1b = f1 + (size_t)b * 32 * 6144;
  const float* f2b = f2 + (size_t)b * 32 * 6144;

  for (int coc = 0; coc < 3; coc++) {
    float acc[32];
#pragma unroll
    for (int c = 0; c < 32; c++) acc[c] = 0.f;

    for (int cb = 0; cb < 64; cb += 8) {
      __syncthreads();
      for (int t = tid; t < 8 * H2 * W2; t += 128) {
        int ci  = t / (H2 * W2);
        int rem = t - ci * (H2 * W2);
        int r   = rem / W2;
        int c   = rem - r * W2;
        int yy = y0 - 1 + r, xx = x0 - 1 + c;
        int cic = cb + ci;
        float v = 0.f;
        bool ok = (unsigned)yy < 64u && (unsigned)xx < 96u &&
                  (unsigned)(yy + dj) < 64u && (unsigned)(xx + di) < 96u;
        if (ok)
          v = (cic < 32) ? f1b[cic * 6144 + yy * 96 + xx]
                         : f2b[(cic - 32) * 6144 + (yy + dj) * 96 + (xx + di)];
        s_in[ci * 340 + r * 34 + c] = v;
      }
      for (int t = tid; t < 32 * 8 * 9; t += 128) {
        int co  = t & 31;
        int rem = t >> 5;
        int k   = rem % 9;
        int ci  = rem / 9;
        s_w[(ci * 9 + k) * 32 + co] =
            w1[((coc * 32 + co) * 64 + cb + ci) * 9 + k];
      }
      __syncthreads();

      if (act) {
#pragma unroll
        for (int ci = 0; ci < 8; ci++)
#pragma unroll
          for (int ky = 0; ky < 3; ky++)
#pragma unroll
            for (int kx = 0; kx < 3; kx++) {
              float v = s_in[ci * 340 + (py + ky) * 34 + (px + kx)];
              const float4* wv = reinterpret_cast<const float4*>(
                  &s_w[(ci * 9 + ky * 3 + kx) * 32]);
#pragma unroll
              for (int q = 0; q < 8; q++) {
                float4 ww = wv[q];
                acc[4 * q + 0] += ww.x * v;
                acc[4 * q + 1] += ww.y * v;
                acc[4 * q + 2] += ww.z * v;
                acc[4 * q + 3] += ww.w * v;
              }
            }
      }
    }
    if (act) {
#pragma unroll
      for (int c = 0; c < 32; c++)
        g_x1[((size_t)n * 96 + coc * 32 + c) * PL1 +
             (y0 + py + 1) * 100 + (x0 + px + 1)] = acc[c];
    }
    __syncthreads();
  }
}

// ---------------------------------------------------------------------------
// 3x3 s2 conv (scalar, R3 form)
// ---------------------------------------------------------------------------
__global__ void __launch_bounds__(128)
conv3x3_s2_k(const float* __restrict__ in, const float* __restrict__ w,
             float* __restrict__ out, int Cin, int Cout) {
  constexpr int RS = 37;
  constexpr int PLS = 17 * RS;

  __shared__ float s_in[8 * PLS];
  __shared__ __align__(16) float s_w[8 * 9 * 16];

  const int tid = threadIdx.x;
  const int cg  = tid >> 5;
  const int py  = (tid & 31) >> 2;
  const int pxg = tid & 3;

  const int tx = blockIdx.x % 3;
  const int ty = blockIdx.x / 3;
  const int n  = blockIdx.z;
  const int coB = blockIdx.y * 16;
  const int y0 = ty * 8, x0 = tx * 16;

  const float* inN = in + (size_t)n * Cin * PL1;

  float acc[4][4];
#pragma unroll
  for (int q = 0; q < 4; q++)
#pragma unroll
    for (int p = 0; p < 4; p++) acc[q][p] = 0.f;

  for (int cb = 0; cb < Cin; cb += 8) {
    __syncthreads();
#pragma unroll
    for (int c = 0; c < 8; c++) {
      for (int t = tid; t < 17 * 9; t += 128) {
        int r = t / 9;
        int q = t - r * 9;
        const float4 v = *reinterpret_cast<const float4*>(
            inN + (size_t)(cb + c) * PL1 + (2 * y0 + r) * 100 + 2 * x0 + 4 * q);
        float* dst = &s_in[c * PLS + r * RS + 4 * q];
        dst[0] = v.x; dst[1] = v.y; dst[2] = v.z; dst[3] = v.w;
      }
    }
    for (int t = tid; t < 16 * 8 * 9; t += 128) {
      int lco = t & 15;
      int rem = t >> 4;
      int k   = rem % 9;
      int lci = rem / 9;
      s_w[(lci * 9 + k) * 16 + lco] =
          w[((size_t)(coB + lco) * Cin + (cb + lci)) * 9 + k];
    }
    __syncthreads();

#pragma unroll
    for (int ci = 0; ci < 8; ci++) {
#pragma unroll
      for (int ky = 0; ky < 3; ky++) {
        float r[9];
#pragma unroll
        for (int m = 0; m < 9; m++)
          r[m] = s_in[ci * PLS + (2 * py + ky) * RS + pxg * 8 + m];
#pragma unroll
        for (int kx = 0; kx < 3; kx++) {
          float4 wv =
              reinterpret_cast<const float4*>(s_w)[(ci * 9 + ky * 3 + kx) * 4 + cg];
#pragma unroll
          for (int p = 0; p < 4; p++) {
            float iv = r[2 * p + kx];
            acc[0][p] += wv.x * iv;
            acc[1][p] += wv.y * iv;
            acc[2][p] += wv.z * iv;
            acc[3][p] += wv.w * iv;
          }
        }
      }
    }
  }

  float* outN = out + (size_t)n * Cout * PL2;
  const int gy = y0 + py + 1;
#pragma unroll
  for (int q = 0; q < 4; q++) {
    int co = coB + cg * 4 + q;
#pragma unroll
    for (int p = 0; p < 4; p++)
      outN[(size_t)co * PL2 + gy * 52 + x0 + pxg * 4 + p + 1] = acc[q][p];
  }
}

// ---------------------------------------------------------------------------
// Instance norm + leaky (planar padded)
// ---------------------------------------------------------------------------
template <int H, int W, int WP>
__global__ void __launch_bounds__(256)
inorm_leaky_k(float* __restrict__ x) {
  constexpr int PLANE = (H + 2) * WP;
  float* p = x + (size_t)blockIdx.x * PLANE;
  const int wid = threadIdx.x >> 5, ln = threadIdx.x & 31;

  float s = 0.f, q = 0.f;
  for (int y = wid; y < H; y += 8)
    for (int xx = ln; xx < W; xx += 32) {
      float v = p[(y + 1) * WP + xx + 1];
      s += v; q += v * v;
    }
#pragma unroll
  for (int o = 16; o > 0; o >>= 1) {
    s += __shfl_xor_sync(0xffffffffu, s, o);
    q += __shfl_xor_sync(0xffffffffu, q, o);
  }
  __shared__ float ss[8], sq[8];
  if (ln == 0) { ss[wid] = s; sq[wid] = q; }
  __syncthreads();
  if (threadIdx.x == 0) {
    float S = 0.f, Q = 0.f;
#pragma unroll
    for (int i = 0; i < 8; i++) { S += ss[i]; Q += sq[i]; }
    float m = S / (float)(H * W);
    float var = Q / (float)(H * W) - m * m;
    ss[0] = m;
    sq[0] = rsqrtf(var + 1e-5f);
  }
  __syncthreads();
  const float m = ss[0], inv = sq[0];
  for (int y = wid; y < H; y += 8)
    for (int xx = ln; xx < W; xx += 32) {
      float v = (p[(y + 1) * WP + xx + 1] - m) * inv;
      p[(y + 1) * WP + xx + 1] = v >= 0.f ? v : 0.01f * v;
    }
}

// ---------------------------------------------------------------------------
// x2 planar padded fp32 -> channel-last padded bf16 hi/lo [n][34*52][128]
// (halo positions never written -> stay zero)
// ---------------------------------------------------------------------------
__global__ void __launch_bounds__(256)
x2cl_k(const float* __restrict__ x2) {
  __shared__ float s[48 * 129];
  const int y = blockIdx.x;   // 0..31 interior
  const int n = blockIdx.y;
  const int tid = threadIdx.x;
  const int wid = tid >> 5, ln = tid & 31;

  for (int ci = wid; ci < 128; ci += 8) {
    const float* src = x2 + ((size_t)(n * 128 + ci)) * PL2 + (y + 1) * 52 + 1;
    for (int x = ln; x < 48; x += 32) s[x * 129 + ci] = src[x];
  }
  __syncthreads();
  for (int idx = tid; idx < 48 * 128; idx += 256) {
    int x = idx >> 7, ci = idx & 127;
    float v = s[x * 129 + ci];
    __nv_bfloat16 h = __float2bfloat16(v);
    __nv_bfloat16 l = __float2bfloat16(v - __bfloat162float(h));
    size_t o = ((size_t)(n * 1768 + (y + 1) * 52 + (x + 1))) * 128 + ci;
    g_Xh[o] = __bfloat16_as_ushort(h);
    g_Xl[o] = __bfloat16_as_ushort(l);
  }
}

// ---------------------------------------------------------------------------
// gemm3: mma.sync bf16-split GEMM, implicit im2col over 9 taps.
// Block 256 thr, tile M=96 px x N=128 co; K = 9 taps x 128 ci (chunks of 32).
// Warps: warp_m = wid&1 (48 rows), warp_n = wid>>1 (32 cols).
// ---------------------------------------------------------------------------
__global__ void __launch_bounds__(256)
gemm3_k(float* __restrict__ xcl) {
  __shared__ unsigned short sA[2][96 * 40];    // [hi/lo][row][40-stride]
  __shared__ unsigned short sB[2][128 * 40];

  const int tid  = threadIdx.x;
  const int wid  = tid >> 5, lane = tid & 31;
  const int warp_m = wid & 1;          // 0..1
  const int warp_n = wid >> 1;         // 0..3
  const int tile = blockIdx.x;         // 0..15
  const int n    = blockIdx.y;
  const int px0  = tile * 96;

  const uint32_t aB = smem_u32(sA);
  const uint32_t bB = smem_u32(sB);

  float acc[3][4][4];
#pragma unroll
  for (int mi = 0; mi < 3; mi++)
#pragma unroll
    for (int ni = 0; ni < 4; ni++)
#pragma unroll
      for (int j = 0; j < 4; j++) acc[mi][ni][j] = 0.f;

  for (int tap = 0; tap < 9; tap++) {
    const int dy = tap / 3, dx = tap % 3;
    for (int cc = 0; cc < 4; cc++) {
      const int ci0 = cc * 32;
      __syncthreads();
      // A: 96 rows x 32 halfs, hi+lo -> 768 uint4
#pragma unroll
      for (int i = 0; i < 3; i++) {
        int id  = tid + i * 256;             // 0..767
        int buf = id / 384;
        int rem = id - buf * 384;
        int r   = rem >> 2, q = rem & 3;
        int px = px0 + r;
        int y = px / 48, x = px - y * 48;
        int pos = (y + dy) * 52 + (x + dx);
        const uint4* src = reinterpret_cast<const uint4*>(
            (buf ? g_Xl : g_Xh) + ((size_t)(n * 1768 + pos)) * 128 + ci0);
        *reinterpret_cast<uint4*>(&sA[buf][r * 40 + q * 8]) = src[q];
      }
      // B: 128 rows x 32 halfs, hi+lo -> 1024 uint4
#pragma unroll
      for (int i = 0; i < 4; i++) {
        int id  = tid + i * 256;             // 0..1023
        int buf = id >> 9;
        int rem = id & 511;
        int r   = rem >> 2, q = rem & 3;
        const uint4* src = reinterpret_cast<const uint4*>(
            (buf ? g_B3l : g_B3h) + ((size_t)(tap * 128 + r)) * 128 + ci0);
        *reinterpret_cast<uint4*>(&sB[buf][r * 40 + q * 8]) = src[q];
      }
      __syncthreads();

#pragma unroll
      for (int ks = 0; ks < 2; ks++) {
        unsigned ah[3][4], al[3][4], bh[4][2], bl[4][2];
        const int arow = warp_m * 48 + (lane & 7) + ((lane >> 3) & 1) * 8;
        const int acol = ks * 16 + ((lane >> 4) & 1) * 8;
#pragma unroll
        for (int mi = 0; mi < 3; mi++) {
          uint32_t off = (uint32_t)(((arow + mi * 16) * 40 + acol) * 2);
          ldsm_x4(ah[mi], aB + off);
          ldsm_x4(al[mi], aB + 96 * 40 * 2 + off);
        }
        const int brow = warp_n * 32 + (lane & 7);
        const int bcol = ks * 16 + ((lane >> 3) & 1) * 8;
#pragma unroll
        for (int ni = 0; ni < 4; ni++) {
          uint32_t off = (uint32_t)(((brow + ni * 8) * 40 + bcol) * 2);
          ldsm_x2(bh[ni], bB + off);
          ldsm_x2(bl[ni], bB + 128 * 40 * 2 + off);
        }
#pragma unroll
        for (int mi = 0; mi < 3; mi++)
#pragma unroll
          for (int ni = 0; ni < 4; ni++) {
            mma_bf16(acc[mi][ni], ah[mi], bh[ni]);
            mma_bf16(acc[mi][ni], ah[mi], bl[ni]);
            mma_bf16(acc[mi][ni], al[mi], bh[ni]);
          }
      }
    }
  }

  // epilogue: C fragment (row = g, g+8; col = 2*tg, +1)
  const int g = lane >> 2, tg = lane & 3;
#pragma unroll
  for (int mi = 0; mi < 3; mi++) {
#pragma unroll
    for (int ni = 0; ni < 4; ni++) {
      int row = px0 + warp_m * 48 + mi * 16 + g;
      int co  = warp_n * 32 + ni * 8 + tg * 2;
      float* d0 = xcl + ((size_t)(n * 1536 + row)) * 128 + co;
      float* d1 = xcl + ((size_t)(n * 1536 + row + 8)) * 128 + co;
      *reinterpret_cast<float2*>(d0) = make_float2(acc[mi][ni][0], acc[mi][ni][1]);
      *reinterpret_cast<float2*>(d1) = make_float2(acc[mi][ni][2], acc[mi][ni][3]);
    }
  }
}

// ---------------------------------------------------------------------------
// channel-last -> planar padded (x3cl -> g_x3). Block = (y, n).
// ---------------------------------------------------------------------------
__global__ void __launch_bounds__(256)
cl2planar_k(const float* __restrict__ xcl) {
  __shared__ float s[48 * 129];
  const int y = blockIdx.x;
  const int n = blockIdx.y;
  const int tid = threadIdx.x;

  for (int idx = tid; idx < 6144; idx += 256) {
    int co = idx & 127, x = idx >> 7;
    s[x * 129 + co] = xcl[((size_t)(n * 1536 + y * 48 + x)) * 128 + co];
  }
  __syncthreads();
  const int co = tid >> 1, half = tid & 1;
  float* dst = g_x3 + ((size_t)(n * 128 + co)) * PL2 + (y + 1) * 52 + 1 + half * 24;
#pragma unroll
  for (int j = 0; j < 24; j++) dst[j] = s[(half * 24 + j) * 129 + co];
}

// ---------------------------------------------------------------------------
// deconv (R3 form)
// ---------------------------------------------------------------------------
__global__ void __launch_bounds__(256)
deconv4x4_k(const float* __restrict__ in, const float* __restrict__ w5,
            float* __restrict__ out) {
  constexpr int RS = 20, PLS = 18 * RS;

  __shared__ float s_in[16 * PLS];
  __shared__ __align__(16) float s_w[16 * 4 * 32];

  const int parity = blockIdx.y;
  const int a = parity >> 1, b = parity & 1;
  const int n = blockIdx.z;
  const int tx = blockIdx.x % 3;
  const int ty = blockIdx.x / 3;
  const int tid = threadIdx.x;
  const int ly = tid >> 4, lx = tid & 15;
  const int ybase = ty * 16, xbase = tx * 16;

  const float* inN = in + (size_t)n * 64 * PL2;

  float acc[32];
#pragma unroll
  for (int c = 0; c < 32; c++) acc[c] = 0.f;

  for (int cb = 0; cb < 64; cb += 16) {
    __syncthreads();
#pragma unroll
    for (int t = tid; t < 16 * 18 * 5; t += 256) {
      int c   = t / 90;
      int rem = t - c * 90;
      int r   = rem / 5;
      int q   = rem - r * 5;
      const float4 v = *reinterpret_cast<const float4*>(
          inN + (size_t)(cb + c) * PL2 + (ybase + r) * 52 + xbase + 4 * q);
      float* dst = &s_in[c * PLS + r * RS + 4 * q];
      dst[0] = v.x; dst[1] = v.y; dst[2] = v.z; dst[3] = v.w;
    }
    for (int t = tid; t < 16 * 4 * 32; t += 256) {
      int co  = t & 31;
      int tap = (t >> 5) & 3;
      int lci = t >> 7;
      int s  = tap >> 1, tt = tap & 1;
      s_w[t] = w5[(((size_t)(cb + lci) * 32 + co) * 4 + (3 - (a + 2 * s))) * 4 +
                  (3 - (b + 2 * tt))];
    }
    __syncthreads();

#pragma unroll 4
    for (int ci = 0; ci < 16; ci++) {
      float i00 = s_in[ci * PLS + (ly + a + 0) * RS + lx + b + 0];
      float i01 = s_in[ci * PLS + (ly + a + 0) * RS + lx + b + 1];
      float i10 = s_in[ci * PLS + (ly + a + 1) * RS + lx + b + 0];
      float i11 = s_in[ci * PLS + (ly + a + 1) * RS + lx + b + 1];
      const float4* wp = reinterpret_cast<const float4*>(s_w + ci * 128);
#pragma unroll
      for (int cq = 0; cq < 8; cq++) {
        float4 w0 = wp[cq];
        float4 w1 = wp[8 + cq];
        float4 w2 = wp[16 + cq];
        float4 w3 = wp[24 + cq];
        acc[4 * cq + 0] += w0.x * i00 + w1.x * i01 + w2.x * i10 + w3.x * i11;
        acc[4 * cq + 1] += w0.y * i00 + w1.y * i01 + w2.y * i10 + w3.y * i11;
        acc[4 * cq + 2] += w0.z * i00 + w1.z * i01 + w2.z * i10 + w3.z * i11;
        acc[4 * cq + 3] += w0.w * i00 + w1.w * i01 + w2.w * i10 + w3.w * i11;
      }
    }
  }

  const int oy = 2 * (ybase + ly) + a + 1;
  const int ox = 2 * (xbase + lx) + b + 1;
  float* outN = out + (size_t)n * 32 * PL1;
#pragma unroll
  for (int co = 0; co < 32; co++)
    outN[(size_t)co * PL1 + oy * 100 + ox] = acc[co];
}

// ---------------------------------------------------------------------------
// final conv (R3 form)
// ---------------------------------------------------------------------------
__global__ void __launch_bounds__(256)
conv_final_k(const float* __restrict__ in, const float* __restrict__ w6,
             const float* __restrict__ b6, float* __restrict__ out) {
  constexpr int RS = 37, PLS = 10 * RS;
  __shared__ float s_in[8 * PLS];
  __shared__ float sw[288];
  __shared__ float sb;

  const int tid = threadIdx.x;
  const int tx = blockIdx.x % 3;
  const int ty = blockIdx.x / 3;
  const int n  = blockIdx.y;
  const int y0 = ty * 8, x0 = tx * 32;
  const int px = tid & 31, py = tid >> 5;

  for (int t = tid; t < 288; t += 256) sw[t] = w6[t];
  if (tid == 0) sb = b6[0];

  const float* inN = in + (size_t)n * 32 * PL1;
  float acc = 0.f;

  for (int cb = 0; cb < 32; cb += 8) {
    __syncthreads();
#pragma unroll
    for (int t = tid; t < 8 * 10 * 9; t += 256) {
      int c   = t / 90;
      int rem = t - c * 90;
      int r   = rem / 9;
      int q   = rem - r * 9;
      const float4 v = *reinterpret_cast<const float4*>(
          inN + (size_t)(cb + c) * PL1 + (y0 + r) * 100 + x0 + 4 * q);
      float* dst = &s_in[c * PLS + r * RS + 4 * q];
      dst[0] = v.x; dst[1] = v.y; dst[2] = v.z; dst[3] = v.w;
    }
    __syncthreads();
#pragma unroll
    for (int c = 0; c < 8; c++)
#pragma unroll
      for (int ky = 0; ky < 3; ky++)
#pragma unroll
        for (int kx = 0; kx < 3; kx++)
          acc += sw[(cb + c) * 9 + ky * 3 + kx] *
                 s_in[c * PLS + (py + ky) * RS + px + kx];
  }

  out[(size_t)n * 6144 + (y0 + py) * 96 + x0 + px] = acc + sb;
}

// ---------------------------------------------------------------------------
// Launch
// ---------------------------------------------------------------------------
extern "C" void kernel_launch(void* const* d_in, const int* in_sizes, int n_in,
                              void* d_out, int out_size) {
  const float* f1 = (const float*)d_in[0];
  const float* f2 = (const float*)d_in[1];
  const float* w1 = (const float*)d_in[2];
  const float* w2 = (const float*)d_in[3];
  const float* w3 = (const float*)d_in[4];
  const float* w4 = (const float*)d_in[5];
  const float* w5 = (const float*)d_in[6];
  const float* w6 = (const float*)d_in[7];
  const float* b6 = (const float*)d_in[8];
  float* out = (float*)d_out;

  float *x1, *x2, *x3, *x4, *x5, *f1p, *f2c, *U, *V, *w1a, *w1b, *x3cl;
  cudaGetSymbolAddress((void**)&x1, g_x1);
  cudaGetSymbolAddress((void**)&x2, g_x2);
  cudaGetSymbolAddress((void**)&x3, g_x3);
  cudaGetSymbolAddress((void**)&x4, g_x4);
  cudaGetSymbolAddress((void**)&x5, g_x5);
  cudaGetSymbolAddress((void**)&f1p, g_f1p);
  cudaGetSymbolAddress((void**)&f2c, g_f2c);
  cudaGetSymbolAddress((void**)&U, g_U);
  cudaGetSymbolAddress((void**)&V, g_V);
  cudaGetSymbolAddress((void**)&w1a, g_w1a);
  cudaGetSymbolAddress((void**)&w1b, g_w1b);
  cudaGetSymbolAddress((void**)&x3cl, g_x3cl);

  // conv1 via factorization
  prep_k<<<(2 * 32 * 6144 + 255) / 256, 256>>>(f1, f2, w1);
  wprep3_k<<<(9 * 128 * 128 + 255) / 256, 256>>>(w3);
  conv3x3_s1_k<32, 64, 96, 100><<<dim3(24, 6, 2), 256>>>(f1p, w1a, U, 32, 96);
  conv_v_k<<<dim3(63, 6, 2), 128>>>(f2c, w1b, V);
  combine_k<<<NIMG * 96, 256>>>();
  stripfix_k<<<dim3(20, NIMG), 128>>>(f1, f2, w1);
  inorm_leaky_k<64, 96, 100><<<NIMG * 96, 256>>>(x1);

  // conv2 s2 96->128 (scalar)
  conv3x3_s2_k<<<dim3(12, 8, NIMG), 128>>>(x1, w2, x2, 96, 128);
  inorm_leaky_k<32, 48, 52><<<NIMG * 128, 256>>>(x2);

  // conv3 via mma.sync bf16-split GEMM (implicit im2col)
  x2cl_k<<<dim3(32, NIMG), 256>>>(x2);
  gemm3_k<<<dim3(16, NIMG), 256>>>(x3cl);
  cl2planar_k<<<dim3(32, NIMG), 256>>>(x3cl);
  inorm_leaky_k<32, 48, 52><<<NIMG * 128, 256>>>(x3);

  // conv4 128->64 (scalar)
  conv3x3_s1_k<16, 32, 48, 52><<<dim3(12, 4, NIMG), 128>>>(x3, w4, x4, 128, 64);
  inorm_leaky_k<32, 48, 52><<<NIMG * 64, 256>>>(x4);

  // deconv + final
  deconv4x4_k<<<dim3(6, 4, NIMG), 256>>>(x4, w5, x5);
  inorm_leaky_k<64, 96, 100><<<NIMG * 32, 256>>>(x5);
  conv_final_k<<<dim3(24, NIMG), 256>>>(x5, w6, b6, out);
}

// round 10
// speedup vs baseline: 2.0327x; 1.3283x over previous
#include <cuda_runtime.h>
#include <cuda_bf16.h>
#include <cstdint>

// ---------------------------------------------------------------------------
// Padded planar layouts [C][H+2][WP], 1-px zero halo (globals zero-init).
// ---------------------------------------------------------------------------
#define NIMG 98
#define PL1 (66 * 100)
#define PL2 (34 * 52)
#define PLV (72 * 112)
#define PLC (80 * 120)

__device__ float g_x1 [NIMG * 96 * PL1];
__device__ float g_x4 [NIMG * 64 * PL2];
__device__ float g_x5 [NIMG * 32 * PL1];

// conv1 factorization scratch
__device__ float g_f1p[2 * 32 * PL1];
__device__ float g_f2c[2 * 32 * PLC];
__device__ float g_U  [2 * 96 * PL1];
__device__ float g_V  [2 * 96 * PLV];
__device__ float g_w1a[96 * 32 * 9];
__device__ float g_w1b[96 * 32 * 9];

// tensor-core path scratch (mma.sync)
__device__ unsigned short g_X1h[(size_t)NIMG * 6600 * 96];  // x1 ch-last bf16 hi (padded 66x100)
__device__ unsigned short g_X1l[(size_t)NIMG * 6600 * 96];
__device__ unsigned short g_Xh[(size_t)NIMG * 1768 * 128];  // x2 then x3, ch-last padded 34x52
__device__ unsigned short g_Xl[(size_t)NIMG * 1768 * 128];
__device__ unsigned short g_B2h[9 * 128 * 96];              // w2 [tap][co][ci]
__device__ unsigned short g_B2l[9 * 128 * 96];
__device__ unsigned short g_B3h[9 * 128 * 128];             // w3 [tap][co][ci]
__device__ unsigned short g_B3l[9 * 128 * 128];
__device__ unsigned short g_B4h[9 * 64 * 128];              // w4 [tap][co][ci]
__device__ unsigned short g_B4l[9 * 64 * 128];
__device__ float g_x2cl[(size_t)NIMG * 1536 * 128];
__device__ float g_x3cl[(size_t)NIMG * 1536 * 128];
__device__ float g_x4cl[(size_t)NIMG * 1536 * 64];
__device__ float g_stm[NIMG * 128];                          // per-(n,c) mean
__device__ float g_sti[NIMG * 128];                          // per-(n,c) rsqrt(var+eps)

// strip-fix segment table
__device__ const int c_segy[20] = {0,0,0, 60,60,60, 4,12,20,28,36,44,52, 4,12,20,28,36,44,52};
__device__ const int c_segx[20] = {0,32,64, 0,32,64, 0,0,0,0,0,0,0, 92,92,92,92,92,92,92};
__device__ const int c_segh[20] = {4,4,4, 4,4,4, 8,8,8,8,8,8,8, 8,8,8,8,8,8,8};
__device__ const int c_segw[20] = {32,32,32, 32,32,32, 4,4,4,4,4,4,4, 4,4,4,4,4,4,4};

// ---------------------------------------------------------------------------
// mma.sync helpers
// ---------------------------------------------------------------------------
__device__ __forceinline__ uint32_t smem_u32(const void* p) {
  uint32_t a;
  asm("{ .reg .u64 t; cvta.to.shared.u64 t, %1; cvt.u32.u64 %0, t; }"
      : "=r"(a) : "l"(p));
  return a;
}
__device__ __forceinline__ void ldsm_x4(unsigned r[4], uint32_t addr) {
  asm volatile("ldmatrix.sync.aligned.m8n8.x4.shared.b16 {%0,%1,%2,%3}, [%4];"
               : "=r"(r[0]), "=r"(r[1]), "=r"(r[2]), "=r"(r[3]) : "r"(addr));
}
__device__ __forceinline__ void ldsm_x2(unsigned r[2], uint32_t addr) {
  asm volatile("ldmatrix.sync.aligned.m8n8.x2.shared.b16 {%0,%1}, [%2];"
               : "=r"(r[0]), "=r"(r[1]) : "r"(addr));
}
__device__ __forceinline__ void mma_bf16(float d[4], const unsigned a[4],
                                         const unsigned b[2]) {
  asm volatile(
      "mma.sync.aligned.m16n8k16.row.col.f32.bf16.bf16.f32 "
      "{%0,%1,%2,%3}, {%4,%5,%6,%7}, {%8,%9}, {%0,%1,%2,%3};"
      : "+f"(d[0]), "+f"(d[1]), "+f"(d[2]), "+f"(d[3])
      : "r"(a[0]), "r"(a[1]), "r"(a[2]), "r"(a[3]), "r"(b[0]), "r"(b[1]));
}
__device__ __forceinline__ void bf16_split(float v, unsigned short& h,
                                           unsigned short& l) {
  __nv_bfloat16 hb = __float2bfloat16(v);
  __nv_bfloat16 lb = __float2bfloat16(v - __bfloat162float(hb));
  h = __bfloat16_as_ushort(hb);
  l = __bfloat16_as_ushort(lb);
}

// ---------------------------------------------------------------------------
// prep: pad f1, embed f2, split w1; weight splits for w2/w3/w4
// ---------------------------------------------------------------------------
__global__ void prep_k(const float* __restrict__ f1, const float* __restrict__ f2,
                       const float* __restrict__ w1) {
  int idx = blockIdx.x * blockDim.x + threadIdx.x;
  if (idx < 2 * 32 * 6144) {
    int x = idx % 96, y = (idx / 96) % 64, c = idx / 6144;
    g_f1p[(size_t)c * PL1 + (y + 1) * 100 + x + 1] = f1[idx];
    g_f2c[(size_t)c * PLC + (y + 8) * 120 + x + 8] = f2[idx];
  }
  if (idx < 96 * 64 * 9) {
    int co = idx / 576, rem = idx % 576, ci = rem / 9, k = rem % 9;
    if (ci < 32) g_w1a[(co * 32 + ci) * 9 + k] = w1[idx];
    else         g_w1b[(co * 32 + (ci - 32)) * 9 + k] = w1[idx];
  }
}
__global__ void wprep2_k(const float* __restrict__ w2) {
  int idx = blockIdx.x * blockDim.x + threadIdx.x;
  if (idx >= 9 * 128 * 96) return;
  int ci = idx % 96, co = (idx / 96) % 128, tap = idx / 12288;
  bf16_split(w2[(co * 96 + ci) * 9 + tap], g_B2h[idx], g_B2l[idx]);
}
__global__ void wprep3_k(const float* __restrict__ w3) {
  int idx = blockIdx.x * blockDim.x + threadIdx.x;
  if (idx >= 9 * 128 * 128) return;
  int ci = idx & 127, co = (idx >> 7) & 127, tap = idx >> 14;
  bf16_split(w3[(co * 128 + ci) * 9 + tap], g_B3h[idx], g_B3l[idx]);
}
__global__ void wprep4_k(const float* __restrict__ w4) {
  int idx = blockIdx.x * blockDim.x + threadIdx.x;
  if (idx >= 9 * 64 * 128) return;
  int ci = idx & 127, co = (idx >> 7) & 63, tap = idx >> 13;
  bf16_split(w4[(co * 128 + ci) * 9 + tap], g_B4h[idx], g_B4l[idx]);
}

// ---------------------------------------------------------------------------
// 3x3 s1 conv (scalar, for conv1 factorization pieces)
// ---------------------------------------------------------------------------
template <int TW, int H, int W, int WP>
__global__ void __launch_bounds__(8 * TW)
conv3x3_s1_k(const float* __restrict__ in, const float* __restrict__ w,
             float* __restrict__ out, int Cin, int Cout) {
  constexpr int PXG = TW / 4;
  constexpr int NT  = 8 * TW;
  constexpr int RS  = 37;
  constexpr int PLS = 10 * RS;
  constexpr int F4  = (TW + 4) / 4;
  constexpr int PLANE = (H + 2) * WP;

  __shared__ float s_in[8 * PLS];
  __shared__ __align__(16) float s_w[8 * 9 * 16];

  const int tid = threadIdx.x;
  const int cg  = tid / (8 * PXG);
  const int pid = tid % (8 * PXG);
  const int py  = pid / PXG;
  const int pxg = pid % PXG;

  const int tilesX = W / TW;
  const int tx = blockIdx.x % tilesX;
  const int ty = blockIdx.x / tilesX;
  const int n  = blockIdx.z;
  const int coB = blockIdx.y * 16;
  const int y0 = ty * 8, x0 = tx * TW;

  const float* inN = in + (size_t)n * Cin * PLANE;

  float acc[4][4];
#pragma unroll
  for (int q = 0; q < 4; q++)
#pragma unroll
    for (int p = 0; p < 4; p++) acc[q][p] = 0.f;

  for (int cb = 0; cb < Cin; cb += 8) {
    __syncthreads();
#pragma unroll
    for (int t = tid; t < 8 * 10 * F4; t += NT) {
      int c   = t / (10 * F4);
      int rem = t - c * (10 * F4);
      int r   = rem / F4;
      int q   = rem - r * F4;
      const float4 v = *reinterpret_cast<const float4*>(
          inN + (size_t)(cb + c) * PLANE + (y0 + r) * WP + x0 + 4 * q);
      float* dst = &s_in[c * PLS + r * RS + 4 * q];
      dst[0] = v.x; dst[1] = v.y; dst[2] = v.z; dst[3] = v.w;
    }
    for (int t = tid; t < 16 * 8 * 9; t += NT) {
      int lco = t & 15;
      int rem = t >> 4;
      int k   = rem % 9;
      int lci = rem / 9;
      s_w[(lci * 9 + k) * 16 + lco] =
          w[((size_t)(coB + lco) * Cin + (cb + lci)) * 9 + k];
    }
    __syncthreads();

#pragma unroll
    for (int ci = 0; ci < 8; ci++) {
#pragma unroll
      for (int ky = 0; ky < 3; ky++) {
        float r[6];
#pragma unroll
        for (int j = 0; j < 6; j++)
          r[j] = s_in[ci * PLS + (py + ky) * RS + pxg * 4 + j];
#pragma unroll
        for (int kx = 0; kx < 3; kx++) {
          float4 wv =
              reinterpret_cast<const float4*>(s_w)[(ci * 9 + ky * 3 + kx) * 4 + cg];
#pragma unroll
          for (int p = 0; p < 4; p++) {
            float iv = r[p + kx];
            acc[0][p] += wv.x * iv;
            acc[1][p] += wv.y * iv;
            acc[2][p] += wv.z * iv;
            acc[3][p] += wv.w * iv;
          }
        }
      }
    }
  }

  float* outN = out + (size_t)n * Cout * PLANE;
  const int gy = y0 + py + 1;
#pragma unroll
  for (int q = 0; q < 4; q++) {
    int co = coB + cg * 4 + q;
#pragma unroll
    for (int p = 0; p < 4; p++)
      outN[(size_t)co * PLANE + gy * WP + x0 + pxg * 4 + p + 1] = acc[q][p];
  }
}

// ---------------------------------------------------------------------------
// V = conv3x3(zero-padded f2) on extended 72x112 grid
// ---------------------------------------------------------------------------
__global__ void __launch_bounds__(128)
conv_v_k(const float* __restrict__ in, const float* __restrict__ w,
         float* __restrict__ out) {
  constexpr int RS = 37, PLS = 10 * RS;
  __shared__ float s_in[8 * PLS];
  __shared__ __align__(16) float s_w[8 * 9 * 16];

  const int tid = threadIdx.x;
  const int cg  = tid >> 5;
  const int pid = tid & 31;
  const int py  = pid >> 2;
  const int pxg = pid & 3;

  const int tx = blockIdx.x % 7;
  const int ty = blockIdx.x / 7;
  const int n  = blockIdx.z;
  const int coB = blockIdx.y * 16;
  const int y0 = ty * 8, x0 = tx * 16;

  const float* inN = in + (size_t)n * 32 * PLC;

  float acc[4][4];
#pragma unroll
  for (int q = 0; q < 4; q++)
#pragma unroll
    for (int p = 0; p < 4; p++) acc[q][p] = 0.f;

  for (int cb = 0; cb < 32; cb += 8) {
    __syncthreads();
#pragma unroll
    for (int t = tid; t < 8 * 10 * 5; t += 128) {
      int c   = t / 50;
      int rem = t - c * 50;
      int r   = rem / 5;
      int q   = rem - r * 5;
      const float4 v = *reinterpret_cast<const float4*>(
          inN + (size_t)(cb + c) * PLC + (y0 + r + 4) * 120 + x0 + 4 * q + 4);
      float* dst = &s_in[c * PLS + r * RS + 4 * q];
      dst[0] = v.x; dst[1] = v.y; dst[2] = v.z; dst[3] = v.w;
    }
    for (int t = tid; t < 16 * 8 * 9; t += 128) {
      int lco = t & 15;
      int rem = t >> 4;
      int k   = rem % 9;
      int lci = rem / 9;
      s_w[(lci * 9 + k) * 16 + lco] =
          w[((coB + lco) * 32 + cb + lci) * 9 + k];
    }
    __syncthreads();

#pragma unroll
    for (int ci = 0; ci < 8; ci++) {
#pragma unroll
      for (int ky = 0; ky < 3; ky++) {
        float r[6];
#pragma unroll
        for (int j = 0; j < 6; j++)
          r[j] = s_in[ci * PLS + (py + ky) * RS + pxg * 4 + j];
#pragma unroll
        for (int kx = 0; kx < 3; kx++) {
          float4 wv =
              reinterpret_cast<const float4*>(s_w)[(ci * 9 + ky * 3 + kx) * 4 + cg];
#pragma unroll
          for (int p = 0; p < 4; p++) {
            float iv = r[p + kx];
            acc[0][p] += wv.x * iv;
            acc[1][p] += wv.y * iv;
            acc[2][p] += wv.z * iv;
            acc[3][p] += wv.w * iv;
          }
        }
      }
    }
  }

  float* outN = out + (size_t)n * 96 * PLV;
  const int gy = y0 + py;
#pragma unroll
  for (int q = 0; q < 4; q++) {
    int co = coB + cg * 4 + q;
#pragma unroll
    for (int p = 0; p < 4; p++)
      outN[(size_t)co * PLV + gy * 112 + x0 + pxg * 4 + p] = acc[q][p];
  }
}

// ---------------------------------------------------------------------------
// combine: x1 = U + shift(V)
// ---------------------------------------------------------------------------
__global__ void __launch_bounds__(256) combine_k() {
  const int bid = blockIdx.x;
  const int co = bid % 96, n = bid / 96;
  const int b = n / 49, d = n % 49;
  const int di = d / 7 - 3, dj = d % 7 - 3;

  const float* U = g_U + ((size_t)(b * 96 + co)) * PL1;
  const float* V = g_V + ((size_t)(b * 96 + co)) * PLV + (dj + 3) * 112 + (di + 3);
  float* X = g_x1 + ((size_t)(n * 96 + co)) * PL1;

  const int y0 = threadIdx.x >> 5, xl = threadIdx.x & 31;
  for (int y = y0; y < 64; y += 8) {
    const int ro = (y + 1) * 100 + 1;
    const int rv = y * 112;
#pragma unroll
    for (int x = xl; x < 96; x += 32)
      X[ro + x] = U[ro + x] + V[rv + x];
  }
}

// ---------------------------------------------------------------------------
// strip fix (exact conv1 on 1216 border px)
// ---------------------------------------------------------------------------
__global__ void __launch_bounds__(128)
stripfix_k(const float* __restrict__ f1, const float* __restrict__ f2,
           const float* __restrict__ w1) {
  const int sid = blockIdx.x;
  const int n   = blockIdx.y;
  const int y0 = c_segy[sid], x0 = c_segx[sid];
  const int h  = c_segh[sid], w = c_segw[sid];
  const int b = n / 49, d = n % 49;
  const int di = d / 7 - 3;
  const int dj = d % 7 - 3;
  const int H2 = h + 2, W2 = w + 2;

  __shared__ float s_in[8 * 10 * 34];
  __shared__ __align__(16) float s_w[8 * 9 * 32];

  const int tid = threadIdx.x;
  const bool act = tid < h * w;
  const int py = act ? tid / w : 0;
  const int px = act ? tid % w : 0;

  const float* f1b = f1 + (size_t)b * 32 * 6144;
  const float* f2b = f2 + (size_t)b * 32 * 6144;

  for (int coc = 0; coc < 3; coc++) {
    float acc[32];
#pragma unroll
    for (int c = 0; c < 32; c++) acc[c] = 0.f;

    for (int cb = 0; cb < 64; cb += 8) {
      __syncthreads();
      for (int t = tid; t < 8 * H2 * W2; t += 128) {
        int ci  = t / (H2 * W2);
        int rem = t - ci * (H2 * W2);
        int r   = rem / W2;
        int c   = rem - r * W2;
        int yy = y0 - 1 + r, xx = x0 - 1 + c;
        int cic = cb + ci;
        float v = 0.f;
        bool ok = (unsigned)yy < 64u && (unsigned)xx < 96u &&
                  (unsigned)(yy + dj) < 64u && (unsigned)(xx + di) < 96u;
        if (ok)
          v = (cic < 32) ? f1b[cic * 6144 + yy * 96 + xx]
                         : f2b[(cic - 32) * 6144 + (yy + dj) * 96 + (xx + di)];
        s_in[ci * 340 + r * 34 + c] = v;
      }
      for (int t = tid; t < 32 * 8 * 9; t += 128) {
        int co  = t & 31;
        int rem = t >> 5;
        int k   = rem % 9;
        int ci  = rem / 9;
        s_w[(ci * 9 + k) * 32 + co] =
            w1[((coc * 32 + co) * 64 + cb + ci) * 9 + k];
      }
      __syncthreads();

      if (act) {
#pragma unroll
        for (int ci = 0; ci < 8; ci++)
#pragma unroll
          for (int ky = 0; ky < 3; ky++)
#pragma unroll
            for (int kx = 0; kx < 3; kx++) {
              float v = s_in[ci * 340 + (py + ky) * 34 + (px + kx)];
              const float4* wv = reinterpret_cast<const float4*>(
                  &s_w[(ci * 9 + ky * 3 + kx) * 32]);
#pragma unroll
              for (int q = 0; q < 8; q++) {
                float4 ww = wv[q];
                acc[4 * q + 0] += ww.x * v;
                acc[4 * q + 1] += ww.y * v;
                acc[4 * q + 2] += ww.z * v;
                acc[4 * q + 3] += ww.w * v;
              }
            }
      }
    }
    if (act) {
#pragma unroll
      for (int c = 0; c < 32; c++)
        g_x1[((size_t)n * 96 + coc * 32 + c) * PL1 +
             (y0 + py + 1) * 100 + (x0 + px + 1)] = acc[c];
    }
    __syncthreads();
  }
}

// ---------------------------------------------------------------------------
// Instance norm + leaky (planar padded) — for x1 and x5
// ---------------------------------------------------------------------------
template <int H, int W, int WP>
__global__ void __launch_bounds__(256)
inorm_leaky_k(float* __restrict__ x) {
  constexpr int PLANE = (H + 2) * WP;
  float* p = x + (size_t)blockIdx.x * PLANE;
  const int wid = threadIdx.x >> 5, ln = threadIdx.x & 31;

  float s = 0.f, q = 0.f;
  for (int y = wid; y < H; y += 8)
    for (int xx = ln; xx < W; xx += 32) {
      float v = p[(y + 1) * WP + xx + 1];
      s += v; q += v * v;
    }
#pragma unroll
  for (int o = 16; o > 0; o >>= 1) {
    s += __shfl_xor_sync(0xffffffffu, s, o);
    q += __shfl_xor_sync(0xffffffffu, q, o);
  }
  __shared__ float ss[8], sq[8];
  if (ln == 0) { ss[wid] = s; sq[wid] = q; }
  __syncthreads();
  if (threadIdx.x == 0) {
    float S = 0.f, Q = 0.f;
#pragma unroll
    for (int i = 0; i < 8; i++) { S += ss[i]; Q += sq[i]; }
    float m = S / (float)(H * W);
    float var = Q / (float)(H * W) - m * m;
    ss[0] = m;
    sq[0] = rsqrtf(var + 1e-5f);
  }
  __syncthreads();
  const float m = ss[0], inv = sq[0];
  for (int y = wid; y < H; y += 8)
    for (int xx = ln; xx < W; xx += 32) {
      float v = (p[(y + 1) * WP + xx + 1] - m) * inv;
      p[(y + 1) * WP + xx + 1] = v >= 0.f ? v : 0.01f * v;
    }
}

// ---------------------------------------------------------------------------
// x1 planar -> channel-last padded bf16 hi/lo [n][66*100][96]
// ---------------------------------------------------------------------------
__global__ void __launch_bounds__(256)
x1cl_k() {
  __shared__ float s[96 * 97];
  const int y = blockIdx.x;   // 0..63
  const int n = blockIdx.y;
  const int tid = threadIdx.x;
  const int wid = tid >> 5, ln = tid & 31;

  for (int ci = wid; ci < 96; ci += 8) {
    const float* src = g_x1 + ((size_t)(n * 96 + ci)) * PL1 + (y + 1) * 100 + 1;
    for (int x = ln; x < 96; x += 32) s[x * 97 + ci] = src[x];
  }
  __syncthreads();
  for (int idx = tid; idx < 96 * 96; idx += 256) {
    int x = idx / 96, ci = idx % 96;
    size_t o = ((size_t)(n * 6600 + (y + 1) * 100 + (x + 1))) * 96 + ci;
    bf16_split(s[x * 97 + ci], g_X1h[o], g_X1l[o]);
  }
}

// ---------------------------------------------------------------------------
// stats over channel-last fp32 [n][1536][C]: per-(n,c) mean + rsqrt(var+eps)
// ---------------------------------------------------------------------------
template <int C>
__global__ void __launch_bounds__(512)
stats_cl_k(const float* __restrict__ xcl) {
  constexpr int SL = 512 / C;          // slices
  constexpr int PXS = 1536 / SL;       // px per slice
  __shared__ float sm[512], sq[512];
  const int n = blockIdx.x;
  const int tid = threadIdx.x;
  const int ci = tid % C, sl = tid / C;

  const float* base = xcl + (size_t)n * 1536 * C + ci;
  float s = 0.f, q = 0.f;
  for (int i = 0; i < PXS; i++) {
    float v = base[(size_t)(sl * PXS + i) * C];
    s += v; q += v * v;
  }
  sm[tid] = s; sq[tid] = q;
  __syncthreads();
  if (tid < C) {
    float S = 0.f, Q = 0.f;
#pragma unroll
    for (int j = 0; j < SL; j++) { S += sm[ci + j * C]; Q += sq[ci + j * C]; }
    float m = S / 1536.f;
    float var = Q / 1536.f - m * m;
    g_stm[n * 128 + ci] = m;
    g_sti[n * 128 + ci] = rsqrtf(var + 1e-5f);
  }
}

// ---------------------------------------------------------------------------
// apply norm+leaky to channel-last x (C=128) and split to bf16 hi/lo padded
// ---------------------------------------------------------------------------
__global__ void __launch_bounds__(256)
apply_cl128_k(const float* __restrict__ xcl) {
  const int y = blockIdx.x;   // 0..31
  const int n = blockIdx.y;
  const int tid = threadIdx.x;
  for (int idx = tid; idx < 48 * 128; idx += 256) {
    int x = idx >> 7, ci = idx & 127;
    float m = g_stm[n * 128 + ci], iv = g_sti[n * 128 + ci];
    float v = (xcl[((size_t)(n * 1536 + y * 48 + x)) * 128 + ci] - m) * iv;
    v = v >= 0.f ? v : 0.01f * v;
    size_t o = ((size_t)(n * 1768 + (y + 1) * 52 + (x + 1))) * 128 + ci;
    bf16_split(v, g_Xh[o], g_Xl[o]);
  }
}

// ---------------------------------------------------------------------------
// apply norm+leaky to x4cl (C=64) and transpose to planar padded g_x4
// ---------------------------------------------------------------------------
__global__ void __launch_bounds__(256)
apply_cl64_planar_k(const float* __restrict__ xcl) {
  __shared__ float s[48 * 65];
  const int y = blockIdx.x;
  const int n = blockIdx.y;
  const int tid = threadIdx.x;

  for (int idx = tid; idx < 48 * 64; idx += 256) {
    int x = idx >> 6, ci = idx & 63;
    float m = g_stm[n * 128 + ci], iv = g_sti[n * 128 + ci];
    float v = (xcl[((size_t)(n * 1536 + y * 48 + x)) * 64 + ci] - m) * iv;
    s[x * 65 + ci] = v >= 0.f ? v : 0.01f * v;
  }
  __syncthreads();
  const int co = tid >> 2, seg = tid & 3;
  float* dst = g_x4 + ((size_t)(n * 64 + co)) * PL2 + (y + 1) * 52 + 1 + seg * 12;
#pragma unroll
  for (int j = 0; j < 12; j++) dst[j] = s[(seg * 12 + j) * 65 + co];
}

// ---------------------------------------------------------------------------
// gemm2: conv2 (stride 2) as implicit-im2col GEMM. M=96-tile, N=128, Cin=96.
// A from x1 channel-last: output (y,x) reads pos (2y+ky)*100 + (2x+kx).
// ---------------------------------------------------------------------------
__global__ void __launch_bounds__(256)
gemm2_k(float* __restrict__ xcl) {
  __shared__ unsigned short sA[2][96 * 40];
  __shared__ unsigned short sB[2][128 * 40];

  const int tid  = threadIdx.x;
  const int wid  = tid >> 5, lane = tid & 31;
  const int warp_m = wid & 1;
  const int warp_n = wid >> 1;
  const int tile = blockIdx.x;
  const int n    = blockIdx.y;
  const int px0  = tile * 96;

  const uint32_t aB = smem_u32(sA);
  const uint32_t bB = smem_u32(sB);

  float acc[3][4][4];
#pragma unroll
  for (int mi = 0; mi < 3; mi++)
#pragma unroll
    for (int ni = 0; ni < 4; ni++)
#pragma unroll
      for (int j = 0; j < 4; j++) acc[mi][ni][j] = 0.f;

  for (int tap = 0; tap < 9; tap++) {
    const int dy = tap / 3, dx = tap % 3;
    for (int cc = 0; cc < 3; cc++) {
      const int ci0 = cc * 32;
      __syncthreads();
#pragma unroll
      for (int i = 0; i < 3; i++) {
        int id  = tid + i * 256;
        int buf = id / 384;
        int rem = id - buf * 384;
        int r   = rem >> 2, q = rem & 3;
        int px = px0 + r;
        int y = px / 48, x = px - y * 48;
        int pos = (2 * y + dy) * 100 + (2 * x + dx);
        const uint4* src = reinterpret_cast<const uint4*>(
            (buf ? g_X1l : g_X1h) + ((size_t)(n * 6600 + pos)) * 96 + ci0);
        *reinterpret_cast<uint4*>(&sA[buf][r * 40 + q * 8]) = src[q];
      }
#pragma unroll
      for (int i = 0; i < 4; i++) {
        int id  = tid + i * 256;
        int buf = id >> 9;
        int rem = id & 511;
        int r   = rem >> 2, q = rem & 3;
        const uint4* src = reinterpret_cast<const uint4*>(
            (buf ? g_B2l : g_B2h) + ((size_t)(tap * 128 + r)) * 96 + ci0);
        *reinterpret_cast<uint4*>(&sB[buf][r * 40 + q * 8]) = src[q];
      }
      __syncthreads();

#pragma unroll
      for (int ks = 0; ks < 2; ks++) {
        unsigned ah[3][4], al[3][4], bh[4][2], bl[4][2];
        const int arow = warp_m * 48 + (lane & 7) + ((lane >> 3) & 1) * 8;
        const int acol = ks * 16 + ((lane >> 4) & 1) * 8;
#pragma unroll
        for (int mi = 0; mi < 3; mi++) {
          uint32_t off = (uint32_t)(((arow + mi * 16) * 40 + acol) * 2);
          ldsm_x4(ah[mi], aB + off);
          ldsm_x4(al[mi], aB + 96 * 40 * 2 + off);
        }
        const int brow = warp_n * 32 + (lane & 7);
        const int bcol = ks * 16 + ((lane >> 3) & 1) * 8;
#pragma unroll
        for (int ni = 0; ni < 4; ni++) {
          uint32_t off = (uint32_t)(((brow + ni * 8) * 40 + bcol) * 2);
          ldsm_x2(bh[ni], bB + off);
          ldsm_x2(bl[ni], bB + 128 * 40 * 2 + off);
        }
#pragma unroll
        for (int mi = 0; mi < 3; mi++)
#pragma unroll
          for (int ni = 0; ni < 4; ni++) {
            mma_bf16(acc[mi][ni], ah[mi], bh[ni]);
            mma_bf16(acc[mi][ni], ah[mi], bl[ni]);
            mma_bf16(acc[mi][ni], al[mi], bh[ni]);
          }
      }
    }
  }

  const int g = lane >> 2, tg = lane & 3;
#pragma unroll
  for (int mi = 0; mi < 3; mi++)
#pragma unroll
    for (int ni = 0; ni < 4; ni++) {
      int row = px0 + warp_m * 48 + mi * 16 + g;
      int co  = warp_n * 32 + ni * 8 + tg * 2;
      float* d0 = xcl + ((size_t)(n * 1536 + row)) * 128 + co;
      float* d1 = xcl + ((size_t)(n * 1536 + row + 8)) * 128 + co;
      *reinterpret_cast<float2*>(d0) = make_float2(acc[mi][ni][0], acc[mi][ni][1]);
      *reinterpret_cast<float2*>(d1) = make_float2(acc[mi][ni][2], acc[mi][ni][3]);
    }
}

// ---------------------------------------------------------------------------
// gemm3: conv3 as GEMM. A from g_Xh/g_Xl (x2), N=128, Cin=128.
// ---------------------------------------------------------------------------
__global__ void __launch_bounds__(256)
gemm3_k(float* __restrict__ xcl) {
  __shared__ unsigned short sA[2][96 * 40];
  __shared__ unsigned short sB[2][128 * 40];

  const int tid  = threadIdx.x;
  const int wid  = tid >> 5, lane = tid & 31;
  const int warp_m = wid & 1;
  const int warp_n = wid >> 1;
  const int tile = blockIdx.x;
  const int n    = blockIdx.y;
  const int px0  = tile * 96;

  const uint32_t aB = smem_u32(sA);
  const uint32_t bB = smem_u32(sB);

  float acc[3][4][4];
#pragma unroll
  for (int mi = 0; mi < 3; mi++)
#pragma unroll
    for (int ni = 0; ni < 4; ni++)
#pragma unroll
      for (int j = 0; j < 4; j++) acc[mi][ni][j] = 0.f;

  for (int tap = 0; tap < 9; tap++) {
    const int dy = tap / 3, dx = tap % 3;
    for (int cc = 0; cc < 4; cc++) {
      const int ci0 = cc * 32;
      __syncthreads();
#pragma unroll
      for (int i = 0; i < 3; i++) {
        int id  = tid + i * 256;
        int buf = id / 384;
        int rem = id - buf * 384;
        int r   = rem >> 2, q = rem & 3;
        int px = px0 + r;
        int y = px / 48, x = px - y * 48;
        int pos = (y + dy) * 52 + (x + dx);
        const uint4* src = reinterpret_cast<const uint4*>(
            (buf ? g_Xl : g_Xh) + ((size_t)(n * 1768 + pos)) * 128 + ci0);
        *reinterpret_cast<uint4*>(&sA[buf][r * 40 + q * 8]) = src[q];
      }
#pragma unroll
      for (int i = 0; i < 4; i++) {
        int id  = tid + i * 256;
        int buf = id >> 9;
        int rem = id & 511;
        int r   = rem >> 2, q = rem & 3;
        const uint4* src = reinterpret_cast<const uint4*>(
            (buf ? g_B3l : g_B3h) + ((size_t)(tap * 128 + r)) * 128 + ci0);
        *reinterpret_cast<uint4*>(&sB[buf][r * 40 + q * 8]) = src[q];
      }
      __syncthreads();

#pragma unroll
      for (int ks = 0; ks < 2; ks++) {
        unsigned ah[3][4], al[3][4], bh[4][2], bl[4][2];
        const int arow = warp_m * 48 + (lane & 7) + ((lane >> 3) & 1) * 8;
        const int acol = ks * 16 + ((lane >> 4) & 1) * 8;
#pragma unroll
        for (int mi = 0; mi < 3; mi++) {
          uint32_t off = (uint32_t)(((arow + mi * 16) * 40 + acol) * 2);
          ldsm_x4(ah[mi], aB + off);
          ldsm_x4(al[mi], aB + 96 * 40 * 2 + off);
        }
        const int brow = warp_n * 32 + (lane & 7);
        const int bcol = ks * 16 + ((lane >> 3) & 1) * 8;
#pragma unroll
        for (int ni = 0; ni < 4; ni++) {
          uint32_t off = (uint32_t)(((brow + ni * 8) * 40 + bcol) * 2);
          ldsm_x2(bh[ni], bB + off);
          ldsm_x2(bl[ni], bB + 128 * 40 * 2 + off);
        }
#pragma unroll
        for (int mi = 0; mi < 3; mi++)
#pragma unroll
          for (int ni = 0; ni < 4; ni++) {
            mma_bf16(acc[mi][ni], ah[mi], bh[ni]);
            mma_bf16(acc[mi][ni], ah[mi], bl[ni]);
            mma_bf16(acc[mi][ni], al[mi], bh[ni]);
          }
      }
    }
  }

  const int g = lane >> 2, tg = lane & 3;
#pragma unroll
  for (int mi = 0; mi < 3; mi++)
#pragma unroll
    for (int ni = 0; ni < 4; ni++) {
      int row = px0 + warp_m * 48 + mi * 16 + g;
      int co  = warp_n * 32 + ni * 8 + tg * 2;
      float* d0 = xcl + ((size_t)(n * 1536 + row)) * 128 + co;
      float* d1 = xcl + ((size_t)(n * 1536 + row + 8)) * 128 + co;
      *reinterpret_cast<float2*>(d0) = make_float2(acc[mi][ni][0], acc[mi][ni][1]);
      *reinterpret_cast<float2*>(d1) = make_float2(acc[mi][ni][2], acc[mi][ni][3]);
    }
}

// ---------------------------------------------------------------------------
// gemm4: conv4 as GEMM. A from g_Xh/g_Xl (x3), N=64, Cin=128.
// ---------------------------------------------------------------------------
__global__ void __launch_bounds__(256)
gemm4_k(float* __restrict__ xcl) {
  __shared__ unsigned short sA[2][96 * 40];
  __shared__ unsigned short sB[2][64 * 40];

  const int tid  = threadIdx.x;
  const int wid  = tid >> 5, lane = tid & 31;
  const int warp_m = wid & 1;
  const int warp_n = wid >> 1;
  const int tile = blockIdx.x;
  const int n    = blockIdx.y;
  const int px0  = tile * 96;

  const uint32_t aB = smem_u32(sA);
  const uint32_t bB = smem_u32(sB);

  float acc[3][2][4];
#pragma unroll
  for (int mi = 0; mi < 3; mi++)
#pragma unroll
    for (int ni = 0; ni < 2; ni++)
#pragma unroll
      for (int j = 0; j < 4; j++) acc[mi][ni][j] = 0.f;

  for (int tap = 0; tap < 9; tap++) {
    const int dy = tap / 3, dx = tap % 3;
    for (int cc = 0; cc < 4; cc++) {
      const int ci0 = cc * 32;
      __syncthreads();
#pragma unroll
      for (int i = 0; i < 3; i++) {
        int id  = tid + i * 256;
        int buf = id / 384;
        int rem = id - buf * 384;
        int r   = rem >> 2, q = rem & 3;
        int px = px0 + r;
        int y = px / 48, x = px - y * 48;
        int pos = (y + dy) * 52 + (x + dx);
        const uint4* src = reinterpret_cast<const uint4*>(
            (buf ? g_Xl : g_Xh) + ((size_t)(n * 1768 + pos)) * 128 + ci0);
        *reinterpret_cast<uint4*>(&sA[buf][r * 40 + q * 8]) = src[q];
      }
#pragma unroll
      for (int i = 0; i < 2; i++) {
        int id  = tid + i * 256;          // 0..511
        int buf = id >> 8;
        int rem = id & 255;
        int r   = rem >> 2, q = rem & 3;
        const uint4* src = reinterpret_cast<const uint4*>(
            (buf ? g_B4l : g_B4h) + ((size_t)(tap * 64 + r)) * 128 + ci0);
        *reinterpret_cast<uint4*>(&sB[buf][r * 40 + q * 8]) = src[q];
      }
      __syncthreads();

#pragma unroll
      for (int ks = 0; ks < 2; ks++) {
        unsigned ah[3][4], al[3][4], bh[2][2], bl[2][2];
        const int arow = warp_m * 48 + (lane & 7) + ((lane >> 3) & 1) * 8;
        const int acol = ks * 16 + ((lane >> 4) & 1) * 8;
#pragma unroll
        for (int mi = 0; mi < 3; mi++) {
          uint32_t off = (uint32_t)(((arow + mi * 16) * 40 + acol) * 2);
          ldsm_x4(ah[mi], aB + off);
          ldsm_x4(al[mi], aB + 96 * 40 * 2 + off);
        }
        const int brow = warp_n * 16 + (lane & 7);
        const int bcol = ks * 16 + ((lane >> 3) & 1) * 8;
#pragma unroll
        for (int ni = 0; ni < 2; ni++) {
          uint32_t off = (uint32_t)(((brow + ni * 8) * 40 + bcol) * 2);
          ldsm_x2(bh[ni], bB + off);
          ldsm_x2(bl[ni], bB + 64 * 40 * 2 + off);
        }
#pragma unroll
        for (int mi = 0; mi < 3; mi++)
#pragma unroll
          for (int ni = 0; ni < 2; ni++) {
            mma_bf16(acc[mi][ni], ah[mi], bh[ni]);
            mma_bf16(acc[mi][ni], ah[mi], bl[ni]);
            mma_bf16(acc[mi][ni], al[mi], bh[ni]);
          }
      }
    }
  }

  const int g = lane >> 2, tg = lane & 3;
#pragma unroll
  for (int mi = 0; mi < 3; mi++)
#pragma unroll
    for (int ni = 0; ni < 2; ni++) {
      int row = px0 + warp_m * 48 + mi * 16 + g;
      int co  = warp_n * 16 + ni * 8 + tg * 2;
      float* d0 = xcl + ((size_t)(n * 1536 + row)) * 64 + co;
      float* d1 = xcl + ((size_t)(n * 1536 + row + 8)) * 64 + co;
      *reinterpret_cast<float2*>(d0) = make_float2(acc[mi][ni][0], acc[mi][ni][1]);
      *reinterpret_cast<float2*>(d1) = make_float2(acc[mi][ni][2], acc[mi][ni][3]);
    }
}

// ---------------------------------------------------------------------------
// deconv (R3 form)
// ---------------------------------------------------------------------------
__global__ void __launch_bounds__(256)
deconv4x4_k(const float* __restrict__ in, const float* __restrict__ w5,
            float* __restrict__ out) {
  constexpr int RS = 20, PLS = 18 * RS;

  __shared__ float s_in[16 * PLS];
  __shared__ __align__(16) float s_w[16 * 4 * 32];

  const int parity = blockIdx.y;
  const int a = parity >> 1, b = parity & 1;
  const int n = blockIdx.z;
  const int tx = blockIdx.x % 3;
  const int ty = blockIdx.x / 3;
  const int tid = threadIdx.x;
  const int ly = tid >> 4, lx = tid & 15;
  const int ybase = ty * 16, xbase = tx * 16;

  const float* inN = in + (size_t)n * 64 * PL2;

  float acc[32];
#pragma unroll
  for (int c = 0; c < 32; c++) acc[c] = 0.f;

  for (int cb = 0; cb < 64; cb += 16) {
    __syncthreads();
#pragma unroll
    for (int t = tid; t < 16 * 18 * 5; t += 256) {
      int c   = t / 90;
      int rem = t - c * 90;
      int r   = rem / 5;
      int q   = rem - r * 5;
      const float4 v = *reinterpret_cast<const float4*>(
          inN + (size_t)(cb + c) * PL2 + (ybase + r) * 52 + xbase + 4 * q);
      float* dst = &s_in[c * PLS + r * RS + 4 * q];
      dst[0] = v.x; dst[1] = v.y; dst[2] = v.z; dst[3] = v.w;
    }
    for (int t = tid; t < 16 * 4 * 32; t += 256) {
      int co  = t & 31;
      int tap = (t >> 5) & 3;
      int lci = t >> 7;
      int s  = tap >> 1, tt = tap & 1;
      s_w[t] = w5[(((size_t)(cb + lci) * 32 + co) * 4 + (3 - (a + 2 * s))) * 4 +
                  (3 - (b + 2 * tt))];
    }
    __syncthreads();

#pragma unroll 4
    for (int ci = 0; ci < 16; ci++) {
      float i00 = s_in[ci * PLS + (ly + a + 0) * RS + lx + b + 0];
      float i01 = s_in[ci * PLS + (ly + a + 0) * RS + lx + b + 1];
      float i10 = s_in[ci * PLS + (ly + a + 1) * RS + lx + b + 0];
      float i11 = s_in[ci * PLS + (ly + a + 1) * RS + lx + b + 1];
      const float4* wp = reinterpret_cast<const float4*>(s_w + ci * 128);
#pragma unroll
      for (int cq = 0; cq < 8; cq++) {
        float4 w0 = wp[cq];
        float4 w1 = wp[8 + cq];
        float4 w2 = wp[16 + cq];
        float4 w3 = wp[24 + cq];
        acc[4 * cq + 0] += w0.x * i00 + w1.x * i01 + w2.x * i10 + w3.x * i11;
        acc[4 * cq + 1] += w0.y * i00 + w1.y * i01 + w2.y * i10 + w3.y * i11;
        acc[4 * cq + 2] += w0.z * i00 + w1.z * i01 + w2.z * i10 + w3.z * i11;
        acc[4 * cq + 3] += w0.w * i00 + w1.w * i01 + w2.w * i10 + w3.w * i11;
      }
    }
  }

  const int oy = 2 * (ybase + ly) + a + 1;
  const int ox = 2 * (xbase + lx) + b + 1;
  float* outN = out + (size_t)n * 32 * PL1;
#pragma unroll
  for (int co = 0; co < 32; co++)
    outN[(size_t)co * PL1 + oy * 100 + ox] = acc[co];
}

// ---------------------------------------------------------------------------
// final conv (R3 form)
// ---------------------------------------------------------------------------
__global__ void __launch_bounds__(256)
conv_final_k(const float* __restrict__ in, const float* __restrict__ w6,
             const float* __restrict__ b6, float* __restrict__ out) {
  constexpr int RS = 37, PLS = 10 * RS;
  __shared__ float s_in[8 * PLS];
  __shared__ float sw[288];
  __shared__ float sb;

  const int tid = threadIdx.x;
  const int tx = blockIdx.x % 3;
  const int ty = blockIdx.x / 3;
  const int n  = blockIdx.y;
  const int y0 = ty * 8, x0 = tx * 32;
  const int px = tid & 31, py = tid >> 5;

  for (int t = tid; t < 288; t += 256) sw[t] = w6[t];
  if (tid == 0) sb = b6[0];

  const float* inN = in + (size_t)n * 32 * PL1;
  float acc = 0.f;

  for (int cb = 0; cb < 32; cb += 8) {
    __syncthreads();
#pragma unroll
    for (int t = tid; t < 8 * 10 * 9; t += 256) {
      int c   = t / 90;
      int rem = t - c * 90;
      int r   = rem / 9;
      int q   = rem - r * 9;
      const float4 v = *reinterpret_cast<const float4*>(
          inN + (size_t)(cb + c) * PL1 + (y0 + r) * 100 + x0 + 4 * q);
      float* dst = &s_in[c * PLS + r * RS + 4 * q];
      dst[0] = v.x; dst[1] = v.y; dst[2] = v.z; dst[3] = v.w;
    }
    __syncthreads();
#pragma unroll
    for (int c = 0; c < 8; c++)
#pragma unroll
      for (int ky = 0; ky < 3; ky++)
#pragma unroll
        for (int kx = 0; kx < 3; kx++)
          acc += sw[(cb + c) * 9 + ky * 3 + kx] *
                 s_in[c * PLS + (py + ky) * RS + px + kx];
  }

  out[(size_t)n * 6144 + (y0 + py) * 96 + x0 + px] = acc + sb;
}

// ---------------------------------------------------------------------------
// Launch
// ---------------------------------------------------------------------------
extern "C" void kernel_launch(void* const* d_in, const int* in_sizes, int n_in,
                              void* d_out, int out_size) {
  const float* f1 = (const float*)d_in[0];
  const float* f2 = (const float*)d_in[1];
  const float* w1 = (const float*)d_in[2];
  const float* w2 = (const float*)d_in[3];
  const float* w3 = (const float*)d_in[4];
  const float* w4 = (const float*)d_in[5];
  const float* w5 = (const float*)d_in[6];
  const float* w6 = (const float*)d_in[7];
  const float* b6 = (const float*)d_in[8];
  float* out = (float*)d_out;

  float *x1, *x4, *x5, *f1p, *f2c, *U, *V, *w1a, *w1b;
  float *x2cl, *x3cl, *x4cl;
  cudaGetSymbolAddress((void**)&x1, g_x1);
  cudaGetSymbolAddress((void**)&x4, g_x4);
  cudaGetSymbolAddress((void**)&x5, g_x5);
  cudaGetSymbolAddress((void**)&f1p, g_f1p);
  cudaGetSymbolAddress((void**)&f2c, g_f2c);
  cudaGetSymbolAddress((void**)&U, g_U);
  cudaGetSymbolAddress((void**)&V, g_V);
  cudaGetSymbolAddress((void**)&w1a, g_w1a);
  cudaGetSymbolAddress((void**)&w1b, g_w1b);
  cudaGetSymbolAddress((void**)&x2cl, g_x2cl);
  cudaGetSymbolAddress((void**)&x3cl, g_x3cl);
  cudaGetSymbolAddress((void**)&x4cl, g_x4cl);

  // prep
  prep_k<<<(2 * 32 * 6144 + 255) / 256, 256>>>(f1, f2, w1);
  wprep2_k<<<(9 * 128 * 96 + 255) / 256, 256>>>(w2);
  wprep3_k<<<(9 * 128 * 128 + 255) / 256, 256>>>(w3);
  wprep4_k<<<(9 * 64 * 128 + 255) / 256, 256>>>(w4);

  // conv1 via factorization -> planar x1, inorm
  conv3x3_s1_k<32, 64, 96, 100><<<dim3(24, 6, 2), 256>>>(f1p, w1a, U, 32, 96);
  conv_v_k<<<dim3(63, 6, 2), 128>>>(f2c, w1b, V);
  combine_k<<<NIMG * 96, 256>>>();
  stripfix_k<<<dim3(20, NIMG), 128>>>(f1, f2, w1);
  inorm_leaky_k<64, 96, 100><<<NIMG * 96, 256>>>(x1);

  // x1 -> channel-last bf16 hi/lo
  x1cl_k<<<dim3(64, NIMG), 256>>>();

  // conv2 GEMM -> x2cl; inorm (stats+apply) -> g_Xh/g_Xl
  gemm2_k<<<dim3(16, NIMG), 256>>>(x2cl);
  stats_cl_k<128><<<NIMG, 512>>>(x2cl);
  apply_cl128_k<<<dim3(32, NIMG), 256>>>(x2cl);

  // conv3 GEMM -> x3cl; inorm -> g_Xh/g_Xl (overwrite)
  gemm3_k<<<dim3(16, NIMG), 256>>>(x3cl);
  stats_cl_k<128><<<NIMG, 512>>>(x3cl);
  apply_cl128_k<<<dim3(32, NIMG), 256>>>(x3cl);

  // conv4 GEMM -> x4cl; inorm + transpose -> planar x4
  gemm4_k<<<dim3(16, NIMG), 256>>>(x4cl);
  stats_cl_k<64><<<NIMG, 512>>>(x4cl);
  apply_cl64_planar_k<<<dim3(32, NIMG), 256>>>(x4cl);

  // deconv + inorm + final
  deconv4x4_k<<<dim3(6, 4, NIMG), 256>>>(x4, w5, x5);
  inorm_leaky_k<64, 96, 100><<<NIMG * 32, 256>>>(x5);
  conv_final_k<<<dim3(24, NIMG), 256>>>(x5, w6, b6, out);
}

// round 12
// speedup vs baseline: 2.1647x; 1.0649x over previous
#include <cuda_runtime.h>
#include <cuda_bf16.h>
#include <cstdint>

// ---------------------------------------------------------------------------
// Padded planar layouts [C][H+2][WP], 1-px zero halo (globals zero-init).
// ---------------------------------------------------------------------------
#define NIMG 98
#define PL1 (66 * 100)
#define PL2 (34 * 52)
#define PLV (72 * 112)
#define PLC (80 * 120)

__device__ float g_x1 [NIMG * 96 * PL1];
__device__ float g_x5 [NIMG * 32 * PL1];

// conv1 factorization scratch
__device__ float g_f1p[2 * 32 * PL1];
__device__ float g_f2c[2 * 32 * PLC];
__device__ float g_U  [2 * 96 * PL1];
__device__ float g_V  [2 * 96 * PLV];
__device__ float g_w1a[96 * 32 * 9];
__device__ float g_w1b[96 * 32 * 9];

// tensor-core path scratch (mma.sync)
__device__ unsigned short g_X1h[(size_t)NIMG * 6600 * 96];  // x1 ch-last bf16 hi
__device__ unsigned short g_X1l[(size_t)NIMG * 6600 * 96];
__device__ unsigned short g_Xh[(size_t)NIMG * 1768 * 128];  // x2 then x3 ch-last (34x52)
__device__ unsigned short g_Xl[(size_t)NIMG * 1768 * 128];
__device__ unsigned short g_X4h[(size_t)NIMG * 1768 * 64];  // x4 ch-last bf16
__device__ unsigned short g_X4l[(size_t)NIMG * 1768 * 64];
__device__ unsigned short g_B2h[9 * 128 * 96];              // w2 [tap][co][ci]
__device__ unsigned short g_B2l[9 * 128 * 96];
__device__ unsigned short g_B3h[9 * 128 * 128];
__device__ unsigned short g_B3l[9 * 128 * 128];
__device__ unsigned short g_B4h[9 * 64 * 128];
__device__ unsigned short g_B4l[9 * 64 * 128];
__device__ unsigned short g_B5h[4 * 4 * 32 * 64];           // w5 [par][tap][co][ci]
__device__ unsigned short g_B5l[4 * 4 * 32 * 64];
__device__ float g_x2cl[(size_t)NIMG * 1536 * 128];
__device__ float g_x3cl[(size_t)NIMG * 1536 * 128];
__device__ float g_x4cl[(size_t)NIMG * 1536 * 64];
__device__ float g_x5cl[(size_t)NIMG * 4 * 1536 * 32];      // [n][par][px][co]
__device__ float g_stm[NIMG * 128];
__device__ float g_sti[NIMG * 128];

// strip-fix segment table
__device__ const int c_segy[20] = {0,0,0, 60,60,60, 4,12,20,28,36,44,52, 4,12,20,28,36,44,52};
__device__ const int c_segx[20] = {0,32,64, 0,32,64, 0,0,0,0,0,0,0, 92,92,92,92,92,92,92};
__device__ const int c_segh[20] = {4,4,4, 4,4,4, 8,8,8,8,8,8,8, 8,8,8,8,8,8,8};
__device__ const int c_segw[20] = {32,32,32, 32,32,32, 4,4,4,4,4,4,4, 4,4,4,4,4,4,4};

// ---------------------------------------------------------------------------
// mma.sync helpers
// ---------------------------------------------------------------------------
__device__ __forceinline__ uint32_t smem_u32(const void* p) {
  uint32_t a;
  asm("{ .reg .u64 t; cvta.to.shared.u64 t, %1; cvt.u32.u64 %0, t; }"
      : "=r"(a) : "l"(p));
  return a;
}
__device__ __forceinline__ void ldsm_x4(unsigned r[4], uint32_t addr) {
  asm volatile("ldmatrix.sync.aligned.m8n8.x4.shared.b16 {%0,%1,%2,%3}, [%4];"
               : "=r"(r[0]), "=r"(r[1]), "=r"(r[2]), "=r"(r[3]) : "r"(addr));
}
__device__ __forceinline__ void ldsm_x2(unsigned r[2], uint32_t addr) {
  asm volatile("ldmatrix.sync.aligned.m8n8.x2.shared.b16 {%0,%1}, [%2];"
               : "=r"(r[0]), "=r"(r[1]) : "r"(addr));
}
__device__ __forceinline__ void mma_bf16(float d[4], const unsigned a[4],
                                         const unsigned b[2]) {
  asm volatile(
      "mma.sync.aligned.m16n8k16.row.col.f32.bf16.bf16.f32 "
      "{%0,%1,%2,%3}, {%4,%5,%6,%7}, {%8,%9}, {%0,%1,%2,%3};"
      : "+f"(d[0]), "+f"(d[1]), "+f"(d[2]), "+f"(d[3])
      : "r"(a[0]), "r"(a[1]), "r"(a[2]), "r"(a[3]), "r"(b[0]), "r"(b[1]));
}
__device__ __forceinline__ void bf16_split(float v, unsigned short& h,
                                           unsigned short& l) {
  __nv_bfloat16 hb = __float2bfloat16(v);
  __nv_bfloat16 lb = __float2bfloat16(v - __bfloat162float(hb));
  h = __bfloat16_as_ushort(hb);
  l = __bfloat16_as_ushort(lb);
}

// ---------------------------------------------------------------------------
// prep + weight splits
// ---------------------------------------------------------------------------
__global__ void prep_k(const float* __restrict__ f1, const float* __restrict__ f2,
                       const float* __restrict__ w1) {
  int idx = blockIdx.x * blockDim.x + threadIdx.x;
  if (idx < 2 * 32 * 6144) {
    int x = idx % 96, y = (idx / 96) % 64, c = idx / 6144;
    g_f1p[(size_t)c * PL1 + (y + 1) * 100 + x + 1] = f1[idx];
    g_f2c[(size_t)c * PLC + (y + 8) * 120 + x + 8] = f2[idx];
  }
  if (idx < 96 * 64 * 9) {
    int co = idx / 576, rem = idx % 576, ci = rem / 9, k = rem % 9;
    if (ci < 32) g_w1a[(co * 32 + ci) * 9 + k] = w1[idx];
    else         g_w1b[(co * 32 + (ci - 32)) * 9 + k] = w1[idx];
  }
}
__global__ void wprep2_k(const float* __restrict__ w2) {
  int idx = blockIdx.x * blockDim.x + threadIdx.x;
  if (idx >= 9 * 128 * 96) return;
  int ci = idx % 96, co = (idx / 96) % 128, tap = idx / 12288;
  bf16_split(w2[(co * 96 + ci) * 9 + tap], g_B2h[idx], g_B2l[idx]);
}
__global__ void wprep3_k(const float* __restrict__ w3) {
  int idx = blockIdx.x * blockDim.x + threadIdx.x;
  if (idx >= 9 * 128 * 128) return;
  int ci = idx & 127, co = (idx >> 7) & 127, tap = idx >> 14;
  bf16_split(w3[(co * 128 + ci) * 9 + tap], g_B3h[idx], g_B3l[idx]);
}
__global__ void wprep4_k(const float* __restrict__ w4) {
  int idx = blockIdx.x * blockDim.x + threadIdx.x;
  if (idx >= 9 * 64 * 128) return;
  int ci = idx & 127, co = (idx >> 7) & 63, tap = idx >> 13;
  bf16_split(w4[(co * 128 + ci) * 9 + tap], g_B4h[idx], g_B4l[idx]);
}
// w5[ci][co][3-(a+2s)][3-(b+2t)] -> [par][tap][co][ci]
__global__ void wprep5_k(const float* __restrict__ w5) {
  int idx = blockIdx.x * blockDim.x + threadIdx.x;
  if (idx >= 4 * 4 * 32 * 64) return;
  int ci  = idx & 63;
  int co  = (idx >> 6) & 31;
  int tap = (idx >> 11) & 3;
  int par = idx >> 13;
  int a = par >> 1, b = par & 1;
  int s = tap >> 1, t = tap & 1;
  float v = w5[(((size_t)ci * 32 + co) * 4 + (3 - (a + 2 * s))) * 4 +
               (3 - (b + 2 * t))];
  bf16_split(v, g_B5h[idx], g_B5l[idx]);
}

// ---------------------------------------------------------------------------
// 3x3 s1 conv (scalar, conv1 factorization)
// ---------------------------------------------------------------------------
template <int TW, int H, int W, int WP>
__global__ void __launch_bounds__(8 * TW)
conv3x3_s1_k(const float* __restrict__ in, const float* __restrict__ w,
             float* __restrict__ out, int Cin, int Cout) {
  constexpr int PXG = TW / 4;
  constexpr int NT  = 8 * TW;
  constexpr int RS  = 37;
  constexpr int PLS = 10 * RS;
  constexpr int F4  = (TW + 4) / 4;
  constexpr int PLANE = (H + 2) * WP;

  __shared__ float s_in[8 * PLS];
  __shared__ __align__(16) float s_w[8 * 9 * 16];

  const int tid = threadIdx.x;
  const int cg  = tid / (8 * PXG);
  const int pid = tid % (8 * PXG);
  const int py  = pid / PXG;
  const int pxg = pid % PXG;

  const int tilesX = W / TW;
  const int tx = blockIdx.x % tilesX;
  const int ty = blockIdx.x / tilesX;
  const int n  = blockIdx.z;
  const int coB = blockIdx.y * 16;
  const int y0 = ty * 8, x0 = tx * TW;

  const float* inN = in + (size_t)n * Cin * PLANE;

  float acc[4][4];
#pragma unroll
  for (int q = 0; q < 4; q++)
#pragma unroll
    for (int p = 0; p < 4; p++) acc[q][p] = 0.f;

  for (int cb = 0; cb < Cin; cb += 8) {
    __syncthreads();
#pragma unroll
    for (int t = tid; t < 8 * 10 * F4; t += NT) {
      int c   = t / (10 * F4);
      int rem = t - c * (10 * F4);
      int r   = rem / F4;
      int q   = rem - r * F4;
      const float4 v = *reinterpret_cast<const float4*>(
          inN + (size_t)(cb + c) * PLANE + (y0 + r) * WP + x0 + 4 * q);
      float* dst = &s_in[c * PLS + r * RS + 4 * q];
      dst[0] = v.x; dst[1] = v.y; dst[2] = v.z; dst[3] = v.w;
    }
    for (int t = tid; t < 16 * 8 * 9; t += NT) {
      int lco = t & 15;
      int rem = t >> 4;
      int k   = rem % 9;
      int lci = rem / 9;
      s_w[(lci * 9 + k) * 16 + lco] =
          w[((size_t)(coB + lco) * Cin + (cb + lci)) * 9 + k];
    }
    __syncthreads();

#pragma unroll
    for (int ci = 0; ci < 8; ci++) {
#pragma unroll
      for (int ky = 0; ky < 3; ky++) {
        float r[6];
#pragma unroll
        for (int j = 0; j < 6; j++)
          r[j] = s_in[ci * PLS + (py + ky) * RS + pxg * 4 + j];
#pragma unroll
        for (int kx = 0; kx < 3; kx++) {
          float4 wv =
              reinterpret_cast<const float4*>(s_w)[(ci * 9 + ky * 3 + kx) * 4 + cg];
#pragma unroll
          for (int p = 0; p < 4; p++) {
            float iv = r[p + kx];
            acc[0][p] += wv.x * iv;
            acc[1][p] += wv.y * iv;
            acc[2][p] += wv.z * iv;
            acc[3][p] += wv.w * iv;
          }
        }
      }
    }
  }

  float* outN = out + (size_t)n * Cout * PLANE;
  const int gy = y0 + py + 1;
#pragma unroll
  for (int q = 0; q < 4; q++) {
    int co = coB + cg * 4 + q;
#pragma unroll
    for (int p = 0; p < 4; p++)
      outN[(size_t)co * PLANE + gy * WP + x0 + pxg * 4 + p + 1] = acc[q][p];
  }
}

// ---------------------------------------------------------------------------
// V = conv3x3(zero-padded f2) on extended 72x112 grid
// ---------------------------------------------------------------------------
__global__ void __launch_bounds__(128)
conv_v_k(const float* __restrict__ in, const float* __restrict__ w,
         float* __restrict__ out) {
  constexpr int RS = 37, PLS = 10 * RS;
  __shared__ float s_in[8 * PLS];
  __shared__ __align__(16) float s_w[8 * 9 * 16];

  const int tid = threadIdx.x;
  const int cg  = tid >> 5;
  const int pid = tid & 31;
  const int py  = pid >> 2;
  const int pxg = pid & 3;

  const int tx = blockIdx.x % 7;
  const int ty = blockIdx.x / 7;
  const int n  = blockIdx.z;
  const int coB = blockIdx.y * 16;
  const int y0 = ty * 8, x0 = tx * 16;

  const float* inN = in + (size_t)n * 32 * PLC;

  float acc[4][4];
#pragma unroll
  for (int q = 0; q < 4; q++)
#pragma unroll
    for (int p = 0; p < 4; p++) acc[q][p] = 0.f;

  for (int cb = 0; cb < 32; cb += 8) {
    __syncthreads();
#pragma unroll
    for (int t = tid; t < 8 * 10 * 5; t += 128) {
      int c   = t / 50;
      int rem = t - c * 50;
      int r   = rem / 5;
      int q   = rem - r * 5;
      const float4 v = *reinterpret_cast<const float4*>(
          inN + (size_t)(cb + c) * PLC + (y0 + r + 4) * 120 + x0 + 4 * q + 4);
      float* dst = &s_in[c * PLS + r * RS + 4 * q];
      dst[0] = v.x; dst[1] = v.y; dst[2] = v.z; dst[3] = v.w;
    }
    for (int t = tid; t < 16 * 8 * 9; t += 128) {
      int lco = t & 15;
      int rem = t >> 4;
      int k   = rem % 9;
      int lci = rem / 9;
      s_w[(lci * 9 + k) * 16 + lco] =
          w[((coB + lco) * 32 + cb + lci) * 9 + k];
    }
    __syncthreads();

#pragma unroll
    for (int ci = 0; ci < 8; ci++) {
#pragma unroll
      for (int ky = 0; ky < 3; ky++) {
        float r[6];
#pragma unroll
        for (int j = 0; j < 6; j++)
          r[j] = s_in[ci * PLS + (py + ky) * RS + pxg * 4 + j];
#pragma unroll
        for (int kx = 0; kx < 3; kx++) {
          float4 wv =
              reinterpret_cast<const float4*>(s_w)[(ci * 9 + ky * 3 + kx) * 4 + cg];
#pragma unroll
          for (int p = 0; p < 4; p++) {
            float iv = r[p + kx];
            acc[0][p] += wv.x * iv;
            acc[1][p] += wv.y * iv;
            acc[2][p] += wv.z * iv;
            acc[3][p] += wv.w * iv;
          }
        }
      }
    }
  }

  float* outN = out + (size_t)n * 96 * PLV;
  const int gy = y0 + py;
#pragma unroll
  for (int q = 0; q < 4; q++) {
    int co = coB + cg * 4 + q;
#pragma unroll
    for (int p = 0; p < 4; p++)
      outN[(size_t)co * PLV + gy * 112 + x0 + pxg * 4 + p] = acc[q][p];
  }
}

// ---------------------------------------------------------------------------
// combine: x1 = U + shift(V)
// ---------------------------------------------------------------------------
__global__ void __launch_bounds__(256) combine_k() {
  const int bid = blockIdx.x;
  const int co = bid % 96, n = bid / 96;
  const int b = n / 49, d = n % 49;
  const int di = d / 7 - 3, dj = d % 7 - 3;

  const float* U = g_U + ((size_t)(b * 96 + co)) * PL1;
  const float* V = g_V + ((size_t)(b * 96 + co)) * PLV + (dj + 3) * 112 + (di + 3);
  float* X = g_x1 + ((size_t)(n * 96 + co)) * PL1;

  const int y0 = threadIdx.x >> 5, xl = threadIdx.x & 31;
  for (int y = y0; y < 64; y += 8) {
    const int ro = (y + 1) * 100 + 1;
    const int rv = y * 112;
#pragma unroll
    for (int x = xl; x < 96; x += 32)
      X[ro + x] = U[ro + x] + V[rv + x];
  }
}

// ---------------------------------------------------------------------------
// strip fix (exact conv1 on 1216 border px)
// ---------------------------------------------------------------------------
__global__ void __launch_bounds__(128)
stripfix_k(const float* __restrict__ f1, const float* __restrict__ f2,
           const float* __restrict__ w1) {
  const int sid = blockIdx.x;
  const int n   = blockIdx.y;
  const int y0 = c_segy[sid], x0 = c_segx[sid];
  const int h  = c_segh[sid], w = c_segw[sid];
  const int b = n / 49, d = n % 49;
  const int di = d / 7 - 3;
  const int dj = d % 7 - 3;
  const int H2 = h + 2, W2 = w + 2;

  __shared__ float s_in[8 * 10 * 34];
  __shared__ __align__(16) float s_w[8 * 9 * 32];

  const int tid = threadIdx.x;
  const bool act = tid < h * w;
  const int py = act ? tid / w : 0;
  const int px = act ? tid % w : 0;

  const float* f1b = f1 + (size_t)b * 32 * 6144;
  const float* f2b = f2 + (size_t)b * 32 * 6144;

  for (int coc = 0; coc < 3; coc++) {
    float acc[32];
#pragma unroll
    for (int c = 0; c < 32; c++) acc[c] = 0.f;

    for (int cb = 0; cb < 64; cb += 8) {
      __syncthreads();
      for (int t = tid; t < 8 * H2 * W2; t += 128) {
        int ci  = t / (H2 * W2);
        int rem = t - ci * (H2 * W2);
        int r   = rem / W2;
        int c   = rem - r * W2;
        int yy = y0 - 1 + r, xx = x0 - 1 + c;
        int cic = cb + ci;
        float v = 0.f;
        bool ok = (unsigned)yy < 64u && (unsigned)xx < 96u &&
                  (unsigned)(yy + dj) < 64u && (unsigned)(xx + di) < 96u;
        if (ok)
          v = (cic < 32) ? f1b[cic * 6144 + yy * 96 + xx]
                         : f2b[(cic - 32) * 6144 + (yy + dj) * 96 + (xx + di)];
        s_in[ci * 340 + r * 34 + c] = v;
      }
      for (int t = tid; t < 32 * 8 * 9; t += 128) {
        int co  = t & 31;
        int rem = t >> 5;
        int k   = rem % 9;
        int ci  = rem / 9;
        s_w[(ci * 9 + k) * 32 + co] =
            w1[((coc * 32 + co) * 64 + cb + ci) * 9 + k];
      }
      __syncthreads();

      if (act) {
#pragma unroll
        for (int ci = 0; ci < 8; ci++)
#pragma unroll
          for (int ky = 0; ky < 3; ky++)
#pragma unroll
            for (int kx = 0; kx < 3; kx++) {
              float v = s_in[ci * 340 + (py + ky) * 34 + (px + kx)];
              const float4* wv = reinterpret_cast<const float4*>(
                  &s_w[(ci * 9 + ky * 3 + kx) * 32]);
#pragma unroll
              for (int q = 0; q < 8; q++) {
                float4 ww = wv[q];
                acc[4 * q + 0] += ww.x * v;
                acc[4 * q + 1] += ww.y * v;
                acc[4 * q + 2] += ww.z * v;
                acc[4 * q + 3] += ww.w * v;
              }
            }
      }
    }
    if (act) {
#pragma unroll
      for (int c = 0; c < 32; c++)
        g_x1[((size_t)n * 96 + coc * 32 + c) * PL1 +
             (y0 + py + 1) * 100 + (x0 + px + 1)] = acc[c];
    }
    __syncthreads();
  }
}

// ---------------------------------------------------------------------------
// stats over planar padded plane (one block per (n,c) plane of g_x1)
// ---------------------------------------------------------------------------
__global__ void __launch_bounds__(256)
stats1_k() {
  const float* p = g_x1 + (size_t)blockIdx.x * PL1;
  const int wid = threadIdx.x >> 5, ln = threadIdx.x & 31;

  float s = 0.f, q = 0.f;
  for (int y = wid; y < 64; y += 8)
    for (int xx = ln; xx < 96; xx += 32) {
      float v = p[(y + 1) * 100 + xx + 1];
      s += v; q += v * v;
    }
#pragma unroll
  for (int o = 16; o > 0; o >>= 1) {
    s += __shfl_xor_sync(0xffffffffu, s, o);
    q += __shfl_xor_sync(0xffffffffu, q, o);
  }
  __shared__ float ss[8], sq[8];
  if (ln == 0) { ss[wid] = s; sq[wid] = q; }
  __syncthreads();
  if (threadIdx.x == 0) {
    float S = 0.f, Q = 0.f;
#pragma unroll
    for (int i = 0; i < 8; i++) { S += ss[i]; Q += sq[i]; }
    float m = S / 6144.f;
    float var = Q / 6144.f - m * m;
    g_stm[blockIdx.x] = m;                  // index = n*96 + c
    g_sti[blockIdx.x] = rsqrtf(var + 1e-5f);
  }
}

// ---------------------------------------------------------------------------
// apply norm+leaky to planar x1, transpose to ch-last, split bf16 hi/lo
// ---------------------------------------------------------------------------
__global__ void __launch_bounds__(256)
apply_x1cl_k() {
  __shared__ float s[96 * 97];
  const int y = blockIdx.x;   // 0..63
  const int n = blockIdx.y;
  const int tid = threadIdx.x;
  const int wid = tid >> 5, ln = tid & 31;

  for (int ci = wid; ci < 96; ci += 8) {
    const float* src = g_x1 + ((size_t)(n * 96 + ci)) * PL1 + (y + 1) * 100 + 1;
    for (int x = ln; x < 96; x += 32) s[x * 97 + ci] = src[x];
  }
  __syncthreads();
  for (int idx = tid; idx < 96 * 96; idx += 256) {
    int x = idx / 96, ci = idx % 96;
    float m = g_stm[n * 96 + ci], iv = g_sti[n * 96 + ci];
    float v = (s[x * 97 + ci] - m) * iv;
    v = v >= 0.f ? v : 0.01f * v;
    size_t o = ((size_t)(n * 6600 + (y + 1) * 100 + (x + 1))) * 96 + ci;
    bf16_split(v, g_X1h[o], g_X1l[o]);
  }
}

// ---------------------------------------------------------------------------
// stats over channel-last fp32 [n][NPX][C]
// ---------------------------------------------------------------------------
template <int C, int NPX>
__global__ void __launch_bounds__(512)
stats_cl_k(const float* __restrict__ xcl) {
  constexpr int SL = 512 / C;
  constexpr int PXS = NPX / SL;
  __shared__ float sm[512], sq[512];
  const int n = blockIdx.x;
  const int tid = threadIdx.x;
  const int ci = tid % C, sl = tid / C;

  const float* base = xcl + (size_t)n * NPX * C + ci;
  float s = 0.f, q = 0.f;
  for (int i = 0; i < PXS; i++) {
    float v = base[(size_t)(sl * PXS + i) * C];
    s += v; q += v * v;
  }
  sm[tid] = s; sq[tid] = q;
  __syncthreads();
  if (tid < C) {
    float S = 0.f, Q = 0.f;
#pragma unroll
    for (int j = 0; j < SL; j++) { S += sm[ci + j * C]; Q += sq[ci + j * C]; }
    float m = S / (float)NPX;
    float var = Q / (float)NPX - m * m;
    g_stm[n * 128 + ci] = m;
    g_sti[n * 128 + ci] = rsqrtf(var + 1e-5f);
  }
}

// ---------------------------------------------------------------------------
// apply norm+leaky (C=128) -> bf16 hi/lo padded ch-last (g_Xh/g_Xl)
// ---------------------------------------------------------------------------
__global__ void __launch_bounds__(256)
apply_cl128_k(const float* __restrict__ xcl) {
  const int y = blockIdx.x;   // 0..31
  const int n = blockIdx.y;
  const int tid = threadIdx.x;
  for (int idx = tid; idx < 48 * 128; idx += 256) {
    int x = idx >> 7, ci = idx & 127;
    float m = g_stm[n * 128 + ci], iv = g_sti[n * 128 + ci];
    float v = (xcl[((size_t)(n * 1536 + y * 48 + x)) * 128 + ci] - m) * iv;
    v = v >= 0.f ? v : 0.01f * v;
    size_t o = ((size_t)(n * 1768 + (y + 1) * 52 + (x + 1))) * 128 + ci;
    bf16_split(v, g_Xh[o], g_Xl[o]);
  }
}

// ---------------------------------------------------------------------------
// apply norm+leaky (C=64) -> bf16 hi/lo padded ch-last (g_X4h/g_X4l)
// ---------------------------------------------------------------------------
__global__ void __launch_bounds__(256)
apply_cl64_k(const float* __restrict__ xcl) {
  const int y = blockIdx.x;   // 0..31
  const int n = blockIdx.y;
  const int tid = threadIdx.x;
  for (int idx = tid; idx < 48 * 64; idx += 256) {
    int x = idx >> 6, ci = idx & 63;
    float m = g_stm[n * 128 + ci], iv = g_sti[n * 128 + ci];
    float v = (xcl[((size_t)(n * 1536 + y * 48 + x)) * 64 + ci] - m) * iv;
    v = v >= 0.f ? v : 0.01f * v;
    size_t o = ((size_t)(n * 1768 + (y + 1) * 52 + (x + 1))) * 64 + ci;
    bf16_split(v, g_X4h[o], g_X4l[o]);
  }
}

// ---------------------------------------------------------------------------
// apply norm+leaky to x5cl [n][par][1536][32] -> planar padded g_x5
// ---------------------------------------------------------------------------
__global__ void __launch_bounds__(256)
apply_x5_planar_k() {
  const int yq = blockIdx.x;  // 0..31 (y')
  const int n  = blockIdx.y;
  const int tid = threadIdx.x;
  float* outN = g_x5 + (size_t)n * 32 * PL1;

  for (int par = 0; par < 4; par++) {
    const int a = par >> 1, b = par & 1;
    const float* src = g_x5cl + ((size_t)(n * 4 + par) * 1536 + yq * 48) * 32;
    const int oy = 2 * yq + a + 1;
    for (int idx = tid; idx < 48 * 32; idx += 256) {
      int x = idx >> 5, co = idx & 31;
      float m = g_stm[n * 128 + co], iv = g_sti[n * 128 + co];
      float v = (src[x * 32 + co] - m) * iv;
      v = v >= 0.f ? v : 0.01f * v;
      outN[(size_t)co * PL1 + oy * 100 + 2 * x + b + 1] = v;
    }
  }
}

// ---------------------------------------------------------------------------
// gemm2: conv2 (stride 2), M-tile 96, N=128, Cin=96
// ---------------------------------------------------------------------------
__global__ void __launch_bounds__(256)
gemm2_k(float* __restrict__ xcl) {
  __shared__ unsigned short sA[2][96 * 40];
  __shared__ unsigned short sB[2][128 * 40];

  const int tid  = threadIdx.x;
  const int wid  = tid >> 5, lane = tid & 31;
  const int warp_m = wid & 1;
  const int warp_n = wid >> 1;
  const int tile = blockIdx.x;
  const int n    = blockIdx.y;
  const int px0  = tile * 96;

  const uint32_t aB = smem_u32(sA);
  const uint32_t bB = smem_u32(sB);

  float acc[3][4][4];
#pragma unroll
  for (int mi = 0; mi < 3; mi++)
#pragma unroll
    for (int ni = 0; ni < 4; ni++)
#pragma unroll
      for (int j = 0; j < 4; j++) acc[mi][ni][j] = 0.f;

  for (int tap = 0; tap < 9; tap++) {
    const int dy = tap / 3, dx = tap % 3;
    for (int cc = 0; cc < 3; cc++) {
      const int ci0 = cc * 32;
      __syncthreads();
#pragma unroll
      for (int i = 0; i < 3; i++) {
        int id  = tid + i * 256;
        int buf = id / 384;
        int rem = id - buf * 384;
        int r   = rem >> 2, q = rem & 3;
        int px = px0 + r;
        int y = px / 48, x = px - y * 48;
        int pos = (2 * y + dy) * 100 + (2 * x + dx);
        const uint4* src = reinterpret_cast<const uint4*>(
            (buf ? g_X1l : g_X1h) + ((size_t)(n * 6600 + pos)) * 96 + ci0);
        *reinterpret_cast<uint4*>(&sA[buf][r * 40 + q * 8]) = src[q];
      }
#pragma unroll
      for (int i = 0; i < 4; i++) {
        int id  = tid + i * 256;
        int buf = id >> 9;
        int rem = id & 511;
        int r   = rem >> 2, q = rem & 3;
        const uint4* src = reinterpret_cast<const uint4*>(
            (buf ? g_B2l : g_B2h) + ((size_t)(tap * 128 + r)) * 96 + ci0);
        *reinterpret_cast<uint4*>(&sB[buf][r * 40 + q * 8]) = src[q];
      }
      __syncthreads();

#pragma unroll
      for (int ks = 0; ks < 2; ks++) {
        unsigned ah[3][4], al[3][4], bh[4][2], bl[4][2];
        const int arow = warp_m * 48 + (lane & 7) + ((lane >> 3) & 1) * 8;
        const int acol = ks * 16 + ((lane >> 4) & 1) * 8;
#pragma unroll
        for (int mi = 0; mi < 3; mi++) {
          uint32_t off = (uint32_t)(((arow + mi * 16) * 40 + acol) * 2);
          ldsm_x4(ah[mi], aB + off);
          ldsm_x4(al[mi], aB + 96 * 40 * 2 + off);
        }
        const int brow = warp_n * 32 + (lane & 7);
        const int bcol = ks * 16 + ((lane >> 3) & 1) * 8;
#pragma unroll
        for (int ni = 0; ni < 4; ni++) {
          uint32_t off = (uint32_t)(((brow + ni * 8) * 40 + bcol) * 2);
          ldsm_x2(bh[ni], bB + off);
          ldsm_x2(bl[ni], bB + 128 * 40 * 2 + off);
        }
#pragma unroll
        for (int mi = 0; mi < 3; mi++)
#pragma unroll
          for (int ni = 0; ni < 4; ni++) {
            mma_bf16(acc[mi][ni], ah[mi], bh[ni]);
            mma_bf16(acc[mi][ni], ah[mi], bl[ni]);
            mma_bf16(acc[mi][ni], al[mi], bh[ni]);
          }
      }
    }
  }

  const int g = lane >> 2, tg = lane & 3;
#pragma unroll
  for (int mi = 0; mi < 3; mi++)
#pragma unroll
    for (int ni = 0; ni < 4; ni++) {
      int row = px0 + warp_m * 48 + mi * 16 + g;
      int co  = warp_n * 32 + ni * 8 + tg * 2;
      float* d0 = xcl + ((size_t)(n * 1536 + row)) * 128 + co;
      float* d1 = xcl + ((size_t)(n * 1536 + row + 8)) * 128 + co;
      *reinterpret_cast<float2*>(d0) = make_float2(acc[mi][ni][0], acc[mi][ni][1]);
      *reinterpret_cast<float2*>(d1) = make_float2(acc[mi][ni][2], acc[mi][ni][3]);
    }
}

// ---------------------------------------------------------------------------
// gemm3: conv3, N=128, Cin=128 (A = g_Xh/g_Xl)
// ---------------------------------------------------------------------------
__global__ void __launch_bounds__(256)
gemm3_k(float* __restrict__ xcl) {
  __shared__ unsigned short sA[2][96 * 40];
  __shared__ unsigned short sB[2][128 * 40];

  const int tid  = threadIdx.x;
  const int wid  = tid >> 5, lane = tid & 31;
  const int warp_m = wid & 1;
  const int warp_n = wid >> 1;
  const int tile = blockIdx.x;
  const int n    = blockIdx.y;
  const int px0  = tile * 96;

  const uint32_t aB = smem_u32(sA);
  const uint32_t bB = smem_u32(sB);

  float acc[3][4][4];
#pragma unroll
  for (int mi = 0; mi < 3; mi++)
#pragma unroll
    for (int ni = 0; ni < 4; ni++)
#pragma unroll
      for (int j = 0; j < 4; j++) acc[mi][ni][j] = 0.f;

  for (int tap = 0; tap < 9; tap++) {
    const int dy = tap / 3, dx = tap % 3;
    for (int cc = 0; cc < 4; cc++) {
      const int ci0 = cc * 32;
      __syncthreads();
#pragma unroll
      for (int i = 0; i < 3; i++) {
        int id  = tid + i * 256;
        int buf = id / 384;
        int rem = id - buf * 384;
        int r   = rem >> 2, q = rem & 3;
        int px = px0 + r;
        int y = px / 48, x = px - y * 48;
        int pos = (y + dy) * 52 + (x + dx);
        const uint4* src = reinterpret_cast<const uint4*>(
            (buf ? g_Xl : g_Xh) + ((size_t)(n * 1768 + pos)) * 128 + ci0);
        *reinterpret_cast<uint4*>(&sA[buf][r * 40 + q * 8]) = src[q];
      }
#pragma unroll
      for (int i = 0; i < 4; i++) {
        int id  = tid + i * 256;
        int buf = id >> 9;
        int rem = id & 511;
        int r   = rem >> 2, q = rem & 3;
        const uint4* src = reinterpret_cast<const uint4*>(
            (buf ? g_B3l : g_B3h) + ((size_t)(tap * 128 + r)) * 128 + ci0);
        *reinterpret_cast<uint4*>(&sB[buf][r * 40 + q * 8]) = src[q];
      }
      __syncthreads();

#pragma unroll
      for (int ks = 0; ks < 2; ks++) {
        unsigned ah[3][4], al[3][4], bh[4][2], bl[4][2];
        const int arow = warp_m * 48 + (lane & 7) + ((lane >> 3) & 1) * 8;
        const int acol = ks * 16 + ((lane >> 4) & 1) * 8;
#pragma unroll
        for (int mi = 0; mi < 3; mi++) {
          uint32_t off = (uint32_t)(((arow + mi * 16) * 40 + acol) * 2);
          ldsm_x4(ah[mi], aB + off);
          ldsm_x4(al[mi], aB + 96 * 40 * 2 + off);
        }
        const int brow = warp_n * 32 + (lane & 7);
        const int bcol = ks * 16 + ((lane >> 3) & 1) * 8;
#pragma unroll
        for (int ni = 0; ni < 4; ni++) {
          uint32_t off = (uint32_t)(((brow + ni * 8) * 40 + bcol) * 2);
          ldsm_x2(bh[ni], bB + off);
          ldsm_x2(bl[ni], bB + 128 * 40 * 2 + off);
        }
#pragma unroll
        for (int mi = 0; mi < 3; mi++)
#pragma unroll
          for (int ni = 0; ni < 4; ni++) {
            mma_bf16(acc[mi][ni], ah[mi], bh[ni]);
            mma_bf16(acc[mi][ni], ah[mi], bl[ni]);
            mma_bf16(acc[mi][ni], al[mi], bh[ni]);
          }
      }
    }
  }

  const int g = lane >> 2, tg = lane & 3;
#pragma unroll
  for (int mi = 0; mi < 3; mi++)
#pragma unroll
    for (int ni = 0; ni < 4; ni++) {
      int row = px0 + warp_m * 48 + mi * 16 + g;
      int co  = warp_n * 32 + ni * 8 + tg * 2;
      float* d0 = xcl + ((size_t)(n * 1536 + row)) * 128 + co;
      float* d1 = xcl + ((size_t)(n * 1536 + row + 8)) * 128 + co;
      *reinterpret_cast<float2*>(d0) = make_float2(acc[mi][ni][0], acc[mi][ni][1]);
      *reinterpret_cast<float2*>(d1) = make_float2(acc[mi][ni][2], acc[mi][ni][3]);
    }
}

// ---------------------------------------------------------------------------
// gemm4: conv4, N=64, Cin=128 (A = g_Xh/g_Xl)
// ---------------------------------------------------------------------------
__global__ void __launch_bounds__(256)
gemm4_k(float* __restrict__ xcl) {
  __shared__ unsigned short sA[2][96 * 40];
  __shared__ unsigned short sB[2][64 * 40];

  const int tid  = threadIdx.x;
  const int wid  = tid >> 5, lane = tid & 31;
  const int warp_m = wid & 1;
  const int warp_n = wid >> 1;
  const int tile = blockIdx.x;
  const int n    = blockIdx.y;
  const int px0  = tile * 96;

  const uint32_t aB = smem_u32(sA);
  const uint32_t bB = smem_u32(sB);

  float acc[3][2][4];
#pragma unroll
  for (int mi = 0; mi < 3; mi++)
#pragma unroll
    for (int ni = 0; ni < 2; ni++)
#pragma unroll
      for (int j = 0; j < 4; j++) acc[mi][ni][j] = 0.f;

  for (int tap = 0; tap < 9; tap++) {
    const int dy = tap / 3, dx = tap % 3;
    for (int cc = 0; cc < 4; cc++) {
      const int ci0 = cc * 32;
      __syncthreads();
#pragma unroll
      for (int i = 0; i < 3; i++) {
        int id  = tid + i * 256;
        int buf = id / 384;
        int rem = id - buf * 384;
        int r   = rem >> 2, q = rem & 3;
        int px = px0 + r;
        int y = px / 48, x = px - y * 48;
        int pos = (y + dy) * 52 + (x + dx);
        const uint4* src = reinterpret_cast<const uint4*>(
            (buf ? g_Xl : g_Xh) + ((size_t)(n * 1768 + pos)) * 128 + ci0);
        *reinterpret_cast<uint4*>(&sA[buf][r * 40 + q * 8]) = src[q];
      }
#pragma unroll
      for (int i = 0; i < 2; i++) {
        int id  = tid + i * 256;
        int buf = id >> 8;
        int rem = id & 255;
        int r   = rem >> 2, q = rem & 3;
        const uint4* src = reinterpret_cast<const uint4*>(
            (buf ? g_B4l : g_B4h) + ((size_t)(tap * 64 + r)) * 128 + ci0);
        *reinterpret_cast<uint4*>(&sB[buf][r * 40 + q * 8]) = src[q];
      }
      __syncthreads();

#pragma unroll
      for (int ks = 0; ks < 2; ks++) {
        unsigned ah[3][4], al[3][4], bh[2][2], bl[2][2];
        const int arow = warp_m * 48 + (lane & 7) + ((lane >> 3) & 1) * 8;
        const int acol = ks * 16 + ((lane >> 4) & 1) * 8;
#pragma unroll
        for (int mi = 0; mi < 3; mi++) {
          uint32_t off = (uint32_t)(((arow + mi * 16) * 40 + acol) * 2);
          ldsm_x4(ah[mi], aB + off);
          ldsm_x4(al[mi], aB + 96 * 40 * 2 + off);
        }
        const int brow = warp_n * 16 + (lane & 7);
        const int bcol = ks * 16 + ((lane >> 3) & 1) * 8;
#pragma unroll
        for (int ni = 0; ni < 2; ni++) {
          uint32_t off = (uint32_t)(((brow + ni * 8) * 40 + bcol) * 2);
          ldsm_x2(bh[ni], bB + off);
          ldsm_x2(bl[ni], bB + 64 * 40 * 2 + off);
        }
#pragma unroll
        for (int mi = 0; mi < 3; mi++)
#pragma unroll
          for (int ni = 0; ni < 2; ni++) {
            mma_bf16(acc[mi][ni], ah[mi], bh[ni]);
            mma_bf16(acc[mi][ni], ah[mi], bl[ni]);
            mma_bf16(acc[mi][ni], al[mi], bh[ni]);
          }
      }
    }
  }

  const int g = lane >> 2, tg = lane & 3;
#pragma unroll
  for (int mi = 0; mi < 3; mi++)
#pragma unroll
    for (int ni = 0; ni < 2; ni++) {
      int row = px0 + warp_m * 48 + mi * 16 + g;
      int co  = warp_n * 16 + ni * 8 + tg * 2;
      float* d0 = xcl + ((size_t)(n * 1536 + row)) * 64 + co;
      float* d1 = xcl + ((size_t)(n * 1536 + row + 8)) * 64 + co;
      *reinterpret_cast<float2*>(d0) = make_float2(acc[mi][ni][0], acc[mi][ni][1]);
      *reinterpret_cast<float2*>(d1) = make_float2(acc[mi][ni][2], acc[mi][ni][3]);
    }
}

// ---------------------------------------------------------------------------
// gemm5: deconv as GEMM per parity. M-tile 128, N=32, K=4 taps x 64 ci.
// A pos = (y'+a+s)*52 + (x'+b+t) in x4 ch-last padded.
// ---------------------------------------------------------------------------
__global__ void __launch_bounds__(256)
gemm5_k() {
  __shared__ unsigned short sA[2][128 * 40];
  __shared__ unsigned short sB[2][32 * 40];

  const int tid  = threadIdx.x;
  const int wid  = tid >> 5, lane = tid & 31;   // warp_m = wid (0..7)
  const int tile = blockIdx.x;                  // 0..11
  const int par  = blockIdx.y;                  // 0..3
  const int n    = blockIdx.z;
  const int a = par >> 1, b = par & 1;
  const int px0 = tile * 128;

  const uint32_t aB = smem_u32(sA);
  const uint32_t bB = smem_u32(sB);

  float acc[4][4];
#pragma unroll
  for (int ni = 0; ni < 4; ni++)
#pragma unroll
    for (int j = 0; j < 4; j++) acc[ni][j] = 0.f;

  for (int tap = 0; tap < 4; tap++) {
    const int s = tap >> 1, t = tap & 1;
    for (int cc = 0; cc < 2; cc++) {
      const int ci0 = cc * 32;
      __syncthreads();
      // A: 128 rows x 32 halfs, hi+lo -> 1024 uint4 -> 4 iters
#pragma unroll
      for (int i = 0; i < 4; i++) {
        int id  = tid + i * 256;
        int buf = id >> 9;
        int rem = id & 511;
        int r   = rem >> 2, q = rem & 3;
        int px = px0 + r;
        int y = px / 48, x = px - y * 48;
        int pos = (y + a + s) * 52 + (x + b + t);
        const uint4* src = reinterpret_cast<const uint4*>(
            (buf ? g_X4l : g_X4h) + ((size_t)(n * 1768 + pos)) * 64 + ci0);
        *reinterpret_cast<uint4*>(&sA[buf][r * 40 + q * 8]) = src[q];
      }
      // B: 32 rows x 32 halfs, hi+lo -> 256 uint4 -> 1 iter
      {
        int buf = tid >> 7;
        int rem = tid & 127;
        int r   = rem >> 2, q = rem & 3;
        const uint4* src = reinterpret_cast<const uint4*>(
            (buf ? g_B5l : g_B5h) + ((size_t)((par * 4 + tap) * 32 + r)) * 64 + ci0);
        *reinterpret_cast<uint4*>(&sB[buf][r * 40 + q * 8]) = src[q];
      }
      __syncthreads();

#pragma unroll
      for (int ks = 0; ks < 2; ks++) {
        unsigned ah[4], al[4], bh[4][2], bl[4][2];
        const int arow = wid * 16 + (lane & 7) + ((lane >> 3) & 1) * 8;
        const int acol = ks * 16 + ((lane >> 4) & 1) * 8;
        {
          uint32_t off = (uint32_t)((arow * 40 + acol) * 2);
          ldsm_x4(ah, aB + off);
          ldsm_x4(al, aB + 128 * 40 * 2 + off);
        }
        const int brow = lane & 7;
        const int bcol = ks * 16 + ((lane >> 3) & 1) * 8;
#pragma unroll
        for (int ni = 0; ni < 4; ni++) {
          uint32_t off = (uint32_t)(((brow + ni * 8) * 40 + bcol) * 2);
          ldsm_x2(bh[ni], bB + off);
          ldsm_x2(bl[ni], bB + 32 * 40 * 2 + off);
        }
#pragma unroll
        for (int ni = 0; ni < 4; ni++) {
          mma_bf16(acc[ni], ah, bh[ni]);
          mma_bf16(acc[ni], ah, bl[ni]);
          mma_bf16(acc[ni], al, bh[ni]);
        }
      }
    }
  }

  const int g = lane >> 2, tg = lane & 3;
  float* base = g_x5cl + ((size_t)(n * 4 + par)) * 1536 * 32;
#pragma unroll
  for (int ni = 0; ni < 4; ni++) {
    int row = px0 + wid * 16 + g;
    int co  = ni * 8 + tg * 2;
    *reinterpret_cast<float2*>(base + (size_t)row * 32 + co) =
        make_float2(acc[ni][0], acc[ni][1]);
    *reinterpret_cast<float2*>(base + (size_t)(row + 8) * 32 + co) =
        make_float2(acc[ni][2], acc[ni][3]);
  }
}

// ---------------------------------------------------------------------------
// final conv 32->1 + bias (planar x5 -> d_out)
// ---------------------------------------------------------------------------
__global__ void __launch_bounds__(256)
conv_final_k(const float* __restrict__ in, const float* __restrict__ w6,
             const float* __restrict__ b6, float* __restrict__ out) {
  constexpr int RS = 37, PLS = 10 * RS;
  __shared__ float s_in[8 * PLS];
  __shared__ float sw[288];
  __shared__ float sb;

  const int tid = threadIdx.x;
  const int tx = blockIdx.x % 3;
  const int ty = blockIdx.x / 3;
  const int n  = blockIdx.y;
  const int y0 = ty * 8, x0 = tx * 32;
  const int px = tid & 31, py = tid >> 5;

  for (int t = tid; t < 288; t += 256) sw[t] = w6[t];
  if (tid == 0) sb = b6[0];

  const float* inN = in + (size_t)n * 32 * PL1;
  float acc = 0.f;

  for (int cb = 0; cb < 32; cb += 8) {
    __syncthreads();
#pragma unroll
    for (int t = tid; t < 8 * 10 * 9; t += 256) {
      int c   = t / 90;
      int rem = t - c * 90;
      int r   = rem / 9;
      int q   = rem - r * 9;
      const float4 v = *reinterpret_cast<const float4*>(
          inN + (size_t)(cb + c) * PL1 + (y0 + r) * 100 + x0 + 4 * q);
      float* dst = &s_in[c * PLS + r * RS + 4 * q];
      dst[0] = v.x; dst[1] = v.y; dst[2] = v.z; dst[3] = v.w;
    }
    __syncthreads();
#pragma unroll
    for (int c = 0; c < 8; c++)
#pragma unroll
      for (int ky = 0; ky < 3; ky++)
#pragma unroll
        for (int kx = 0; kx < 3; kx++)
          acc += sw[(cb + c) * 9 + ky * 3 + kx] *
                 s_in[c * PLS + (py + ky) * RS + px + kx];
  }

  out[(size_t)n * 6144 + (y0 + py) * 96 + x0 + px] = acc + sb;
}

// ---------------------------------------------------------------------------
// Launch
// ---------------------------------------------------------------------------
extern "C" void kernel_launch(void* const* d_in, const int* in_sizes, int n_in,
                              void* d_out, int out_size) {
  const float* f1 = (const float*)d_in[0];
  const float* f2 = (const float*)d_in[1];
  const float* w1 = (const float*)d_in[2];
  const float* w2 = (const float*)d_in[3];
  const float* w3 = (const float*)d_in[4];
  const float* w4 = (const float*)d_in[5];
  const float* w5 = (const float*)d_in[6];
  const float* w6 = (const float*)d_in[7];
  const float* b6 = (const float*)d_in[8];
  float* out = (float*)d_out;

  float *x5, *f1p, *f2c, *U, *V, *w1a, *w1b, *x2cl, *x3cl, *x4cl;
  cudaGetSymbolAddress((void**)&x5, g_x5);
  cudaGetSymbolAddress((void**)&f1p, g_f1p);
  cudaGetSymbolAddress((void**)&f2c, g_f2c);
  cudaGetSymbolAddress((void**)&U, g_U);
  cudaGetSymbolAddress((void**)&V, g_V);
  cudaGetSymbolAddress((void**)&w1a, g_w1a);
  cudaGetSymbolAddress((void**)&w1b, g_w1b);
  cudaGetSymbolAddress((void**)&x2cl, g_x2cl);
  cudaGetSymbolAddress((void**)&x3cl, g_x3cl);
  cudaGetSymbolAddress((void**)&x4cl, g_x4cl);

  // prep
  prep_k<<<(2 * 32 * 6144 + 255) / 256, 256>>>(f1, f2, w1);
  wprep2_k<<<(9 * 128 * 96 + 255) / 256, 256>>>(w2);
  wprep3_k<<<(9 * 128 * 128 + 255) / 256, 256>>>(w3);
  wprep4_k<<<(9 * 64 * 128 + 255) / 256, 256>>>(w4);
  wprep5_k<<<(4 * 4 * 32 * 64 + 255) / 256, 256>>>(w5);

  // conv1 via factorization -> planar x1 (pre-norm)
  conv3x3_s1_k<32, 64, 96, 100><<<dim3(24, 6, 2), 256>>>(f1p, w1a, U, 32, 96);
  conv_v_k<<<dim3(63, 6, 2), 128>>>(f2c, w1b, V);
  combine_k<<<NIMG * 96, 256>>>();
  stripfix_k<<<dim3(20, NIMG), 128>>>(f1, f2, w1);

  // x1: fused stats -> apply+transpose+bf16 split
  stats1_k<<<NIMG * 96, 256>>>();
  apply_x1cl_k<<<dim3(64, NIMG), 256>>>();

  // conv2 GEMM; inorm -> g_Xh/g_Xl
  gemm2_k<<<dim3(16, NIMG), 256>>>(x2cl);
  stats_cl_k<128, 1536><<<NIMG, 512>>>(x2cl);
  apply_cl128_k<<<dim3(32, NIMG), 256>>>(x2cl);

  // conv3 GEMM; inorm -> g_Xh/g_Xl (overwrite)
  gemm3_k<<<dim3(16, NIMG), 256>>>(x3cl);
  stats_cl_k<128, 1536><<<NIMG, 512>>>(x3cl);
  apply_cl128_k<<<dim3(32, NIMG), 256>>>(x3cl);

  // conv4 GEMM; inorm -> g_X4h/g_X4l (ch-last bf16)
  gemm4_k<<<dim3(16, NIMG), 256>>>(x4cl);
  stats_cl_k<64, 1536><<<NIMG, 512>>>(x4cl);
  apply_cl64_k<<<dim3(32, NIMG), 256>>>(x4cl);

  // deconv GEMM (4 parities); inorm -> planar x5
  gemm5_k<<<dim3(12, 4, NIMG), 256>>>();
  {
    float* x5cl;
    cudaGetSymbolAddress((void**)&x5cl, g_x5cl);
    stats_cl_k<32, 6144><<<NIMG, 512>>>(x5cl);
  }
  apply_x5_planar_k<<<dim3(32, NIMG), 256>>>();

  // final conv
  conv_final_k<<<dim3(24, NIMG), 256>>>(x5, w6, b6, out);
}

// round 15
// speedup vs baseline: 2.6210x; 1.2108x over previous
#include <cuda_runtime.h>
#include <cuda_bf16.h>
#include <cstdint>

// ---------------------------------------------------------------------------
// Padded planar layouts [C][H+2][WP], 1-px zero halo (globals zero-init).
// ---------------------------------------------------------------------------
#define NIMG 98
#define PL1 (66 * 100)
#define PL2 (34 * 52)
#define PLV (72 * 112)
#define PLC (80 * 120)

__device__ float g_x1 [NIMG * 96 * PL1];
__device__ float g_x5 [NIMG * 32 * PL1];

// conv1 factorization scratch
__device__ float g_f1p[2 * 32 * PL1];
__device__ float g_f2c[2 * 32 * PLC];
__device__ float g_U  [2 * 96 * PL1];
__device__ float g_V  [2 * 96 * PLV];
__device__ float g_w1a[96 * 32 * 9];
__device__ float g_w1b[96 * 32 * 9];

// tensor-core path scratch (mma.sync)
__device__ unsigned short g_X1h[(size_t)NIMG * 6600 * 96];  // x1 ch-last bf16 hi
__device__ unsigned short g_X1l[(size_t)NIMG * 6600 * 96];
__device__ unsigned short g_Xh[(size_t)NIMG * 1768 * 128];  // x2 then x3 ch-last (34x52)
__device__ unsigned short g_Xl[(size_t)NIMG * 1768 * 128];
__device__ unsigned short g_X4h[(size_t)NIMG * 1768 * 64];  // x4 ch-last bf16
__device__ unsigned short g_X4l[(size_t)NIMG * 1768 * 64];
__device__ unsigned short g_B2h[9 * 128 * 96];              // w2 [tap][co][ci]
__device__ unsigned short g_B2l[9 * 128 * 96];
__device__ unsigned short g_B3h[9 * 128 * 128];
__device__ unsigned short g_B3l[9 * 128 * 128];
__device__ unsigned short g_B4h[9 * 64 * 128];
__device__ unsigned short g_B4l[9 * 64 * 128];
__device__ unsigned short g_B5h[4 * 4 * 32 * 64];           // w5 [par][tap][co][ci]
__device__ unsigned short g_B5l[4 * 4 * 32 * 64];
__device__ float g_x2cl[(size_t)NIMG * 1536 * 128];
__device__ float g_x3cl[(size_t)NIMG * 1536 * 128];
__device__ float g_x4cl[(size_t)NIMG * 1536 * 64];
__device__ float g_x5cl[(size_t)NIMG * 4 * 1536 * 32];      // [n][par][px][co]
__device__ float g_stm[NIMG * 128];
__device__ float g_sti[NIMG * 128];

// delta segment table: 10 segments, <=128 px each, covering the 4-px frame
__device__ const int d_segy[10] = {0,0,0, 60,60,60, 4,32, 4,32};
__device__ const int d_segx[10] = {0,32,64, 0,32,64, 0,0, 92,92};
__device__ const int d_segh[10] = {4,4,4, 4,4,4, 28,28, 28,28};
__device__ const int d_segw[10] = {32,32,32, 32,32,32, 4,4, 4,4};

// ---------------------------------------------------------------------------
// mma.sync helpers
// ---------------------------------------------------------------------------
__device__ __forceinline__ uint32_t smem_u32(const void* p) {
  uint32_t a;
  asm("{ .reg .u64 t; cvta.to.shared.u64 t, %1; cvt.u32.u64 %0, t; }"
      : "=r"(a) : "l"(p));
  return a;
}
__device__ __forceinline__ void ldsm_x4(unsigned r[4], uint32_t addr) {
  asm volatile("ldmatrix.sync.aligned.m8n8.x4.shared.b16 {%0,%1,%2,%3}, [%4];"
               : "=r"(r[0]), "=r"(r[1]), "=r"(r[2]), "=r"(r[3]) : "r"(addr));
}
__device__ __forceinline__ void ldsm_x2(unsigned r[2], uint32_t addr) {
  asm volatile("ldmatrix.sync.aligned.m8n8.x2.shared.b16 {%0,%1}, [%2];"
               : "=r"(r[0]), "=r"(r[1]) : "r"(addr));
}
__device__ __forceinline__ void mma_bf16(float d[4], const unsigned a[4],
                                         const unsigned b[2]) {
  asm volatile(
      "mma.sync.aligned.m16n8k16.row.col.f32.bf16.bf16.f32 "
      "{%0,%1,%2,%3}, {%4,%5,%6,%7}, {%8,%9}, {%0,%1,%2,%3};"
      : "+f"(d[0]), "+f"(d[1]), "+f"(d[2]), "+f"(d[3])
      : "r"(a[0]), "r"(a[1]), "r"(a[2]), "r"(a[3]), "r"(b[0]), "r"(b[1]));
}
__device__ __forceinline__ void bf16_split(float v, unsigned short& h,
                                           unsigned short& l) {
  __nv_bfloat16 hb = __float2bfloat16(v);
  __nv_bfloat16 lb = __float2bfloat16(v - __bfloat162float(hb));
  h = __bfloat16_as_ushort(hb);
  l = __bfloat16_as_ushort(lb);
}

// ---------------------------------------------------------------------------
// prep + weight splits
// ---------------------------------------------------------------------------
__global__ void prep_k(const float* __restrict__ f1, const float* __restrict__ f2,
                       const float* __restrict__ w1) {
  int idx = blockIdx.x * blockDim.x + threadIdx.x;
  if (idx < 2 * 32 * 6144) {
    int x = idx % 96, y = (idx / 96) % 64, c = idx / 6144;
    g_f1p[(size_t)c * PL1 + (y + 1) * 100 + x + 1] = f1[idx];
    g_f2c[(size_t)c * PLC + (y + 8) * 120 + x + 8] = f2[idx];
  }
  if (idx < 96 * 64 * 9) {
    int co = idx / 576, rem = idx % 576, ci = rem / 9, k = rem % 9;
    if (ci < 32) g_w1a[(co * 32 + ci) * 9 + k] = w1[idx];
    else         g_w1b[(co * 32 + (ci - 32)) * 9 + k] = w1[idx];
  }
}
__global__ void wprep2_k(const float* __restrict__ w2) {
  int idx = blockIdx.x * blockDim.x + threadIdx.x;
  if (idx >= 9 * 128 * 96) return;
  int ci = idx % 96, co = (idx / 96) % 128, tap = idx / 12288;
  bf16_split(w2[(co * 96 + ci) * 9 + tap], g_B2h[idx], g_B2l[idx]);
}
__global__ void wprep3_k(const float* __restrict__ w3) {
  int idx = blockIdx.x * blockDim.x + threadIdx.x;
  if (idx >= 9 * 128 * 128) return;
  int ci = idx & 127, co = (idx >> 7) & 127, tap = idx >> 14;
  bf16_split(w3[(co * 128 + ci) * 9 + tap], g_B3h[idx], g_B3l[idx]);
}
__global__ void wprep4_k(const float* __restrict__ w4) {
  int idx = blockIdx.x * blockDim.x + threadIdx.x;
  if (idx >= 9 * 64 * 128) return;
  int ci = idx & 127, co = (idx >> 7) & 63, tap = idx >> 13;
  bf16_split(w4[(co * 128 + ci) * 9 + tap], g_B4h[idx], g_B4l[idx]);
}
// w5[ci][co][3-(a+2s)][3-(b+2t)] -> [par][tap][co][ci]
__global__ void wprep5_k(const float* __restrict__ w5) {
  int idx = blockIdx.x * blockDim.x + threadIdx.x;
  if (idx >= 4 * 4 * 32 * 64) return;
  int ci  = idx & 63;
  int co  = (idx >> 6) & 31;
  int tap = (idx >> 11) & 3;
  int par = idx >> 13;
  int a = par >> 1, b = par & 1;
  int s = tap >> 1, t = tap & 1;
  float v = w5[(((size_t)ci * 32 + co) * 4 + (3 - (a + 2 * s))) * 4 +
               (3 - (b + 2 * t))];
  bf16_split(v, g_B5h[idx], g_B5l[idx]);
}

// ---------------------------------------------------------------------------
// 3x3 s1 conv (scalar, conv1 factorization)
// ---------------------------------------------------------------------------
template <int TW, int H, int W, int WP>
__global__ void __launch_bounds__(8 * TW)
conv3x3_s1_k(const float* __restrict__ in, const float* __restrict__ w,
             float* __restrict__ out, int Cin, int Cout) {
  constexpr int PXG = TW / 4;
  constexpr int NT  = 8 * TW;
  constexpr int RS  = 37;
  constexpr int PLS = 10 * RS;
  constexpr int F4  = (TW + 4) / 4;
  constexpr int PLANE = (H + 2) * WP;

  __shared__ float s_in[8 * PLS];
  __shared__ __align__(16) float s_w[8 * 9 * 16];

  const int tid = threadIdx.x;
  const int cg  = tid / (8 * PXG);
  const int pid = tid % (8 * PXG);
  const int py  = pid / PXG;
  const int pxg = pid % PXG;

  const int tilesX = W / TW;
  const int tx = blockIdx.x % tilesX;
  const int ty = blockIdx.x / tilesX;
  const int n  = blockIdx.z;
  const int coB = blockIdx.y * 16;
  const int y0 = ty * 8, x0 = tx * TW;

  const float* inN = in + (size_t)n * Cin * PLANE;

  float acc[4][4];
#pragma unroll
  for (int q = 0; q < 4; q++)
#pragma unroll
    for (int p = 0; p < 4; p++) acc[q][p] = 0.f;

  for (int cb = 0; cb < Cin; cb += 8) {
    __syncthreads();
#pragma unroll
    for (int t = tid; t < 8 * 10 * F4; t += NT) {
      int c   = t / (10 * F4);
      int rem = t - c * (10 * F4);
      int r   = rem / F4;
      int q   = rem - r * F4;
      const float4 v = *reinterpret_cast<const float4*>(
          inN + (size_t)(cb + c) * PLANE + (y0 + r) * WP + x0 + 4 * q);
      float* dst = &s_in[c * PLS + r * RS + 4 * q];
      dst[0] = v.x; dst[1] = v.y; dst[2] = v.z; dst[3] = v.w;
    }
    for (int t = tid; t < 16 * 8 * 9; t += NT) {
      int lco = t & 15;
      int rem = t >> 4;
      int k   = rem % 9;
      int lci = rem / 9;
      s_w[(lci * 9 + k) * 16 + lco] =
          w[((size_t)(coB + lco) * Cin + (cb + lci)) * 9 + k];
    }
    __syncthreads();

#pragma unroll
    for (int ci = 0; ci < 8; ci++) {
#pragma unroll
      for (int ky = 0; ky < 3; ky++) {
        float r[6];
#pragma unroll
        for (int j = 0; j < 6; j++)
          r[j] = s_in[ci * PLS + (py + ky) * RS + pxg * 4 + j];
#pragma unroll
        for (int kx = 0; kx < 3; kx++) {
          float4 wv =
              reinterpret_cast<const float4*>(s_w)[(ci * 9 + ky * 3 + kx) * 4 + cg];
#pragma unroll
          for (int p = 0; p < 4; p++) {
            float iv = r[p + kx];
            acc[0][p] += wv.x * iv;
            acc[1][p] += wv.y * iv;
            acc[2][p] += wv.z * iv;
            acc[3][p] += wv.w * iv;
          }
        }
      }
    }
  }

  float* outN = out + (size_t)n * Cout * PLANE;
  const int gy = y0 + py + 1;
#pragma unroll
  for (int q = 0; q < 4; q++) {
    int co = coB + cg * 4 + q;
#pragma unroll
    for (int p = 0; p < 4; p++)
      outN[(size_t)co * PLANE + gy * WP + x0 + pxg * 4 + p + 1] = acc[q][p];
  }
}

// ---------------------------------------------------------------------------
// V = conv3x3(zero-padded f2) on extended 72x112 grid
// ---------------------------------------------------------------------------
__global__ void __launch_bounds__(128)
conv_v_k(const float* __restrict__ in, const float* __restrict__ w,
         float* __restrict__ out) {
  constexpr int RS = 37, PLS = 10 * RS;
  __shared__ float s_in[8 * PLS];
  __shared__ __align__(16) float s_w[8 * 9 * 16];

  const int tid = threadIdx.x;
  const int cg  = tid >> 5;
  const int pid = tid & 31;
  const int py  = pid >> 2;
  const int pxg = pid & 3;

  const int tx = blockIdx.x % 7;
  const int ty = blockIdx.x / 7;
  const int n  = blockIdx.z;
  const int coB = blockIdx.y * 16;
  const int y0 = ty * 8, x0 = tx * 16;

  const float* inN = in + (size_t)n * 32 * PLC;

  float acc[4][4];
#pragma unroll
  for (int q = 0; q < 4; q++)
#pragma unroll
    for (int p = 0; p < 4; p++) acc[q][p] = 0.f;

  for (int cb = 0; cb < 32; cb += 8) {
    __syncthreads();
#pragma unroll
    for (int t = tid; t < 8 * 10 * 5; t += 128) {
      int c   = t / 50;
      int rem = t - c * 50;
      int r   = rem / 5;
      int q   = rem - r * 5;
      const float4 v = *reinterpret_cast<const float4*>(
          inN + (size_t)(cb + c) * PLC + (y0 + r + 4) * 120 + x0 + 4 * q + 4);
      float* dst = &s_in[c * PLS + r * RS + 4 * q];
      dst[0] = v.x; dst[1] = v.y; dst[2] = v.z; dst[3] = v.w;
    }
    for (int t = tid; t < 16 * 8 * 9; t += 128) {
      int lco = t & 15;
      int rem = t >> 4;
      int k   = rem % 9;
      int lci = rem / 9;
      s_w[(lci * 9 + k) * 16 + lco] =
          w[((coB + lco) * 32 + cb + lci) * 9 + k];
    }
    __syncthreads();

#pragma unroll
    for (int ci = 0; ci < 8; ci++) {
#pragma unroll
      for (int ky = 0; ky < 3; ky++) {
        float r[6];
#pragma unroll
        for (int j = 0; j < 6; j++)
          r[j] = s_in[ci * PLS + (py + ky) * RS + pxg * 4 + j];
#pragma unroll
        for (int kx = 0; kx < 3; kx++) {
          float4 wv =
              reinterpret_cast<const float4*>(s_w)[(ci * 9 + ky * 3 + kx) * 4 + cg];
#pragma unroll
          for (int p = 0; p < 4; p++) {
            float iv = r[p + kx];
            acc[0][p] += wv.x * iv;
            acc[1][p] += wv.y * iv;
            acc[2][p] += wv.z * iv;
            acc[3][p] += wv.w * iv;
          }
        }
      }
    }
  }

  float* outN = out + (size_t)n * 96 * PLV;
  const int gy = y0 + py;
#pragma unroll
  for (int q = 0; q < 4; q++) {
    int co = coB + cg * 4 + q;
#pragma unroll
    for (int p = 0; p < 4; p++)
      outN[(size_t)co * PLV + gy * 112 + x0 + pxg * 4 + p] = acc[q][p];
  }
}

// ---------------------------------------------------------------------------
// combine: x1 = U + shift(V) on ALL pixels; border corrected by stripdelta_k
// ---------------------------------------------------------------------------
__global__ void __launch_bounds__(256) combine_k() {
  const int bid = blockIdx.x;
  const int co = bid % 96, n = bid / 96;
  const int b = n / 49, d = n % 49;
  const int di = d / 7 - 3, dj = d % 7 - 3;

  const float* U = g_U + ((size_t)(b * 96 + co)) * PL1;
  const float* V = g_V + ((size_t)(b * 96 + co)) * PLV + (dj + 3) * 112 + (di + 3);
  float* X = g_x1 + ((size_t)(n * 96 + co)) * PL1;

  const int y0 = threadIdx.x >> 5, xl = threadIdx.x & 31;
  for (int y = y0; y < 64; y += 8) {
    const int ro = (y + 1) * 100 + 1;
    const int rv = y * 112;
#pragma unroll
    for (int x = xl; x < 96; x += 32)
      X[ro + x] = U[ro + x] + V[rv + x];
  }
}

// ---------------------------------------------------------------------------
// stripdelta: subtract BOTH border corrections from x1 on the 4-px frame:
//   f1 half (ci<32):  conv(f1 on taps in-image AND outside mask)   [mask err]
//   f2 half (ci>=32): conv(f2[tap+shift] on taps OUTSIDE image with
//                     shifted tap inside f2)                        [pad err]
// ---------------------------------------------------------------------------
__global__ void __launch_bounds__(128)
stripdelta_k(const float* __restrict__ f1, const float* __restrict__ f2,
             const float* __restrict__ w1) {
  const int sid = blockIdx.x;   // 0..9
  const int n   = blockIdx.y;
  const int y0 = d_segy[sid], x0 = d_segx[sid];
  const int h  = d_segh[sid], w = d_segw[sid];
  const int b = n / 49, d = n % 49;
  const int di = d / 7 - 3;
  const int dj = d % 7 - 3;

  // per-half activity
  bool af1, af2;
  {
    int rlo = y0 > 0 ? y0 - 1 : 0;
    int rhi = (y0 + h < 64) ? y0 + h : 63;
    int clo = x0 > 0 ? x0 - 1 : 0;
    int chi = (x0 + w < 96) ? x0 + w : 95;
    af1 = (dj < 0 && rlo < -dj) || (dj > 0 && rhi >= 64 - dj) ||
          (di < 0 && clo < -di) || (di > 0 && chi >= 96 - di);
    af2 = (y0 == 0 && dj > 0) || (y0 + h == 64 && dj < 0) ||
          (x0 == 0 && di > 0) || (x0 + w == 96 && di < 0);
    if (!af1 && !af2) return;
  }
  const int cbLo = af1 ? 0 : 32;
  const int cbHi = af2 ? 64 : 32;

  const int H2 = h + 2, W2 = w + 2;

  __shared__ float s_in[8 * 204];                  // max H2*W2 = 6*34 = 204
  __shared__ __align__(16) float s_w[8 * 9 * 32];

  const int tid = threadIdx.x;
  const bool pact = tid < h * w;
  const int py = pact ? tid / w : 0;
  const int px = pact ? tid % w : 0;

  const float* f1b = f1 + (size_t)b * 32 * 6144;
  const float* f2b = f2 + (size_t)b * 32 * 6144;

  for (int coc = 0; coc < 3; coc++) {
    float acc[32];
#pragma unroll
    for (int c = 0; c < 32; c++) acc[c] = 0.f;

    for (int cb = cbLo; cb < cbHi; cb += 8) {
      __syncthreads();
      for (int t = tid; t < 8 * H2 * W2; t += 128) {
        int ci  = t / (H2 * W2);
        int rem = t - ci * (H2 * W2);
        int r   = rem / W2;
        int c   = rem - r * W2;
        int yy = y0 - 1 + r, xx = x0 - 1 + c;
        int cic = cb + ci;
        float v = 0.f;
        bool inimg  = (unsigned)yy < 64u && (unsigned)xx < 96u;
        if (cic < 32) {
          bool inmask = (unsigned)(yy + dj) < 64u && (unsigned)(xx + di) < 96u;
          if (inimg && !inmask)
            v = f1b[cic * 6144 + yy * 96 + xx];
        } else {
          int sy = yy + dj, sx = xx + di;
          if (!inimg && (unsigned)sy < 64u && (unsigned)sx < 96u)
            v = f2b[(cic - 32) * 6144 + sy * 96 + sx];
        }
        s_in[ci * 204 + r * W2 + c] = v;
      }
      for (int t = tid; t < 32 * 8 * 9; t += 128) {
        int co  = t & 31;
        int rem = t >> 5;
        int k   = rem % 9;
        int ci  = rem / 9;
        s_w[(ci * 9 + k) * 32 + co] =
            w1[((coc * 32 + co) * 64 + cb + ci) * 9 + k];
      }
      __syncthreads();

      if (pact) {
#pragma unroll
        for (int ci = 0; ci < 8; ci++)
#pragma unroll
          for (int ky = 0; ky < 3; ky++)
#pragma unroll
            for (int kx = 0; kx < 3; kx++) {
              float v = s_in[ci * 204 + (py + ky) * W2 + (px + kx)];
              const float4* wv = reinterpret_cast<const float4*>(
                  &s_w[(ci * 9 + ky * 3 + kx) * 32]);
#pragma unroll
              for (int q = 0; q < 8; q++) {
                float4 ww = wv[q];
                acc[4 * q + 0] += ww.x * v;
                acc[4 * q + 1] += ww.y * v;
                acc[4 * q + 2] += ww.z * v;
                acc[4 * q + 3] += ww.w * v;
              }
            }
      }
    }
    if (pact) {
#pragma unroll
      for (int c = 0; c < 32; c++)
        g_x1[((size_t)n * 96 + coc * 32 + c) * PL1 +
             (y0 + py + 1) * 100 + (x0 + px + 1)] -= acc[c];
    }
    __syncthreads();
  }
}

// ---------------------------------------------------------------------------
// stats over planar padded plane (one block per (n,c) plane of g_x1)
// ---------------------------------------------------------------------------
__global__ void __launch_bounds__(256)
stats1_k() {
  const float* p = g_x1 + (size_t)blockIdx.x * PL1;
  const int wid = threadIdx.x >> 5, ln = threadIdx.x & 31;

  float s = 0.f, q = 0.f;
  for (int y = wid; y < 64; y += 8)
    for (int xx = ln; xx < 96; xx += 32) {
      float v = p[(y + 1) * 100 + xx + 1];
      s += v; q += v * v;
    }
#pragma unroll
  for (int o = 16; o > 0; o >>= 1) {
    s += __shfl_xor_sync(0xffffffffu, s, o);
    q += __shfl_xor_sync(0xffffffffu, q, o);
  }
  __shared__ float ss[8], sq[8];
  if (ln == 0) { ss[wid] = s; sq[wid] = q; }
  __syncthreads();
  if (threadIdx.x == 0) {
    float S = 0.f, Q = 0.f;
#pragma unroll
    for (int i = 0; i < 8; i++) { S += ss[i]; Q += sq[i]; }
    float m = S / 6144.f;
    float var = Q / 6144.f - m * m;
    g_stm[blockIdx.x] = m;                  // index = n*96 + c
    g_sti[blockIdx.x] = rsqrtf(var + 1e-5f);
  }
}

// ---------------------------------------------------------------------------
// apply norm+leaky to planar x1, transpose to ch-last, split bf16 hi/lo
// ---------------------------------------------------------------------------
__global__ void __launch_bounds__(256)
apply_x1cl_k() {
  __shared__ float s[96 * 97];
  const int y = blockIdx.x;   // 0..63
  const int n = blockIdx.y;
  const int tid = threadIdx.x;
  const int wid = tid >> 5, ln = tid & 31;

  for (int ci = wid; ci < 96; ci += 8) {
    const float* src = g_x1 + ((size_t)(n * 96 + ci)) * PL1 + (y + 1) * 100 + 1;
    for (int x = ln; x < 96; x += 32) s[x * 97 + ci] = src[x];
  }
  __syncthreads();
  for (int idx = tid; idx < 96 * 96; idx += 256) {
    int x = idx / 96, ci = idx % 96;
    float m = g_stm[n * 96 + ci], iv = g_sti[n * 96 + ci];
    float v = (s[x * 97 + ci] - m) * iv;
    v = v >= 0.f ? v : 0.01f * v;
    size_t o = ((size_t)(n * 6600 + (y + 1) * 100 + (x + 1))) * 96 + ci;
    bf16_split(v, g_X1h[o], g_X1l[o]);
  }
}

// ---------------------------------------------------------------------------
// stats over channel-last fp32 [n][NPX][C]
// ---------------------------------------------------------------------------
template <int C, int NPX>
__global__ void __launch_bounds__(512)
stats_cl_k(const float* __restrict__ xcl) {
  constexpr int SL = 512 / C;
  constexpr int PXS = NPX / SL;
  __shared__ float sm[512], sq[512];
  const int n = blockIdx.x;
  const int tid = threadIdx.x;
  const int ci = tid % C, sl = tid / C;

  const float* base = xcl + (size_t)n * NPX * C + ci;
  float s = 0.f, q = 0.f;
  for (int i = 0; i < PXS; i++) {
    float v = base[(size_t)(sl * PXS + i) * C];
    s += v; q += v * v;
  }
  sm[tid] = s; sq[tid] = q;
  __syncthreads();
  if (tid < C) {
    float S = 0.f, Q = 0.f;
#pragma unroll
    for (int j = 0; j < SL; j++) { S += sm[ci + j * C]; Q += sq[ci + j * C]; }
    float m = S / (float)NPX;
    float var = Q / (float)NPX - m * m;
    g_stm[n * 128 + ci] = m;
    g_sti[n * 128 + ci] = rsqrtf(var + 1e-5f);
  }
}

// ---------------------------------------------------------------------------
// apply norm+leaky (C=128) -> bf16 hi/lo padded ch-last (g_Xh/g_Xl)
// ---------------------------------------------------------------------------
__global__ void __launch_bounds__(256)
apply_cl128_k(const float* __restrict__ xcl) {
  const int y = blockIdx.x;   // 0..31
  const int n = blockIdx.y;
  const int tid = threadIdx.x;
  for (int idx = tid; idx < 48 * 128; idx += 256) {
    int x = idx >> 7, ci = idx & 127;
    float m = g_stm[n * 128 + ci], iv = g_sti[n * 128 + ci];
    float v = (xcl[((size_t)(n * 1536 + y * 48 + x)) * 128 + ci] - m) * iv;
    v = v >= 0.f ? v : 0.01f * v;
    size_t o = ((size_t)(n * 1768 + (y + 1) * 52 + (x + 1))) * 128 + ci;
    bf16_split(v, g_Xh[o], g_Xl[o]);
  }
}

// ---------------------------------------------------------------------------
// apply norm+leaky (C=64) -> bf16 hi/lo padded ch-last (g_X4h/g_X4l)
// ---------------------------------------------------------------------------
__global__ void __launch_bounds__(256)
apply_cl64_k(const float* __restrict__ xcl) {
  const int y = blockIdx.x;   // 0..31
  const int n = blockIdx.y;
  const int tid = threadIdx.x;
  for (int idx = tid; idx < 48 * 64; idx += 256) {
    int x = idx >> 6, ci = idx & 63;
    float m = g_stm[n * 128 + ci], iv = g_sti[n * 128 + ci];
    float v = (xcl[((size_t)(n * 1536 + y * 48 + x)) * 64 + ci] - m) * iv;
    v = v >= 0.f ? v : 0.01f * v;
    size_t o = ((size_t)(n * 1768 + (y + 1) * 52 + (x + 1))) * 64 + ci;
    bf16_split(v, g_X4h[o], g_X4l[o]);
  }
}

// ---------------------------------------------------------------------------
// apply norm+leaky to x5cl [n][par][1536][32] -> planar padded g_x5
// ---------------------------------------------------------------------------
__global__ void __launch_bounds__(256)
apply_x5_planar_k() {
  const int yq = blockIdx.x;  // 0..31 (y')
  const int n  = blockIdx.y;
  const int tid = threadIdx.x;
  float* outN = g_x5 + (size_t)n * 32 * PL1;

  for (int par = 0; par < 4; par++) {
    const int a = par >> 1, b = par & 1;
    const float* src = g_x5cl + ((size_t)(n * 4 + par) * 1536 + yq * 48) * 32;
    const int oy = 2 * yq + a + 1;
    for (int idx = tid; idx < 48 * 32; idx += 256) {
      int x = idx >> 5, co = idx & 31;
      float m = g_stm[n * 128 + co], iv = g_sti[n * 128 + co];
      float v = (src[x * 32 + co] - m) * iv;
      v = v >= 0.f ? v : 0.01f * v;
      outN[(size_t)co * PL1 + oy * 100 + 2 * x + b + 1] = v;
    }
  }
}

// ---------------------------------------------------------------------------
// gemm2: conv2 (stride 2), M-tile 96, N=128, Cin=96
// ---------------------------------------------------------------------------
__global__ void __launch_bounds__(256)
gemm2_k(float* __restrict__ xcl) {
  __shared__ unsigned short sA[2][96 * 40];
  __shared__ unsigned short sB[2][128 * 40];

  const int tid  = threadIdx.x;
  const int wid  = tid >> 5, lane = tid & 31;
  const int warp_m = wid & 1;
  const int warp_n = wid >> 1;
  const int tile = blockIdx.x;
  const int n    = blockIdx.y;
  const int px0  = tile * 96;

  const uint32_t aB = smem_u32(sA);
  const uint32_t bB = smem_u32(sB);

  float acc[3][4][4];
#pragma unroll
  for (int mi = 0; mi < 3; mi++)
#pragma unroll
    for (int ni = 0; ni < 4; ni++)
#pragma unroll
      for (int j = 0; j < 4; j++) acc[mi][ni][j] = 0.f;

  for (int tap = 0; tap < 9; tap++) {
    const int dy = tap / 3, dx = tap % 3;
    for (int cc = 0; cc < 3; cc++) {
      const int ci0 = cc * 32;
      __syncthreads();
#pragma unroll
      for (int i = 0; i < 3; i++) {
        int id  = tid + i * 256;
        int buf = id / 384;
        int rem = id - buf * 384;
        int r   = rem >> 2, q = rem & 3;
        int px = px0 + r;
        int y = px / 48, x = px - y * 48;
        int pos = (2 * y + dy) * 100 + (2 * x + dx);
        const uint4* src = reinterpret_cast<const uint4*>(
            (buf ? g_X1l : g_X1h) + ((size_t)(n * 6600 + pos)) * 96 + ci0);
        *reinterpret_cast<uint4*>(&sA[buf][r * 40 + q * 8]) = src[q];
      }
#pragma unroll
      for (int i = 0; i < 4; i++) {
        int id  = tid + i * 256;
        int buf = id >> 9;
        int rem = id & 511;
        int r   = rem >> 2, q = rem & 3;
        const uint4* src = reinterpret_cast<const uint4*>(
            (buf ? g_B2l : g_B2h) + ((size_t)(tap * 128 + r)) * 96 + ci0);
        *reinterpret_cast<uint4*>(&sB[buf][r * 40 + q * 8]) = src[q];
      }
      __syncthreads();

#pragma unroll
      for (int ks = 0; ks < 2; ks++) {
        unsigned ah[3][4], al[3][4], bh[4][2], bl[4][2];
        const int arow = warp_m * 48 + (lane & 7) + ((lane >> 3) & 1) * 8;
        const int acol = ks * 16 + ((lane >> 4) & 1) * 8;
#pragma unroll
        for (int mi = 0; mi < 3; mi++) {
          uint32_t off = (uint32_t)(((arow + mi * 16) * 40 + acol) * 2);
          ldsm_x4(ah[mi], aB + off);
          ldsm_x4(al[mi], aB + 96 * 40 * 2 + off);
        }
        const int brow = warp_n * 32 + (lane & 7);
        const int bcol = ks * 16 + ((lane >> 3) & 1) * 8;
#pragma unroll
        for (int ni = 0; ni < 4; ni++) {
          uint32_t off = (uint32_t)(((brow + ni * 8) * 40 + bcol) * 2);
          ldsm_x2(bh[ni], bB + off);
          ldsm_x2(bl[ni], bB + 128 * 40 * 2 + off);
        }
#pragma unroll
        for (int mi = 0; mi < 3; mi++)
#pragma unroll
          for (int ni = 0; ni < 4; ni++) {
            mma_bf16(acc[mi][ni], ah[mi], bh[ni]);
            mma_bf16(acc[mi][ni], ah[mi], bl[ni]);
            mma_bf16(acc[mi][ni], al[mi], bh[ni]);
          }
      }
    }
  }

  const int g = lane >> 2, tg = lane & 3;
#pragma unroll
  for (int mi = 0; mi < 3; mi++)
#pragma unroll
    for (int ni = 0; ni < 4; ni++) {
      int row = px0 + warp_m * 48 + mi * 16 + g;
      int co  = warp_n * 32 + ni * 8 + tg * 2;
      float* d0 = xcl + ((size_t)(n * 1536 + row)) * 128 + co;
      float* d1 = xcl + ((size_t)(n * 1536 + row + 8)) * 128 + co;
      *reinterpret_cast<float2*>(d0) = make_float2(acc[mi][ni][0], acc[mi][ni][1]);
      *reinterpret_cast<float2*>(d1) = make_float2(acc[mi][ni][2], acc[mi][ni][3]);
    }
}

// ---------------------------------------------------------------------------
// gemm3: conv3, N=128, Cin=128 (A = g_Xh/g_Xl)
// ---------------------------------------------------------------------------
__global__ void __launch_bounds__(256)
gemm3_k(float* __restrict__ xcl) {
  __shared__ unsigned short sA[2][96 * 40];
  __shared__ unsigned short sB[2][128 * 40];

  const int tid  = threadIdx.x;
  const int wid  = tid >> 5, lane = tid & 31;
  const int warp_m = wid & 1;
  const int warp_n = wid >> 1;
  const int tile = blockIdx.x;
  const int n    = blockIdx.y;
  const int px0  = tile * 96;

  const uint32_t aB = smem_u32(sA);
  const uint32_t bB = smem_u32(sB);

  float acc[3][4][4];
#pragma unroll
  for (int mi = 0; mi < 3; mi++)
#pragma unroll
    for (int ni = 0; ni < 4; ni++)
#pragma unroll
      for (int j = 0; j < 4; j++) acc[mi][ni][j] = 0.f;

  for (int tap = 0; tap < 9; tap++) {
    const int dy = tap / 3, dx = tap % 3;
    for (int cc = 0; cc < 4; cc++) {
      const int ci0 = cc * 32;
      __syncthreads();
#pragma unroll
      for (int i = 0; i < 3; i++) {
        int id  = tid + i * 256;
        int buf = id / 384;
        int rem = id - buf * 384;
        int r   = rem >> 2, q = rem & 3;
        int px = px0 + r;
        int y = px / 48, x = px - y * 48;
        int pos = (y + dy) * 52 + (x + dx);
        const uint4* src = reinterpret_cast<const uint4*>(
            (buf ? g_Xl : g_Xh) + ((size_t)(n * 1768 + pos)) * 128 + ci0);
        *reinterpret_cast<uint4*>(&sA[buf][r * 40 + q * 8]) = src[q];
      }
#pragma unroll
      for (int i = 0; i < 4; i++) {
        int id  = tid + i * 256;
        int buf = id >> 9;
        int rem = id & 511;
        int r   = rem >> 2, q = rem & 3;
        const uint4* src = reinterpret_cast<const uint4*>(
            (buf ? g_B3l : g_B3h) + ((size_t)(tap * 128 + r)) * 128 + ci0);
        *reinterpret_cast<uint4*>(&sB[buf][r * 40 + q * 8]) = src[q];
      }
      __syncthreads();

#pragma unroll
      for (int ks = 0; ks < 2; ks++) {
        unsigned ah[3][4], al[3][4], bh[4][2], bl[4][2];
        const int arow = warp_m * 48 + (lane & 7) + ((lane >> 3) & 1) * 8;
        const int acol = ks * 16 + ((lane >> 4) & 1) * 8;
#pragma unroll
        for (int mi = 0; mi < 3; mi++) {
          uint32_t off = (uint32_t)(((arow + mi * 16) * 40 + acol) * 2);
          ldsm_x4(ah[mi], aB + off);
          ldsm_x4(al[mi], aB + 96 * 40 * 2 + off);
        }
        const int brow = warp_n * 32 + (lane & 7);
        const int bcol = ks * 16 + ((lane >> 3) & 1) * 8;
#pragma unroll
        for (int ni = 0; ni < 4; ni++) {
          uint32_t off = (uint32_t)(((brow + ni * 8) * 40 + bcol) * 2);
          ldsm_x2(bh[ni], bB + off);
          ldsm_x2(bl[ni], bB + 128 * 40 * 2 + off);
        }
#pragma unroll
        for (int mi = 0; mi < 3; mi++)
#pragma unroll
          for (int ni = 0; ni < 4; ni++) {
            mma_bf16(acc[mi][ni], ah[mi], bh[ni]);
            mma_bf16(acc[mi][ni], ah[mi], bl[ni]);
            mma_bf16(acc[mi][ni], al[mi], bh[ni]);
          }
      }
    }
  }

  const int g = lane >> 2, tg = lane & 3;
#pragma unroll
  for (int mi = 0; mi < 3; mi++)
#pragma unroll
    for (int ni = 0; ni < 4; ni++) {
      int row = px0 + warp_m * 48 + mi * 16 + g;
      int co  = warp_n * 32 + ni * 8 + tg * 2;
      float* d0 = xcl + ((size_t)(n * 1536 + row)) * 128 + co;
      float* d1 = xcl + ((size_t)(n * 1536 + row + 8)) * 128 + co;
      *reinterpret_cast<float2*>(d0) = make_float2(acc[mi][ni][0], acc[mi][ni][1]);
      *reinterpret_cast<float2*>(d1) = make_float2(acc[mi][ni][2], acc[mi][ni][3]);
    }
}

// ---------------------------------------------------------------------------
// gemm4: conv4, N=64, Cin=128 (A = g_Xh/g_Xl)
// ---------------------------------------------------------------------------
__global__ void __launch_bounds__(256)
gemm4_k(float* __restrict__ xcl) {
  __shared__ unsigned short sA[2][96 * 40];
  __shared__ unsigned short sB[2][64 * 40];

  const int tid  = threadIdx.x;
  const int wid  = tid >> 5, lane = tid & 31;
  const int warp_m = wid & 1;
  const int warp_n = wid >> 1;
  const int tile = blockIdx.x;
  const int n    = blockIdx.y;
  const int px0  = tile * 96;

  const uint32_t aB = smem_u32(sA);
  const uint32_t bB = smem_u32(sB);

  float acc[3][2][4];
#pragma unroll
  for (int mi = 0; mi < 3; mi++)
#pragma unroll
    for (int ni = 0; ni < 2; ni++)
#pragma unroll
      for (int j = 0; j < 4; j++) acc[mi][ni][j] = 0.f;

  for (int tap = 0; tap < 9; tap++) {
    const int dy = tap / 3, dx = tap % 3;
    for (int cc = 0; cc < 4; cc++) {
      const int ci0 = cc * 32;
      __syncthreads();
#pragma unroll
      for (int i = 0; i < 3; i++) {
        int id  = tid + i * 256;
        int buf = id / 384;
        int rem = id - buf * 384;
        int r   = rem >> 2, q = rem & 3;
        int px = px0 + r;
        int y = px / 48, x = px - y * 48;
        int pos = (y + dy) * 52 + (x + dx);
        const uint4* src = reinterpret_cast<const uint4*>(
            (buf ? g_Xl : g_Xh) + ((size_t)(n * 1768 + pos)) * 128 + ci0);
        *reinterpret_cast<uint4*>(&sA[buf][r * 40 + q * 8]) = src[q];
      }
#pragma unroll
      for (int i = 0; i < 2; i++) {
        int id  = tid + i * 256;
        int buf = id >> 8;
        int rem = id & 255;
        int r   = rem >> 2, q = rem & 3;
        const uint4* src = reinterpret_cast<const uint4*>(
            (buf ? g_B4l : g_B4h) + ((size_t)(tap * 64 + r)) * 128 + ci0);
        *reinterpret_cast<uint4*>(&sB[buf][r * 40 + q * 8]) = src[q];
      }
      __syncthreads();

#pragma unroll
      for (int ks = 0; ks < 2; ks++) {
        unsigned ah[3][4], al[3][4], bh[2][2], bl[2][2];
        const int arow = warp_m * 48 + (lane & 7) + ((lane >> 3) & 1) * 8;
        const int acol = ks * 16 + ((lane >> 4) & 1) * 8;
#pragma unroll
        for (int mi = 0; mi < 3; mi++) {
          uint32_t off = (uint32_t)(((arow + mi * 16) * 40 + acol) * 2);
          ldsm_x4(ah[mi], aB + off);
          ldsm_x4(al[mi], aB + 96 * 40 * 2 + off);
        }
        const int brow = warp_n * 16 + (lane & 7);
        const int bcol = ks * 16 + ((lane >> 3) & 1) * 8;
#pragma unroll
        for (int ni = 0; ni < 2; ni++) {
          uint32_t off = (uint32_t)(((brow + ni * 8) * 40 + bcol) * 2);
          ldsm_x2(bh[ni], bB + off);
          ldsm_x2(bl[ni], bB + 64 * 40 * 2 + off);
        }
#pragma unroll
        for (int mi = 0; mi < 3; mi++)
#pragma unroll
          for (int ni = 0; ni < 2; ni++) {
            mma_bf16(acc[mi][ni], ah[mi], bh[ni]);
            mma_bf16(acc[mi][ni], ah[mi], bl[ni]);
            mma_bf16(acc[mi][ni], al[mi], bh[ni]);
          }
      }
    }
  }

  const int g = lane >> 2, tg = lane & 3;
#pragma unroll
  for (int mi = 0; mi < 3; mi++)
#pragma unroll
    for (int ni = 0; ni < 2; ni++) {
      int row = px0 + warp_m * 48 + mi * 16 + g;
      int co  = warp_n * 16 + ni * 8 + tg * 2;
      float* d0 = xcl + ((size_t)(n * 1536 + row)) * 64 + co;
      float* d1 = xcl + ((size_t)(n * 1536 + row + 8)) * 64 + co;
      *reinterpret_cast<float2*>(d0) = make_float2(acc[mi][ni][0], acc[mi][ni][1]);
      *reinterpret_cast<float2*>(d1) = make_float2(acc[mi][ni][2], acc[mi][ni][3]);
    }
}

// ---------------------------------------------------------------------------
// gemm5: deconv as GEMM per parity. M-tile 128, N=32, K=4 taps x 64 ci.
// ---------------------------------------------------------------------------
__global__ void __launch_bounds__(256)
gemm5_k() {
  __shared__ unsigned short sA[2][128 * 40];
  __shared__ unsigned short sB[2][32 * 40];

  const int tid  = threadIdx.x;
  const int wid  = tid >> 5, lane = tid & 31;   // warp_m = wid (0..7)
  const int tile = blockIdx.x;                  // 0..11
  const int par  = blockIdx.y;                  // 0..3
  const int n    = blockIdx.z;
  const int a = par >> 1, b = par & 1;
  const int px0 = tile * 128;

  const uint32_t aB = smem_u32(sA);
  const uint32_t bB = smem_u32(sB);

  float acc[4][4];
#pragma unroll
  for (int ni = 0; ni < 4; ni++)
#pragma unroll
    for (int j = 0; j < 4; j++) acc[ni][j] = 0.f;

  for (int tap = 0; tap < 4; tap++) {
    const int s = tap >> 1, t = tap & 1;
    for (int cc = 0; cc < 2; cc++) {
      const int ci0 = cc * 32;
      __syncthreads();
#pragma unroll
      for (int i = 0; i < 4; i++) {
        int id  = tid + i * 256;
        int buf = id >> 9;
        int rem = id & 511;
        int r   = rem >> 2, q = rem & 3;
        int px = px0 + r;
        int y = px / 48, x = px - y * 48;
        int pos = (y + a + s) * 52 + (x + b + t);
        const uint4* src = reinterpret_cast<const uint4*>(
            (buf ? g_X4l : g_X4h) + ((size_t)(n * 1768 + pos)) * 64 + ci0);
        *reinterpret_cast<uint4*>(&sA[buf][r * 40 + q * 8]) = src[q];
      }
      {
        int buf = tid >> 7;
        int rem = tid & 127;
        int r   = rem >> 2, q = rem & 3;
        const uint4* src = reinterpret_cast<const uint4*>(
            (buf ? g_B5l : g_B5h) + ((size_t)((par * 4 + tap) * 32 + r)) * 64 + ci0);
        *reinterpret_cast<uint4*>(&sB[buf][r * 40 + q * 8]) = src[q];
      }
      __syncthreads();

#pragma unroll
      for (int ks = 0; ks < 2; ks++) {
        unsigned ah[4], al[4], bh[4][2], bl[4][2];
        const int arow = wid * 16 + (lane & 7) + ((lane >> 3) & 1) * 8;
        const int acol = ks * 16 + ((lane >> 4) & 1) * 8;
        {
          uint32_t off = (uint32_t)((arow * 40 + acol) * 2);
          ldsm_x4(ah, aB + off);
          ldsm_x4(al, aB + 128 * 40 * 2 + off);
        }
        const int brow = lane & 7;
        const int bcol = ks * 16 + ((lane >> 3) & 1) * 8;
#pragma unroll
        for (int ni = 0; ni < 4; ni++) {
          uint32_t off = (uint32_t)(((brow + ni * 8) * 40 + bcol) * 2);
          ldsm_x2(bh[ni], bB + off);
          ldsm_x2(bl[ni], bB + 32 * 40 * 2 + off);
        }
#pragma unroll
        for (int ni = 0; ni < 4; ni++) {
          mma_bf16(acc[ni], ah, bh[ni]);
          mma_bf16(acc[ni], ah, bl[ni]);
          mma_bf16(acc[ni], al, bh[ni]);
        }
      }
    }
  }

  const int g = lane >> 2, tg = lane & 3;
  float* base = g_x5cl + ((size_t)(n * 4 + par)) * 1536 * 32;
#pragma unroll
  for (int ni = 0; ni < 4; ni++) {
    int row = px0 + wid * 16 + g;
    int co  = ni * 8 + tg * 2;
    *reinterpret_cast<float2*>(base + (size_t)row * 32 + co) =
        make_float2(acc[ni][0], acc[ni][1]);
    *reinterpret_cast<float2*>(base + (size_t)(row + 8) * 32 + co) =
        make_float2(acc[ni][2], acc[ni][3]);
  }
}

// ---------------------------------------------------------------------------
// final conv 32->1 + bias (planar x5 -> d_out)
// ---------------------------------------------------------------------------
__global__ void __launch_bounds__(256)
conv_final_k(const float* __restrict__ in, const float* __restrict__ w6,
             const float* __restrict__ b6, float* __restrict__ out) {
  constexpr int RS = 37, PLS = 10 * RS;
  __shared__ float s_in[8 * PLS];
  __shared__ float sw[288];
  __shared__ float sb;

  const int tid = threadIdx.x;
  const int tx = blockIdx.x % 3;
  const int ty = blockIdx.x / 3;
  const int n  = blockIdx.y;
  const int y0 = ty * 8, x0 = tx * 32;
  const int px = tid & 31, py = tid >> 5;

  for (int t = tid; t < 288; t += 256) sw[t] = w6[t];
  if (tid == 0) sb = b6[0];

  const float* inN = in + (size_t)n * 32 * PL1;
  float acc = 0.f;

  for (int cb = 0; cb < 32; cb += 8) {
    __syncthreads();
#pragma unroll
    for (int t = tid; t < 8 * 10 * 9; t += 256) {
      int c   = t / 90;
      int rem = t - c * 90;
      int r   = rem / 9;
      int q   = rem - r * 9;
      const float4 v = *reinterpret_cast<const float4*>(
          inN + (size_t)(cb + c) * PL1 + (y0 + r) * 100 + x0 + 4 * q);
      float* dst = &s_in[c * PLS + r * RS + 4 * q];
      dst[0] = v.x; dst[1] = v.y; dst[2] = v.z; dst[3] = v.w;
    }
    __syncthreads();
#pragma unroll
    for (int c = 0; c < 8; c++)
#pragma unroll
      for (int ky = 0; ky < 3; ky++)
#pragma unroll
        for (int kx = 0; kx < 3; kx++)
          acc += sw[(cb + c) * 9 + ky * 3 + kx] *
                 s_in[c * PLS + (py + ky) * RS + px + kx];
  }

  out[(size_t)n * 6144 + (y0 + py) * 96 + x0 + px] = acc + sb;
}

// ---------------------------------------------------------------------------
// Launch
// ---------------------------------------------------------------------------
extern "C" void kernel_launch(void* const* d_in, const int* in_sizes, int n_in,
                              void* d_out, int out_size) {
  const float* f1 = (const float*)d_in[0];
  const float* f2 = (const float*)d_in[1];
  const float* w1 = (const float*)d_in[2];
  const float* w2 = (const float*)d_in[3];
  const float* w3 = (const float*)d_in[4];
  const float* w4 = (const float*)d_in[5];
  const float* w5 = (const float*)d_in[6];
  const float* w6 = (const float*)d_in[7];
  const float* b6 = (const float*)d_in[8];
  float* out = (float*)d_out;

  float *x5, *f1p, *f2c, *U, *V, *w1a, *w1b, *x2cl, *x3cl, *x4cl;
  cudaGetSymbolAddress((void**)&x5, g_x5);
  cudaGetSymbolAddress((void**)&f1p, g_f1p);
  cudaGetSymbolAddress((void**)&f2c, g_f2c);
  cudaGetSymbolAddress((void**)&U, g_U);
  cudaGetSymbolAddress((void**)&V, g_V);
  cudaGetSymbolAddress((void**)&w1a, g_w1a);
  cudaGetSymbolAddress((void**)&w1b, g_w1b);
  cudaGetSymbolAddress((void**)&x2cl, g_x2cl);
  cudaGetSymbolAddress((void**)&x3cl, g_x3cl);
  cudaGetSymbolAddress((void**)&x4cl, g_x4cl);

  // prep
  prep_k<<<(2 * 32 * 6144 + 255) / 256, 256>>>(f1, f2, w1);
  wprep2_k<<<(9 * 128 * 96 + 255) / 256, 256>>>(w2);
  wprep3_k<<<(9 * 128 * 128 + 255) / 256, 256>>>(w3);
  wprep4_k<<<(9 * 64 * 128 + 255) / 256, 256>>>(w4);
  wprep5_k<<<(4 * 4 * 32 * 64 + 255) / 256, 256>>>(w5);

  // conv1 via factorization -> planar x1 (pre-norm), border via delta subtract
  conv3x3_s1_k<32, 64, 96, 100><<<dim3(24, 6, 2), 256>>>(f1p, w1a, U, 32, 96);
  conv_v_k<<<dim3(63, 6, 2), 128>>>(f2c, w1b, V);
  combine_k<<<NIMG * 96, 256>>>();
  stripdelta_k<<<dim3(10, NIMG), 128>>>(f1, f2, w1);

  // x1: fused stats -> apply+transpose+bf16 split
  stats1_k<<<NIMG * 96, 256>>>();
  apply_x1cl_k<<<dim3(64, NIMG), 256>>>();

  // conv2 GEMM; inorm -> g_Xh/g_Xl
  gemm2_k<<<dim3(16, NIMG), 256>>>(x2cl);
  stats_cl_k<128, 1536><<<NIMG, 512>>>(x2cl);
  apply_cl128_k<<<dim3(32, NIMG), 256>>>(x2cl);

  // conv3 GEMM; inorm -> g_Xh/g_Xl (overwrite)
  gemm3_k<<<dim3(16, NIMG), 256>>>(x3cl);
  stats_cl_k<128, 1536><<<NIMG, 512>>>(x3cl);
  apply_cl128_k<<<dim3(32, NIMG), 256>>>(x3cl);

  // conv4 GEMM; inorm -> g_X4h/g_X4l (ch-last bf16)
  gemm4_k<<<dim3(16, NIMG), 256>>>(x4cl);
  stats_cl_k<64, 1536><<<NIMG, 512>>>(x4cl);
  apply_cl64_k<<<dim3(32, NIMG), 256>>>(x4cl);

  // deconv GEMM (4 parities); inorm -> planar x5
  gemm5_k<<<dim3(12, 4, NIMG), 256>>>();
  {
    float* x5cl;
    cudaGetSymbolAddress((void**)&x5cl, g_x5cl);
    stats_cl_k<32, 6144><<<NIMG, 512>>>(x5cl);
  }
  apply_x5_planar_k<<<dim3(32, NIMG), 256>>>();

  // final conv
  conv_final_k<<<dim3(24, NIMG), 256>>>(x5, w6, b6, out);
}

// round 16
// speedup vs baseline: 2.8365x; 1.0822x over previous
#include <cuda_runtime.h>
#include <cuda_bf16.h>
#include <cstdint>

// ---------------------------------------------------------------------------
// Padded planar layouts [C][H+2][WP], 1-px zero halo (globals zero-init).
// ---------------------------------------------------------------------------
#define NIMG 98
#define PL1 (66 * 100)
#define PL2 (34 * 52)
#define PLV (72 * 112)
#define PLC (80 * 120)

__device__ float g_x1 [NIMG * 96 * PL1];
__device__ float g_x5 [NIMG * 32 * PL1];

// conv1 factorization scratch
__device__ float g_f1p[2 * 32 * PL1];
__device__ float g_f2c[2 * 32 * PLC];
__device__ float g_U  [2 * 96 * PL1];
__device__ float g_V  [2 * 96 * PLV];
__device__ float g_w1a[96 * 32 * 9];
__device__ float g_w1b[96 * 32 * 9];

// tensor-core path scratch (mma.sync)
__device__ unsigned short g_X1h[(size_t)NIMG * 6600 * 96];  // x1 ch-last bf16 hi
__device__ unsigned short g_X1l[(size_t)NIMG * 6600 * 96];
__device__ unsigned short g_Xh[(size_t)NIMG * 1768 * 128];  // x2 then x3 ch-last (34x52)
__device__ unsigned short g_Xl[(size_t)NIMG * 1768 * 128];
__device__ unsigned short g_X4h[(size_t)NIMG * 1768 * 64];  // x4 ch-last bf16
__device__ unsigned short g_X4l[(size_t)NIMG * 1768 * 64];
__device__ unsigned short g_B2h[9 * 128 * 96];              // w2 [tap][co][ci]
__device__ unsigned short g_B2l[9 * 128 * 96];
__device__ unsigned short g_B3h[9 * 128 * 128];
__device__ unsigned short g_B3l[9 * 128 * 128];
__device__ unsigned short g_B4h[9 * 64 * 128];
__device__ unsigned short g_B4l[9 * 64 * 128];
__device__ unsigned short g_B5h[4 * 4 * 32 * 64];           // w5 [par][tap][co][ci]
__device__ unsigned short g_B5l[4 * 4 * 32 * 64];
__device__ float g_x2cl[(size_t)NIMG * 1536 * 128];
__device__ float g_x3cl[(size_t)NIMG * 1536 * 128];
__device__ float g_x4cl[(size_t)NIMG * 1536 * 64];
__device__ float g_x5cl[(size_t)NIMG * 4 * 1536 * 32];      // [n][par][px][co]
__device__ float g_stm[NIMG * 128];
__device__ float g_sti[NIMG * 128];

// delta segment table: 10 segments, <=128 px each, covering the 4-px frame
__device__ const int d_segy[10] = {0,0,0, 60,60,60, 4,32, 4,32};
__device__ const int d_segx[10] = {0,32,64, 0,32,64, 0,0, 92,92};
__device__ const int d_segh[10] = {4,4,4, 4,4,4, 28,28, 28,28};
__device__ const int d_segw[10] = {32,32,32, 32,32,32, 4,4, 4,4};

// ---------------------------------------------------------------------------
// mma.sync + cp.async helpers
// ---------------------------------------------------------------------------
__device__ __forceinline__ uint32_t smem_u32(const void* p) {
  uint32_t a;
  asm("{ .reg .u64 t; cvta.to.shared.u64 t, %1; cvt.u32.u64 %0, t; }"
      : "=r"(a) : "l"(p));
  return a;
}
__device__ __forceinline__ void ldsm_x4(unsigned r[4], uint32_t addr) {
  asm volatile("ldmatrix.sync.aligned.m8n8.x4.shared.b16 {%0,%1,%2,%3}, [%4];"
               : "=r"(r[0]), "=r"(r[1]), "=r"(r[2]), "=r"(r[3]) : "r"(addr));
}
__device__ __forceinline__ void ldsm_x2(unsigned r[2], uint32_t addr) {
  asm volatile("ldmatrix.sync.aligned.m8n8.x2.shared.b16 {%0,%1}, [%2];"
               : "=r"(r[0]), "=r"(r[1]) : "r"(addr));
}
__device__ __forceinline__ void mma_bf16(float d[4], const unsigned a[4],
                                         const unsigned b[2]) {
  asm volatile(
      "mma.sync.aligned.m16n8k16.row.col.f32.bf16.bf16.f32 "
      "{%0,%1,%2,%3}, {%4,%5,%6,%7}, {%8,%9}, {%0,%1,%2,%3};"
      : "+f"(d[0]), "+f"(d[1]), "+f"(d[2]), "+f"(d[3])
      : "r"(a[0]), "r"(a[1]), "r"(a[2]), "r"(a[3]), "r"(b[0]), "r"(b[1]));
}
__device__ __forceinline__ void bf16_split(float v, unsigned short& h,
                                           unsigned short& l) {
  __nv_bfloat16 hb = __float2bfloat16(v);
  __nv_bfloat16 lb = __float2bfloat16(v - __bfloat162float(hb));
  h = __bfloat16_as_ushort(hb);
  l = __bfloat16_as_ushort(lb);
}
__device__ __forceinline__ void cp_async16(uint32_t smem_addr, const void* gptr) {
  asm volatile("cp.async.cg.shared.global [%0], [%1], 16;"
               :: "r"(smem_addr), "l"(gptr) : "memory");
}
#define CP_COMMIT() asm volatile("cp.async.commit_group;" ::: "memory")
#define CP_WAIT(N)  asm volatile("cp.async.wait_group %0;" :: "n"(N) : "memory")

// ---------------------------------------------------------------------------
// prep + weight splits
// ---------------------------------------------------------------------------
__global__ void prep_k(const float* __restrict__ f1, const float* __restrict__ f2,
                       const float* __restrict__ w1) {
  int idx = blockIdx.x * blockDim.x + threadIdx.x;
  if (idx < 2 * 32 * 6144) {
    int x = idx % 96, y = (idx / 96) % 64, c = idx / 6144;
    g_f1p[(size_t)c * PL1 + (y + 1) * 100 + x + 1] = f1[idx];
    g_f2c[(size_t)c * PLC + (y + 8) * 120 + x + 8] = f2[idx];
  }
  if (idx < 96 * 64 * 9) {
    int co = idx / 576, rem = idx % 576, ci = rem / 9, k = rem % 9;
    if (ci < 32) g_w1a[(co * 32 + ci) * 9 + k] = w1[idx];
    else         g_w1b[(co * 32 + (ci - 32)) * 9 + k] = w1[idx];
  }
}
__global__ void wprep2_k(const float* __restrict__ w2) {
  int idx = blockIdx.x * blockDim.x + threadIdx.x;
  if (idx >= 9 * 128 * 96) return;
  int ci = idx % 96, co = (idx / 96) % 128, tap = idx / 12288;
  bf16_split(w2[(co * 96 + ci) * 9 + tap], g_B2h[idx], g_B2l[idx]);
}
__global__ void wprep3_k(const float* __restrict__ w3) {
  int idx = blockIdx.x * blockDim.x + threadIdx.x;
  if (idx >= 9 * 128 * 128) return;
  int ci = idx & 127, co = (idx >> 7) & 127, tap = idx >> 14;
  bf16_split(w3[(co * 128 + ci) * 9 + tap], g_B3h[idx], g_B3l[idx]);
}
__global__ void wprep4_k(const float* __restrict__ w4) {
  int idx = blockIdx.x * blockDim.x + threadIdx.x;
  if (idx >= 9 * 64 * 128) return;
  int ci = idx & 127, co = (idx >> 7) & 63, tap = idx >> 13;
  bf16_split(w4[(co * 128 + ci) * 9 + tap], g_B4h[idx], g_B4l[idx]);
}
// w5[ci][co][3-(a+2s)][3-(b+2t)] -> [par][tap][co][ci]
__global__ void wprep5_k(const float* __restrict__ w5) {
  int idx = blockIdx.x * blockDim.x + threadIdx.x;
  if (idx >= 4 * 4 * 32 * 64) return;
  int ci  = idx & 63;
  int co  = (idx >> 6) & 31;
  int tap = (idx >> 11) & 3;
  int par = idx >> 13;
  int a = par >> 1, b = par & 1;
  int s = tap >> 1, t = tap & 1;
  float v = w5[(((size_t)ci * 32 + co) * 4 + (3 - (a + 2 * s))) * 4 +
               (3 - (b + 2 * t))];
  bf16_split(v, g_B5h[idx], g_B5l[idx]);
}

// ---------------------------------------------------------------------------
// 3x3 s1 conv (scalar, conv1 factorization)
// ---------------------------------------------------------------------------
template <int TW, int H, int W, int WP>
__global__ void __launch_bounds__(8 * TW)
conv3x3_s1_k(const float* __restrict__ in, const float* __restrict__ w,
             float* __restrict__ out, int Cin, int Cout) {
  constexpr int PXG = TW / 4;
  constexpr int NT  = 8 * TW;
  constexpr int RS  = 37;
  constexpr int PLS = 10 * RS;
  constexpr int F4  = (TW + 4) / 4;
  constexpr int PLANE = (H + 2) * WP;

  __shared__ float s_in[8 * PLS];
  __shared__ __align__(16) float s_w[8 * 9 * 16];

  const int tid = threadIdx.x;
  const int cg  = tid / (8 * PXG);
  const int pid = tid % (8 * PXG);
  const int py  = pid / PXG;
  const int pxg = pid % PXG;

  const int tilesX = W / TW;
  const int tx = blockIdx.x % tilesX;
  const int ty = blockIdx.x / tilesX;
  const int n  = blockIdx.z;
  const int coB = blockIdx.y * 16;
  const int y0 = ty * 8, x0 = tx * TW;

  const float* inN = in + (size_t)n * Cin * PLANE;

  float acc[4][4];
#pragma unroll
  for (int q = 0; q < 4; q++)
#pragma unroll
    for (int p = 0; p < 4; p++) acc[q][p] = 0.f;

  for (int cb = 0; cb < Cin; cb += 8) {
    __syncthreads();
#pragma unroll
    for (int t = tid; t < 8 * 10 * F4; t += NT) {
      int c   = t / (10 * F4);
      int rem = t - c * (10 * F4);
      int r   = rem / F4;
      int q   = rem - r * F4;
      const float4 v = *reinterpret_cast<const float4*>(
          inN + (size_t)(cb + c) * PLANE + (y0 + r) * WP + x0 + 4 * q);
      float* dst = &s_in[c * PLS + r * RS + 4 * q];
      dst[0] = v.x; dst[1] = v.y; dst[2] = v.z; dst[3] = v.w;
    }
    for (int t = tid; t < 16 * 8 * 9; t += NT) {
      int lco = t & 15;
      int rem = t >> 4;
      int k   = rem % 9;
      int lci = rem / 9;
      s_w[(lci * 9 + k) * 16 + lco] =
          w[((size_t)(coB + lco) * Cin + (cb + lci)) * 9 + k];
    }
    __syncthreads();

#pragma unroll
    for (int ci = 0; ci < 8; ci++) {
#pragma unroll
      for (int ky = 0; ky < 3; ky++) {
        float r[6];
#pragma unroll
        for (int j = 0; j < 6; j++)
          r[j] = s_in[ci * PLS + (py + ky) * RS + pxg * 4 + j];
#pragma unroll
        for (int kx = 0; kx < 3; kx++) {
          float4 wv =
              reinterpret_cast<const float4*>(s_w)[(ci * 9 + ky * 3 + kx) * 4 + cg];
#pragma unroll
          for (int p = 0; p < 4; p++) {
            float iv = r[p + kx];
            acc[0][p] += wv.x * iv;
            acc[1][p] += wv.y * iv;
            acc[2][p] += wv.z * iv;
            acc[3][p] += wv.w * iv;
          }
        }
      }
    }
  }

  float* outN = out + (size_t)n * Cout * PLANE;
  const int gy = y0 + py + 1;
#pragma unroll
  for (int q = 0; q < 4; q++) {
    int co = coB + cg * 4 + q;
#pragma unroll
    for (int p = 0; p < 4; p++)
      outN[(size_t)co * PLANE + gy * WP + x0 + pxg * 4 + p + 1] = acc[q][p];
  }
}

// ---------------------------------------------------------------------------
// V = conv3x3(zero-padded f2) on extended 72x112 grid
// ---------------------------------------------------------------------------
__global__ void __launch_bounds__(128)
conv_v_k(const float* __restrict__ in, const float* __restrict__ w,
         float* __restrict__ out) {
  constexpr int RS = 37, PLS = 10 * RS;
  __shared__ float s_in[8 * PLS];
  __shared__ __align__(16) float s_w[8 * 9 * 16];

  const int tid = threadIdx.x;
  const int cg  = tid >> 5;
  const int pid = tid & 31;
  const int py  = pid >> 2;
  const int pxg = pid & 3;

  const int tx = blockIdx.x % 7;
  const int ty = blockIdx.x / 7;
  const int n  = blockIdx.z;
  const int coB = blockIdx.y * 16;
  const int y0 = ty * 8, x0 = tx * 16;

  const float* inN = in + (size_t)n * 32 * PLC;

  float acc[4][4];
#pragma unroll
  for (int q = 0; q < 4; q++)
#pragma unroll
    for (int p = 0; p < 4; p++) acc[q][p] = 0.f;

  for (int cb = 0; cb < 32; cb += 8) {
    __syncthreads();
#pragma unroll
    for (int t = tid; t < 8 * 10 * 5; t += 128) {
      int c   = t / 50;
      int rem = t - c * 50;
      int r   = rem / 5;
      int q   = rem - r * 5;
      const float4 v = *reinterpret_cast<const float4*>(
          inN + (size_t)(cb + c) * PLC + (y0 + r + 4) * 120 + x0 + 4 * q + 4);
      float* dst = &s_in[c * PLS + r * RS + 4 * q];
      dst[0] = v.x; dst[1] = v.y; dst[2] = v.z; dst[3] = v.w;
    }
    for (int t = tid; t < 16 * 8 * 9; t += 128) {
      int lco = t & 15;
      int rem = t >> 4;
      int k   = rem % 9;
      int lci = rem / 9;
      s_w[(lci * 9 + k) * 16 + lco] =
          w[((coB + lco) * 32 + cb + lci) * 9 + k];
    }
    __syncthreads();

#pragma unroll
    for (int ci = 0; ci < 8; ci++) {
#pragma unroll
      for (int ky = 0; ky < 3; ky++) {
        float r[6];
#pragma unroll
        for (int j = 0; j < 6; j++)
          r[j] = s_in[ci * PLS + (py + ky) * RS + pxg * 4 + j];
#pragma unroll
        for (int kx = 0; kx < 3; kx++) {
          float4 wv =
              reinterpret_cast<const float4*>(s_w)[(ci * 9 + ky * 3 + kx) * 4 + cg];
#pragma unroll
          for (int p = 0; p < 4; p++) {
            float iv = r[p + kx];
            acc[0][p] += wv.x * iv;
            acc[1][p] += wv.y * iv;
            acc[2][p] += wv.z * iv;
            acc[3][p] += wv.w * iv;
          }
        }
      }
    }
  }

  float* outN = out + (size_t)n * 96 * PLV;
  const int gy = y0 + py;
#pragma unroll
  for (int q = 0; q < 4; q++) {
    int co = coB + cg * 4 + q;
#pragma unroll
    for (int p = 0; p < 4; p++)
      outN[(size_t)co * PLV + gy * 112 + x0 + pxg * 4 + p] = acc[q][p];
  }
}

// ---------------------------------------------------------------------------
// combine: x1 = U + shift(V) on ALL pixels; border corrected by stripdelta_k
// ---------------------------------------------------------------------------
__global__ void __launch_bounds__(256) combine_k() {
  const int bid = blockIdx.x;
  const int co = bid % 96, n = bid / 96;
  const int b = n / 49, d = n % 49;
  const int di = d / 7 - 3, dj = d % 7 - 3;

  const float* U = g_U + ((size_t)(b * 96 + co)) * PL1;
  const float* V = g_V + ((size_t)(b * 96 + co)) * PLV + (dj + 3) * 112 + (di + 3);
  float* X = g_x1 + ((size_t)(n * 96 + co)) * PL1;

  const int y0 = threadIdx.x >> 5, xl = threadIdx.x & 31;
  for (int y = y0; y < 64; y += 8) {
    const int ro = (y + 1) * 100 + 1;
    const int rv = y * 112;
#pragma unroll
    for (int x = xl; x < 96; x += 32)
      X[ro + x] = U[ro + x] + V[rv + x];
  }
}

// ---------------------------------------------------------------------------
// stripdelta: subtract BOTH border corrections from x1 on the 4-px frame:
//   f1 half (ci<32):  conv(f1 on taps in-image AND outside mask)   [mask err]
//   f2 half (ci>=32): conv(f2[tap+shift] on taps OUTSIDE image with
//                     shifted tap inside f2)                        [pad err]
// ---------------------------------------------------------------------------
__global__ void __launch_bounds__(128)
stripdelta_k(const float* __restrict__ f1, const float* __restrict__ f2,
             const float* __restrict__ w1) {
  const int sid = blockIdx.x;   // 0..9
  const int n   = blockIdx.y;
  const int y0 = d_segy[sid], x0 = d_segx[sid];
  const int h  = d_segh[sid], w = d_segw[sid];
  const int b = n / 49, d = n % 49;
  const int di = d / 7 - 3;
  const int dj = d % 7 - 3;

  // per-half activity
  bool af1, af2;
  {
    int rlo = y0 > 0 ? y0 - 1 : 0;
    int rhi = (y0 + h < 64) ? y0 + h : 63;
    int clo = x0 > 0 ? x0 - 1 : 0;
    int chi = (x0 + w < 96) ? x0 + w : 95;
    af1 = (dj < 0 && rlo < -dj) || (dj > 0 && rhi >= 64 - dj) ||
          (di < 0 && clo < -di) || (di > 0 && chi >= 96 - di);
    af2 = (y0 == 0 && dj > 0) || (y0 + h == 64 && dj < 0) ||
          (x0 == 0 && di > 0) || (x0 + w == 96 && di < 0);
    if (!af1 && !af2) return;
  }
  const int cbLo = af1 ? 0 : 32;
  const int cbHi = af2 ? 64 : 32;

  const int H2 = h + 2, W2 = w + 2;

  __shared__ float s_in[8 * 204];                  // max H2*W2 = 6*34 = 204
  __shared__ __align__(16) float s_w[8 * 9 * 32];

  const int tid = threadIdx.x;
  const bool pact = tid < h * w;
  const int py = pact ? tid / w : 0;
  const int px = pact ? tid % w : 0;

  const float* f1b = f1 + (size_t)b * 32 * 6144;
  const float* f2b = f2 + (size_t)b * 32 * 6144;

  for (int coc = 0; coc < 3; coc++) {
    float acc[32];
#pragma unroll
    for (int c = 0; c < 32; c++) acc[c] = 0.f;

    for (int cb = cbLo; cb < cbHi; cb += 8) {
      __syncthreads();
      for (int t = tid; t < 8 * H2 * W2; t += 128) {
        int ci  = t / (H2 * W2);
        int rem = t - ci * (H2 * W2);
        int r   = rem / W2;
        int c   = rem - r * W2;
        int yy = y0 - 1 + r, xx = x0 - 1 + c;
        int cic = cb + ci;
        float v = 0.f;
        bool inimg  = (unsigned)yy < 64u && (unsigned)xx < 96u;
        if (cic < 32) {
          bool inmask = (unsigned)(yy + dj) < 64u && (unsigned)(xx + di) < 96u;
          if (inimg && !inmask)
            v = f1b[cic * 6144 + yy * 96 + xx];
        } else {
          int sy = yy + dj, sx = xx + di;
          if (!inimg && (unsigned)sy < 64u && (unsigned)sx < 96u)
            v = f2b[(cic - 32) * 6144 + sy * 96 + sx];
        }
        s_in[ci * 204 + r * W2 + c] = v;
      }
      for (int t = tid; t < 32 * 8 * 9; t += 128) {
        int co  = t & 31;
        int rem = t >> 5;
        int k   = rem % 9;
        int ci  = rem / 9;
        s_w[(ci * 9 + k) * 32 + co] =
            w1[((coc * 32 + co) * 64 + cb + ci) * 9 + k];
      }
      __syncthreads();

      if (pact) {
#pragma unroll
        for (int ci = 0; ci < 8; ci++)
#pragma unroll
          for (int ky = 0; ky < 3; ky++)
#pragma unroll
            for (int kx = 0; kx < 3; kx++) {
              float v = s_in[ci * 204 + (py + ky) * W2 + (px + kx)];
              const float4* wv = reinterpret_cast<const float4*>(
                  &s_w[(ci * 9 + ky * 3 + kx) * 32]);
#pragma unroll
              for (int q = 0; q < 8; q++) {
                float4 ww = wv[q];
                acc[4 * q + 0] += ww.x * v;
                acc[4 * q + 1] += ww.y * v;
                acc[4 * q + 2] += ww.z * v;
                acc[4 * q + 3] += ww.w * v;
              }
            }
      }
    }
    if (pact) {
#pragma unroll
      for (int c = 0; c < 32; c++)
        g_x1[((size_t)n * 96 + coc * 32 + c) * PL1 +
             (y0 + py + 1) * 100 + (x0 + px + 1)] -= acc[c];
    }
    __syncthreads();
  }
}

// ---------------------------------------------------------------------------
// stats over planar padded plane (one block per (n,c) plane of g_x1)
// ---------------------------------------------------------------------------
__global__ void __launch_bounds__(256)
stats1_k() {
  const float* p = g_x1 + (size_t)blockIdx.x * PL1;
  const int wid = threadIdx.x >> 5, ln = threadIdx.x & 31;

  float s = 0.f, q = 0.f;
  for (int y = wid; y < 64; y += 8)
    for (int xx = ln; xx < 96; xx += 32) {
      float v = p[(y + 1) * 100 + xx + 1];
      s += v; q += v * v;
    }
#pragma unroll
  for (int o = 16; o > 0; o >>= 1) {
    s += __shfl_xor_sync(0xffffffffu, s, o);
    q += __shfl_xor_sync(0xffffffffu, q, o);
  }
  __shared__ float ss[8], sq[8];
  if (ln == 0) { ss[wid] = s; sq[wid] = q; }
  __syncthreads();
  if (threadIdx.x == 0) {
    float S = 0.f, Q = 0.f;
#pragma unroll
    for (int i = 0; i < 8; i++) { S += ss[i]; Q += sq[i]; }
    float m = S / 6144.f;
    float var = Q / 6144.f - m * m;
    g_stm[blockIdx.x] = m;                  // index = n*96 + c
    g_sti[blockIdx.x] = rsqrtf(var + 1e-5f);
  }
}

// ---------------------------------------------------------------------------
// apply norm+leaky to planar x1, transpose to ch-last, split bf16 hi/lo
// ---------------------------------------------------------------------------
__global__ void __launch_bounds__(256)
apply_x1cl_k() {
  __shared__ float s[96 * 97];
  const int y = blockIdx.x;   // 0..63
  const int n = blockIdx.y;
  const int tid = threadIdx.x;
  const int wid = tid >> 5, ln = tid & 31;

  for (int ci = wid; ci < 96; ci += 8) {
    const float* src = g_x1 + ((size_t)(n * 96 + ci)) * PL1 + (y + 1) * 100 + 1;
    for (int x = ln; x < 96; x += 32) s[x * 97 + ci] = src[x];
  }
  __syncthreads();
  for (int idx = tid; idx < 96 * 96; idx += 256) {
    int x = idx / 96, ci = idx % 96;
    float m = g_stm[n * 96 + ci], iv = g_sti[n * 96 + ci];
    float v = (s[x * 97 + ci] - m) * iv;
    v = v >= 0.f ? v : 0.01f * v;
    size_t o = ((size_t)(n * 6600 + (y + 1) * 100 + (x + 1))) * 96 + ci;
    bf16_split(v, g_X1h[o], g_X1l[o]);
  }
}

// ---------------------------------------------------------------------------
// stats over channel-last fp32 [n][NPX][C]
// ---------------------------------------------------------------------------
template <int C, int NPX>
__global__ void __launch_bounds__(512)
stats_cl_k(const float* __restrict__ xcl) {
  constexpr int SL = 512 / C;
  constexpr int PXS = NPX / SL;
  __shared__ float sm[512], sq[512];
  const int n = blockIdx.x;
  const int tid = threadIdx.x;
  const int ci = tid % C, sl = tid / C;

  const float* base = xcl + (size_t)n * NPX * C + ci;
  float s = 0.f, q = 0.f;
  for (int i = 0; i < PXS; i++) {
    float v = base[(size_t)(sl * PXS + i) * C];
    s += v; q += v * v;
  }
  sm[tid] = s; sq[tid] = q;
  __syncthreads();
  if (tid < C) {
    float S = 0.f, Q = 0.f;
#pragma unroll
    for (int j = 0; j < SL; j++) { S += sm[ci + j * C]; Q += sq[ci + j * C]; }
    float m = S / (float)NPX;
    float var = Q / (float)NPX - m * m;
    g_stm[n * 128 + ci] = m;
    g_sti[n * 128 + ci] = rsqrtf(var + 1e-5f);
  }
}

// ---------------------------------------------------------------------------
// apply norm+leaky (C=128) -> bf16 hi/lo padded ch-last (g_Xh/g_Xl)
// ---------------------------------------------------------------------------
__global__ void __launch_bounds__(256)
apply_cl128_k(const float* __restrict__ xcl) {
  const int y = blockIdx.x;   // 0..31
  const int n = blockIdx.y;
  const int tid = threadIdx.x;
  for (int idx = tid; idx < 48 * 128; idx += 256) {
    int x = idx >> 7, ci = idx & 127;
    float m = g_stm[n * 128 + ci], iv = g_sti[n * 128 + ci];
    float v = (xcl[((size_t)(n * 1536 + y * 48 + x)) * 128 + ci] - m) * iv;
    v = v >= 0.f ? v : 0.01f * v;
    size_t o = ((size_t)(n * 1768 + (y + 1) * 52 + (x + 1))) * 128 + ci;
    bf16_split(v, g_Xh[o], g_Xl[o]);
  }
}

// ---------------------------------------------------------------------------
// apply norm+leaky (C=64) -> bf16 hi/lo padded ch-last (g_X4h/g_X4l)
// ---------------------------------------------------------------------------
__global__ void __launch_bounds__(256)
apply_cl64_k(const float* __restrict__ xcl) {
  const int y = blockIdx.x;   // 0..31
  const int n = blockIdx.y;
  const int tid = threadIdx.x;
  for (int idx = tid; idx < 48 * 64; idx += 256) {
    int x = idx >> 6, ci = idx & 63;
    float m = g_stm[n * 128 + ci], iv = g_sti[n * 128 + ci];
    float v = (xcl[((size_t)(n * 1536 + y * 48 + x)) * 64 + ci] - m) * iv;
    v = v >= 0.f ? v : 0.01f * v;
    size_t o = ((size_t)(n * 1768 + (y + 1) * 52 + (x + 1))) * 64 + ci;
    bf16_split(v, g_X4h[o], g_X4l[o]);
  }
}

// ---------------------------------------------------------------------------
// apply norm+leaky to x5cl [n][par][1536][32] -> planar padded g_x5
// ---------------------------------------------------------------------------
__global__ void __launch_bounds__(256)
apply_x5_planar_k() {
  const int yq = blockIdx.x;  // 0..31 (y')
  const int n  = blockIdx.y;
  const int tid = threadIdx.x;
  float* outN = g_x5 + (size_t)n * 32 * PL1;

  for (int par = 0; par < 4; par++) {
    const int a = par >> 1, b = par & 1;
    const float* src = g_x5cl + ((size_t)(n * 4 + par) * 1536 + yq * 48) * 32;
    const int oy = 2 * yq + a + 1;
    for (int idx = tid; idx < 48 * 32; idx += 256) {
      int x = idx >> 5, co = idx & 31;
      float m = g_stm[n * 128 + co], iv = g_sti[n * 128 + co];
      float v = (src[x * 32 + co] - m) * iv;
      v = v >= 0.f ? v : 0.01f * v;
      outN[(size_t)co * PL1 + oy * 100 + 2 * x + b + 1] = v;
    }
  }
}

// ---------------------------------------------------------------------------
// gemm2: conv2 (stride 2), M-tile 96, N=128, Cin=96. cp.async 2-stage.
// dyn smem: A 2*15360 + B 2*20480 = 71680 B
// ---------------------------------------------------------------------------
__global__ void __launch_bounds__(256)
gemm2_k(float* __restrict__ xcl) {
  extern __shared__ __align__(16) unsigned short dynsm[];
  const int tid  = threadIdx.x;
  const int wid  = tid >> 5, lane = tid & 31;
  const int warp_m = wid & 1;
  const int warp_n = wid >> 1;
  const int tile = blockIdx.x;
  const int n    = blockIdx.y;
  const int px0  = tile * 96;

  const uint32_t aB = smem_u32(dynsm);
  const uint32_t bB = aB + 30720;

  float acc[3][4][4];
#pragma unroll
  for (int mi = 0; mi < 3; mi++)
#pragma unroll
    for (int ni = 0; ni < 4; ni++)
#pragma unroll
      for (int j = 0; j < 4; j++) acc[mi][ni][j] = 0.f;

  auto load_chunk = [&](int t, int stg) {
    int tap = t / 3, cc = t - tap * 3;
    int dy = tap / 3, dx = tap % 3, ci0 = cc * 32;
#pragma unroll
    for (int i = 0; i < 3; i++) {
      int id  = tid + i * 256;
      int hl  = id / 384;
      int rem = id - hl * 384;
      int r = rem >> 2, q = rem & 3;
      int px = px0 + r;
      int y = px / 48, x = px - y * 48;
      int pos = (2 * y + dy) * 100 + (2 * x + dx);
      const unsigned short* src =
          (hl ? g_X1l : g_X1h) + ((size_t)(n * 6600 + pos)) * 96 + ci0 + q * 8;
      cp_async16(aB + (uint32_t)(stg * 15360 + hl * 7680 + (r * 40 + q * 8) * 2), src);
    }
#pragma unroll
    for (int i = 0; i < 4; i++) {
      int id  = tid + i * 256;
      int hl  = id >> 9;
      int rem = id & 511;
      int r = rem >> 2, q = rem & 3;
      const unsigned short* src =
          (hl ? g_B2l : g_B2h) + ((size_t)(tap * 128 + r)) * 96 + ci0 + q * 8;
      cp_async16(bB + (uint32_t)(stg * 20480 + hl * 10240 + (r * 40 + q * 8) * 2), src);
    }
  };

  load_chunk(0, 0); CP_COMMIT();
  for (int t = 0; t < 27; t++) {
    int stg = t & 1;
    if (t + 1 < 27) { load_chunk(t + 1, stg ^ 1); CP_COMMIT(); CP_WAIT(1); }
    else CP_WAIT(0);
    __syncthreads();

    const uint32_t aH = aB + stg * 15360, aL = aH + 7680;
    const uint32_t bH = bB + stg * 20480, bL = bH + 10240;
#pragma unroll
    for (int ks = 0; ks < 2; ks++) {
      unsigned ah[3][4], al[3][4], bh[4][2], bl[4][2];
      const int arow = warp_m * 48 + (lane & 7) + ((lane >> 3) & 1) * 8;
      const int acol = ks * 16 + ((lane >> 4) & 1) * 8;
#pragma unroll
      for (int mi = 0; mi < 3; mi++) {
        uint32_t off = (uint32_t)(((arow + mi * 16) * 40 + acol) * 2);
        ldsm_x4(ah[mi], aH + off);
        ldsm_x4(al[mi], aL + off);
      }
      const int brow = warp_n * 32 + (lane & 7);
      const int bcol = ks * 16 + ((lane >> 3) & 1) * 8;
#pragma unroll
      for (int ni = 0; ni < 4; ni++) {
        uint32_t off = (uint32_t)(((brow + ni * 8) * 40 + bcol) * 2);
        ldsm_x2(bh[ni], bH + off);
        ldsm_x2(bl[ni], bL + off);
      }
#pragma unroll
      for (int mi = 0; mi < 3; mi++)
#pragma unroll
        for (int ni = 0; ni < 4; ni++) {
          mma_bf16(acc[mi][ni], ah[mi], bh[ni]);
          mma_bf16(acc[mi][ni], ah[mi], bl[ni]);
          mma_bf16(acc[mi][ni], al[mi], bh[ni]);
        }
    }
    __syncthreads();
  }

  const int g = lane >> 2, tg = lane & 3;
#pragma unroll
  for (int mi = 0; mi < 3; mi++)
#pragma unroll
    for (int ni = 0; ni < 4; ni++) {
      int row = px0 + warp_m * 48 + mi * 16 + g;
      int co  = warp_n * 32 + ni * 8 + tg * 2;
      float* d0 = xcl + ((size_t)(n * 1536 + row)) * 128 + co;
      float* d1 = xcl + ((size_t)(n * 1536 + row + 8)) * 128 + co;
      *reinterpret_cast<float2*>(d0) = make_float2(acc[mi][ni][0], acc[mi][ni][1]);
      *reinterpret_cast<float2*>(d1) = make_float2(acc[mi][ni][2], acc[mi][ni][3]);
    }
}

// ---------------------------------------------------------------------------
// gemm3: conv3, N=128, Cin=128. cp.async 2-stage. dyn smem 71680 B
// ---------------------------------------------------------------------------
__global__ void __launch_bounds__(256)
gemm3_k(float* __restrict__ xcl) {
  extern __shared__ __align__(16) unsigned short dynsm[];
  const int tid  = threadIdx.x;
  const int wid  = tid >> 5, lane = tid & 31;
  const int warp_m = wid & 1;
  const int warp_n = wid >> 1;
  const int tile = blockIdx.x;
  const int n    = blockIdx.y;
  const int px0  = tile * 96;

  const uint32_t aB = smem_u32(dynsm);
  const uint32_t bB = aB + 30720;

  float acc[3][4][4];
#pragma unroll
  for (int mi = 0; mi < 3; mi++)
#pragma unroll
    for (int ni = 0; ni < 4; ni++)
#pragma unroll
      for (int j = 0; j < 4; j++) acc[mi][ni][j] = 0.f;

  auto load_chunk = [&](int t, int stg) {
    int tap = t >> 2, cc = t & 3;
    int dy = tap / 3, dx = tap % 3, ci0 = cc * 32;
#pragma unroll
    for (int i = 0; i < 3; i++) {
      int id  = tid + i * 256;
      int hl  = id / 384;
      int rem = id - hl * 384;
      int r = rem >> 2, q = rem & 3;
      int px = px0 + r;
      int y = px / 48, x = px - y * 48;
      int pos = (y + dy) * 52 + (x + dx);
      const unsigned short* src =
          (hl ? g_Xl : g_Xh) + ((size_t)(n * 1768 + pos)) * 128 + ci0 + q * 8;
      cp_async16(aB + (uint32_t)(stg * 15360 + hl * 7680 + (r * 40 + q * 8) * 2), src);
    }
#pragma unroll
    for (int i = 0; i < 4; i++) {
      int id  = tid + i * 256;
      int hl  = id >> 9;
      int rem = id & 511;
      int r = rem >> 2, q = rem & 3;
      const unsigned short* src =
          (hl ? g_B3l : g_B3h) + ((size_t)(tap * 128 + r)) * 128 + ci0 + q * 8;
      cp_async16(bB + (uint32_t)(stg * 20480 + hl * 10240 + (r * 40 + q * 8) * 2), src);
    }
  };

  load_chunk(0, 0); CP_COMMIT();
  for (int t = 0; t < 36; t++) {
    int stg = t & 1;
    if (t + 1 < 36) { load_chunk(t + 1, stg ^ 1); CP_COMMIT(); CP_WAIT(1); }
    else CP_WAIT(0);
    __syncthreads();

    const uint32_t aH = aB + stg * 15360, aL = aH + 7680;
    const uint32_t bH = bB + stg * 20480, bL = bH + 10240;
#pragma unroll
    for (int ks = 0; ks < 2; ks++) {
      unsigned ah[3][4], al[3][4], bh[4][2], bl[4][2];
      const int arow = warp_m * 48 + (lane & 7) + ((lane >> 3) & 1) * 8;
      const int acol = ks * 16 + ((lane >> 4) & 1) * 8;
#pragma unroll
      for (int mi = 0; mi < 3; mi++) {
        uint32_t off = (uint32_t)(((arow + mi * 16) * 40 + acol) * 2);
        ldsm_x4(ah[mi], aH + off);
        ldsm_x4(al[mi], aL + off);
      }
      const int brow = warp_n * 32 + (lane & 7);
      const int bcol = ks * 16 + ((lane >> 3) & 1) * 8;
#pragma unroll
      for (int ni = 0; ni < 4; ni++) {
        uint32_t off = (uint32_t)(((brow + ni * 8) * 40 + bcol) * 2);
        ldsm_x2(bh[ni], bH + off);
        ldsm_x2(bl[ni], bL + off);
      }
#pragma unroll
      for (int mi = 0; mi < 3; mi++)
#pragma unroll
        for (int ni = 0; ni < 4; ni++) {
          mma_bf16(acc[mi][ni], ah[mi], bh[ni]);
          mma_bf16(acc[mi][ni], ah[mi], bl[ni]);
          mma_bf16(acc[mi][ni], al[mi], bh[ni]);
        }
    }
    __syncthreads();
  }

  const int g = lane >> 2, tg = lane & 3;
#pragma unroll
  for (int mi = 0; mi < 3; mi++)
#pragma unroll
    for (int ni = 0; ni < 4; ni++) {
      int row = px0 + warp_m * 48 + mi * 16 + g;
      int co  = warp_n * 32 + ni * 8 + tg * 2;
      float* d0 = xcl + ((size_t)(n * 1536 + row)) * 128 + co;
      float* d1 = xcl + ((size_t)(n * 1536 + row + 8)) * 128 + co;
      *reinterpret_cast<float2*>(d0) = make_float2(acc[mi][ni][0], acc[mi][ni][1]);
      *reinterpret_cast<float2*>(d1) = make_float2(acc[mi][ni][2], acc[mi][ni][3]);
    }
}

// ---------------------------------------------------------------------------
// gemm4: conv4, N=64, Cin=128. cp.async 2-stage. dyn smem 51200 B
// ---------------------------------------------------------------------------
__global__ void __launch_bounds__(256)
gemm4_k(float* __restrict__ xcl) {
  extern __shared__ __align__(16) unsigned short dynsm[];
  const int tid  = threadIdx.x;
  const int wid  = tid >> 5, lane = tid & 31;
  const int warp_m = wid & 1;
  const int warp_n = wid >> 1;
  const int tile = blockIdx.x;
  const int n    = blockIdx.y;
  const int px0  = tile * 96;

  const uint32_t aB = smem_u32(dynsm);
  const uint32_t bB = aB + 30720;

  float acc[3][2][4];
#pragma unroll
  for (int mi = 0; mi < 3; mi++)
#pragma unroll
    for (int ni = 0; ni < 2; ni++)
#pragma unroll
      for (int j = 0; j < 4; j++) acc[mi][ni][j] = 0.f;

  auto load_chunk = [&](int t, int stg) {
    int tap = t >> 2, cc = t & 3;
    int dy = tap / 3, dx = tap % 3, ci0 = cc * 32;
#pragma unroll
    for (int i = 0; i < 3; i++) {
      int id  = tid + i * 256;
      int hl  = id / 384;
      int rem = id - hl * 384;
      int r = rem >> 2, q = rem & 3;
      int px = px0 + r;
      int y = px / 48, x = px - y * 48;
      int pos = (y + dy) * 52 + (x + dx);
      const unsigned short* src =
          (hl ? g_Xl : g_Xh) + ((size_t)(n * 1768 + pos)) * 128 + ci0 + q * 8;
      cp_async16(aB + (uint32_t)(stg * 15360 + hl * 7680 + (r * 40 + q * 8) * 2), src);
    }
#pragma unroll
    for (int i = 0; i < 2; i++) {
      int id  = tid + i * 256;
      int hl  = id >> 8;
      int rem = id & 255;
      int r = rem >> 2, q = rem & 3;
      const unsigned short* src =
          (hl ? g_B4l : g_B4h) + ((size_t)(tap * 64 + r)) * 128 + ci0 + q * 8;
      cp_async16(bB + (uint32_t)(stg * 10240 + hl * 5120 + (r * 40 + q * 8) * 2), src);
    }
  };

  load_chunk(0, 0); CP_COMMIT();
  for (int t = 0; t < 36; t++) {
    int stg = t & 1;
    if (t + 1 < 36) { load_chunk(t + 1, stg ^ 1); CP_COMMIT(); CP_WAIT(1); }
    else CP_WAIT(0);
    __syncthreads();

    const uint32_t aH = aB + stg * 15360, aL = aH + 7680;
    const uint32_t bH = bB + stg * 10240, bL = bH + 5120;
#pragma unroll
    for (int ks = 0; ks < 2; ks++) {
      unsigned ah[3][4], al[3][4], bh[2][2], bl[2][2];
      const int arow = warp_m * 48 + (lane & 7) + ((lane >> 3) & 1) * 8;
      const int acol = ks * 16 + ((lane >> 4) & 1) * 8;
#pragma unroll
      for (int mi = 0; mi < 3; mi++) {
        uint32_t off = (uint32_t)(((arow + mi * 16) * 40 + acol) * 2);
        ldsm_x4(ah[mi], aH + off);
        ldsm_x4(al[mi], aL + off);
      }
      const int brow = warp_n * 16 + (lane & 7);
      const int bcol = ks * 16 + ((lane >> 3) & 1) * 8;
#pragma unroll
      for (int ni = 0; ni < 2; ni++) {
        uint32_t off = (uint32_t)(((brow + ni * 8) * 40 + bcol) * 2);
        ldsm_x2(bh[ni], bH + off);
        ldsm_x2(bl[ni], bL + off);
      }
#pragma unroll
      for (int mi = 0; mi < 3; mi++)
#pragma unroll
        for (int ni = 0; ni < 2; ni++) {
          mma_bf16(acc[mi][ni], ah[mi], bh[ni]);
          mma_bf16(acc[mi][ni], ah[mi], bl[ni]);
          mma_bf16(acc[mi][ni], al[mi], bh[ni]);
        }
    }
    __syncthreads();
  }

  const int g = lane >> 2, tg = lane & 3;
#pragma unroll
  for (int mi = 0; mi < 3; mi++)
#pragma unroll
    for (int ni = 0; ni < 2; ni++) {
      int row = px0 + warp_m * 48 + mi * 16 + g;
      int co  = warp_n * 16 + ni * 8 + tg * 2;
      float* d0 = xcl + ((size_t)(n * 1536 + row)) * 64 + co;
      float* d1 = xcl + ((size_t)(n * 1536 + row + 8)) * 64 + co;
      *reinterpret_cast<float2*>(d0) = make_float2(acc[mi][ni][0], acc[mi][ni][1]);
      *reinterpret_cast<float2*>(d1) = make_float2(acc[mi][ni][2], acc[mi][ni][3]);
    }
}

// ---------------------------------------------------------------------------
// gemm5: deconv per parity, M-tile 128, N=32, K=4x64. cp.async 2-stage.
// dyn smem: A 2*20480 + B 2*5120 = 51200 B
// ---------------------------------------------------------------------------
__global__ void __launch_bounds__(256)
gemm5_k() {
  extern __shared__ __align__(16) unsigned short dynsm[];
  const int tid  = threadIdx.x;
  const int wid  = tid >> 5, lane = tid & 31;   // warp_m = wid (0..7)
  const int tile = blockIdx.x;                  // 0..11
  const int par  = blockIdx.y;                  // 0..3
  const int n    = blockIdx.z;
  const int a = par >> 1, b = par & 1;
  const int px0 = tile * 128;

  const uint32_t aB = smem_u32(dynsm);
  const uint32_t bB = aB + 40960;

  float acc[4][4];
#pragma unroll
  for (int ni = 0; ni < 4; ni++)
#pragma unroll
    for (int j = 0; j < 4; j++) acc[ni][j] = 0.f;

  auto load_chunk = [&](int t, int stg) {
    int tap = t >> 1, cc = t & 1;
    int s = tap >> 1, tt = tap & 1, ci0 = cc * 32;
#pragma unroll
    for (int i = 0; i < 4; i++) {
      int id  = tid + i * 256;
      int hl  = id >> 9;
      int rem = id & 511;
      int r = rem >> 2, q = rem & 3;
      int px = px0 + r;
      int y = px / 48, x = px - y * 48;
      int pos = (y + a + s) * 52 + (x + b + tt);
      const unsigned short* src =
          (hl ? g_X4l : g_X4h) + ((size_t)(n * 1768 + pos)) * 64 + ci0 + q * 8;
      cp_async16(aB + (uint32_t)(stg * 20480 + hl * 10240 + (r * 40 + q * 8) * 2), src);
    }
    {
      int hl  = tid >> 7;
      int rem = tid & 127;
      int r = rem >> 2, q = rem & 3;
      const unsigned short* src =
          (hl ? g_B5l : g_B5h) + ((size_t)((par * 4 + tap) * 32 + r)) * 64 + ci0 + q * 8;
      cp_async16(bB + (uint32_t)(stg * 5120 + hl * 2560 + (r * 40 + q * 8) * 2), src);
    }
  };

  load_chunk(0, 0); CP_COMMIT();
  for (int t = 0; t < 8; t++) {
    int stg = t & 1;
    if (t + 1 < 8) { load_chunk(t + 1, stg ^ 1); CP_COMMIT(); CP_WAIT(1); }
    else CP_WAIT(0);
    __syncthreads();

    const uint32_t aH = aB + stg * 20480, aL = aH + 10240;
    const uint32_t bH = bB + stg * 5120, bL = bH + 2560;
#pragma unroll
    for (int ks = 0; ks < 2; ks++) {
      unsigned ah[4], al[4], bh[4][2], bl[4][2];
      const int arow = wid * 16 + (lane & 7) + ((lane >> 3) & 1) * 8;
      const int acol = ks * 16 + ((lane >> 4) & 1) * 8;
      {
        uint32_t off = (uint32_t)((arow * 40 + acol) * 2);
        ldsm_x4(ah, aH + off);
        ldsm_x4(al, aL + off);
      }
      const int brow = lane & 7;
      const int bcol = ks * 16 + ((lane >> 3) & 1) * 8;
#pragma unroll
      for (int ni = 0; ni < 4; ni++) {
        uint32_t off = (uint32_t)(((brow + ni * 8) * 40 + bcol) * 2);
        ldsm_x2(bh[ni], bH + off);
        ldsm_x2(bl[ni], bL + off);
      }
#pragma unroll
      for (int ni = 0; ni < 4; ni++) {
        mma_bf16(acc[ni], ah, bh[ni]);
        mma_bf16(acc[ni], ah, bl[ni]);
        mma_bf16(acc[ni], al, bh[ni]);
      }
    }
    __syncthreads();
  }

  const int g = lane >> 2, tg = lane & 3;
  float* base = g_x5cl + ((size_t)(n * 4 + par)) * 1536 * 32;
#pragma unroll
  for (int ni = 0; ni < 4; ni++) {
    int row = px0 + wid * 16 + g;
    int co  = ni * 8 + tg * 2;
    *reinterpret_cast<float2*>(base + (size_t)row * 32 + co) =
        make_float2(acc[ni][0], acc[ni][1]);
    *reinterpret_cast<float2*>(base + (size_t)(row + 8) * 32 + co) =
        make_float2(acc[ni][2], acc[ni][3]);
  }
}

// ---------------------------------------------------------------------------
// final conv 32->1 + bias (planar x5 -> d_out)
// ---------------------------------------------------------------------------
__global__ void __launch_bounds__(256)
conv_final_k(const float* __restrict__ in, const float* __restrict__ w6,
             const float* __restrict__ b6, float* __restrict__ out) {
  constexpr int RS = 37, PLS = 10 * RS;
  __shared__ float s_in[8 * PLS];
  __shared__ float sw[288];
  __shared__ float sb;

  const int tid = threadIdx.x;
  const int tx = blockIdx.x % 3;
  const int ty = blockIdx.x / 3;
  const int n  = blockIdx.y;
  const int y0 = ty * 8, x0 = tx * 32;
  const int px = tid & 31, py = tid >> 5;

  for (int t = tid; t < 288; t += 256) sw[t] = w6[t];
  if (tid == 0) sb = b6[0];

  const float* inN = in + (size_t)n * 32 * PL1;
  float acc = 0.f;

  for (int cb = 0; cb < 32; cb += 8) {
    __syncthreads();
#pragma unroll
    for (int t = tid; t < 8 * 10 * 9; t += 256) {
      int c   = t / 90;
      int rem = t - c * 90;
      int r   = rem / 9;
      int q   = rem - r * 9;
      const float4 v = *reinterpret_cast<const float4*>(
          inN + (size_t)(cb + c) * PL1 + (y0 + r) * 100 + x0 + 4 * q);
      float* dst = &s_in[c * PLS + r * RS + 4 * q];
      dst[0] = v.x; dst[1] = v.y; dst[2] = v.z; dst[3] = v.w;
    }
    __syncthreads();
#pragma unroll
    for (int c = 0; c < 8; c++)
#pragma unroll
      for (int ky = 0; ky < 3; ky++)
#pragma unroll
        for (int kx = 0; kx < 3; kx++)
          acc += sw[(cb + c) * 9 + ky * 3 + kx] *
                 s_in[c * PLS + (py + ky) * RS + px + kx];
  }

  out[(size_t)n * 6144 + (y0 + py) * 96 + x0 + px] = acc + sb;
}

// ---------------------------------------------------------------------------
// Launch
// ---------------------------------------------------------------------------
extern "C" void kernel_launch(void* const* d_in, const int* in_sizes, int n_in,
                              void* d_out, int out_size) {
  const float* f1 = (const float*)d_in[0];
  const float* f2 = (const float*)d_in[1];
  const float* w1 = (const float*)d_in[2];
  const float* w2 = (const float*)d_in[3];
  const float* w3 = (const float*)d_in[4];
  const float* w4 = (const float*)d_in[5];
  const float* w5 = (const float*)d_in[6];
  const float* w6 = (const float*)d_in[7];
  const float* b6 = (const float*)d_in[8];
  float* out = (float*)d_out;

  float *x5, *f1p, *f2c, *U, *V, *w1a, *w1b, *x2cl, *x3cl, *x4cl;
  cudaGetSymbolAddress((void**)&x5, g_x5);
  cudaGetSymbolAddress((void**)&f1p, g_f1p);
  cudaGetSymbolAddress((void**)&f2c, g_f2c);
  cudaGetSymbolAddress((void**)&U, g_U);
  cudaGetSymbolAddress((void**)&V, g_V);
  cudaGetSymbolAddress((void**)&w1a, g_w1a);
  cudaGetSymbolAddress((void**)&w1b, g_w1b);
  cudaGetSymbolAddress((void**)&x2cl, g_x2cl);
  cudaGetSymbolAddress((void**)&x3cl, g_x3cl);
  cudaGetSymbolAddress((void**)&x4cl, g_x4cl);

  // dyn smem opt-in (idempotent; safe each call)
  cudaFuncSetAttribute(gemm2_k, cudaFuncAttributeMaxDynamicSharedMemorySize, 71680);
  cudaFuncSetAttribute(gemm3_k, cudaFuncAttributeMaxDynamicSharedMemorySize, 71680);
  cudaFuncSetAttribute(gemm4_k, cudaFuncAttributeMaxDynamicSharedMemorySize, 51200);
  cudaFuncSetAttribute(gemm5_k, cudaFuncAttributeMaxDynamicSharedMemorySize, 51200);

  // prep
  prep_k<<<(2 * 32 * 6144 + 255) / 256, 256>>>(f1, f2, w1);
  wprep2_k<<<(9 * 128 * 96 + 255) / 256, 256>>>(w2);
  wprep3_k<<<(9 * 128 * 128 + 255) / 256, 256>>>(w3);
  wprep4_k<<<(9 * 64 * 128 + 255) / 256, 256>>>(w4);
  wprep5_k<<<(4 * 4 * 32 * 64 + 255) / 256, 256>>>(w5);

  // conv1 via factorization -> planar x1 (pre-norm), border via delta subtract
  conv3x3_s1_k<32, 64, 96, 100><<<dim3(24, 6, 2), 256>>>(f1p, w1a, U, 32, 96);
  conv_v_k<<<dim3(63, 6, 2), 128>>>(f2c, w1b, V);
  combine_k<<<NIMG * 96, 256>>>();
  stripdelta_k<<<dim3(10, NIMG), 128>>>(f1, f2, w1);

  // x1: fused stats -> apply+transpose+bf16 split
  stats1_k<<<NIMG * 96, 256>>>();
  apply_x1cl_k<<<dim3(64, NIMG), 256>>>();

  // conv2 GEMM; inorm -> g_Xh/g_Xl
  gemm2_k<<<dim3(16, NIMG), 256, 71680>>>(x2cl);
  stats_cl_k<128, 1536><<<NIMG, 512>>>(x2cl);
  apply_cl128_k<<<dim3(32, NIMG), 256>>>(x2cl);

  // conv3 GEMM; inorm -> g_Xh/g_Xl (overwrite)
  gemm3_k<<<dim3(16, NIMG), 256, 71680>>>(x3cl);
  stats_cl_k<128, 1536><<<NIMG, 512>>>(x3cl);
  apply_cl128_k<<<dim3(32, NIMG), 256>>>(x3cl);

  // conv4 GEMM; inorm -> g_X4h/g_X4l (ch-last bf16)
  gemm4_k<<<dim3(16, NIMG), 256, 51200>>>(x4cl);
  stats_cl_k<64, 1536><<<NIMG, 512>>>(x4cl);
  apply_cl64_k<<<dim3(32, NIMG), 256>>>(x4cl);

  // deconv GEMM (4 parities); inorm -> planar x5
  gemm5_k<<<dim3(12, 4, NIMG), 256, 51200>>>();
  {
    float* x5cl;
    cudaGetSymbolAddress((void**)&x5cl, g_x5cl);
    stats_cl_k<32, 6144><<<NIMG, 512>>>(x5cl);
  }
  apply_x5_planar_k<<<dim3(32, NIMG), 256>>>();

  // final conv
  conv_final_k<<<dim3(24, NIMG), 256>>>(x5, w6, b6, out);
}

// round 17
// speedup vs baseline: 2.9213x; 1.0299x over previous
#include <cuda_runtime.h>
#include <cuda_bf16.h>
#include <cstdint>

// ---------------------------------------------------------------------------
// Padded planar layouts [C][H+2][WP], 1-px zero halo (globals zero-init).
// ---------------------------------------------------------------------------
#define NIMG 98
#define PL1 (66 * 100)
#define PL2 (34 * 52)
#define PLV (72 * 112)
#define PLC (80 * 120)

__device__ float g_x1 [NIMG * 96 * PL1];
__device__ float g_x5 [NIMG * 32 * PL1];

// conv1 factorization scratch
__device__ float g_f1p[2 * 32 * PL1];
__device__ float g_f2c[2 * 32 * PLC];
__device__ float g_U  [2 * 96 * PL1];
__device__ float g_V  [2 * 96 * PLV];
__device__ float g_w1a[96 * 32 * 9];
__device__ float g_w1b[96 * 32 * 9];

// tensor-core path scratch (mma.sync)
__device__ unsigned short g_X1h[(size_t)NIMG * 6600 * 96];  // x1 ch-last bf16 hi
__device__ unsigned short g_X1l[(size_t)NIMG * 6600 * 96];
__device__ unsigned short g_Xh[(size_t)NIMG * 1768 * 128];  // x2 then x3 ch-last (34x52)
__device__ unsigned short g_Xl[(size_t)NIMG * 1768 * 128];
__device__ unsigned short g_X4h[(size_t)NIMG * 1768 * 64];  // x4 ch-last bf16
__device__ unsigned short g_X4l[(size_t)NIMG * 1768 * 64];
__device__ unsigned short g_B2h[9 * 128 * 96];              // w2 [tap][co][ci]
__device__ unsigned short g_B2l[9 * 128 * 96];
__device__ unsigned short g_B3h[9 * 128 * 128];
__device__ unsigned short g_B3l[9 * 128 * 128];
__device__ unsigned short g_B4h[9 * 64 * 128];
__device__ unsigned short g_B4l[9 * 64 * 128];
__device__ unsigned short g_B5h[4 * 4 * 32 * 64];           // w5 [par][tap][co][ci]
__device__ unsigned short g_B5l[4 * 4 * 32 * 64];
__device__ float g_x2cl[(size_t)NIMG * 1536 * 128];
__device__ float g_x3cl[(size_t)NIMG * 1536 * 128];
__device__ float g_x4cl[(size_t)NIMG * 1536 * 64];
__device__ float g_x5cl[(size_t)NIMG * 4 * 1536 * 32];      // [n][par][px][co]
__device__ float g_stm[NIMG * 128];
__device__ float g_sti[NIMG * 128];

// deterministic stats scratch
__device__ float g_r1S[NIMG * 96];            // x1 raw sums (combine)
__device__ float g_r1Q[NIMG * 96];
__device__ float g_d1S[NIMG * 10 * 96];       // x1 per-segment deltas
__device__ float g_d1Q[NIMG * 10 * 96];
__device__ float g_gp[(size_t)NIMG * 48 * 256]; // gemm per-block partials [n][slot][ci][S,Q]

// delta segment table: 10 segments, <=128 px each, covering the 4-px frame
__device__ const int d_segy[10] = {0,0,0, 60,60,60, 4,32, 4,32};
__device__ const int d_segx[10] = {0,32,64, 0,32,64, 0,0, 92,92};
__device__ const int d_segh[10] = {4,4,4, 4,4,4, 28,28, 28,28};
__device__ const int d_segw[10] = {32,32,32, 32,32,32, 4,4, 4,4};

// ---------------------------------------------------------------------------
// mma.sync + cp.async helpers
// ---------------------------------------------------------------------------
__device__ __forceinline__ uint32_t smem_u32(const void* p) {
  uint32_t a;
  asm("{ .reg .u64 t; cvta.to.shared.u64 t, %1; cvt.u32.u64 %0, t; }"
      : "=r"(a) : "l"(p));
  return a;
}
__device__ __forceinline__ void ldsm_x4(unsigned r[4], uint32_t addr) {
  asm volatile("ldmatrix.sync.aligned.m8n8.x4.shared.b16 {%0,%1,%2,%3}, [%4];"
               : "=r"(r[0]), "=r"(r[1]), "=r"(r[2]), "=r"(r[3]) : "r"(addr));
}
__device__ __forceinline__ void ldsm_x2(unsigned r[2], uint32_t addr) {
  asm volatile("ldmatrix.sync.aligned.m8n8.x2.shared.b16 {%0,%1}, [%2];"
               : "=r"(r[0]), "=r"(r[1]) : "r"(addr));
}
__device__ __forceinline__ void mma_bf16(float d[4], const unsigned a[4],
                                         const unsigned b[2]) {
  asm volatile(
      "mma.sync.aligned.m16n8k16.row.col.f32.bf16.bf16.f32 "
      "{%0,%1,%2,%3}, {%4,%5,%6,%7}, {%8,%9}, {%0,%1,%2,%3};"
      : "+f"(d[0]), "+f"(d[1]), "+f"(d[2]), "+f"(d[3])
      : "r"(a[0]), "r"(a[1]), "r"(a[2]), "r"(a[3]), "r"(b[0]), "r"(b[1]));
}
__device__ __forceinline__ void bf16_split(float v, unsigned short& h,
                                           unsigned short& l) {
  __nv_bfloat16 hb = __float2bfloat16(v);
  __nv_bfloat16 lb = __float2bfloat16(v - __bfloat162float(hb));
  h = __bfloat16_as_ushort(hb);
  l = __bfloat16_as_ushort(lb);
}
__device__ __forceinline__ void cp_async16(uint32_t smem_addr, const void* gptr) {
  asm volatile("cp.async.cg.shared.global [%0], [%1], 16;"
               :: "r"(smem_addr), "l"(gptr) : "memory");
}
#define CP_COMMIT() asm volatile("cp.async.commit_group;" ::: "memory")
#define CP_WAIT(N)  asm volatile("cp.async.wait_group %0;" :: "n"(N) : "memory")

// ---------------------------------------------------------------------------
// merged prep: pad f1/f2, split w1, bf16-split w2..w5
// ---------------------------------------------------------------------------
__global__ void prep_all_k(const float* __restrict__ f1, const float* __restrict__ f2,
                           const float* __restrict__ w1, const float* __restrict__ w2,
                           const float* __restrict__ w3, const float* __restrict__ w4,
                           const float* __restrict__ w5) {
  int idx = blockIdx.x * blockDim.x + threadIdx.x;
  if (idx < 2 * 32 * 6144) {
    int x = idx % 96, y = (idx / 96) % 64, c = idx / 6144;
    g_f1p[(size_t)c * PL1 + (y + 1) * 100 + x + 1] = f1[idx];
    g_f2c[(size_t)c * PLC + (y + 8) * 120 + x + 8] = f2[idx];
  }
  if (idx < 96 * 64 * 9) {
    int co = idx / 576, rem = idx % 576, ci = rem / 9, k = rem % 9;
    if (ci < 32) g_w1a[(co * 32 + ci) * 9 + k] = w1[idx];
    else         g_w1b[(co * 32 + (ci - 32)) * 9 + k] = w1[idx];
  }
  if (idx < 9 * 128 * 96) {
    int ci = idx % 96, co = (idx / 96) % 128, tap = idx / 12288;
    bf16_split(w2[(co * 96 + ci) * 9 + tap], g_B2h[idx], g_B2l[idx]);
  }
  if (idx < 9 * 128 * 128) {
    int ci = idx & 127, co = (idx >> 7) & 127, tap = idx >> 14;
    bf16_split(w3[(co * 128 + ci) * 9 + tap], g_B3h[idx], g_B3l[idx]);
  }
  if (idx < 9 * 64 * 128) {
    int ci = idx & 127, co = (idx >> 7) & 63, tap = idx >> 13;
    bf16_split(w4[(co * 128 + ci) * 9 + tap], g_B4h[idx], g_B4l[idx]);
  }
  if (idx < 4 * 4 * 32 * 64) {
    int ci  = idx & 63;
    int co  = (idx >> 6) & 31;
    int tap = (idx >> 11) & 3;
    int par = idx >> 13;
    int a = par >> 1, b = par & 1;
    int s = tap >> 1, t = tap & 1;
    float v = w5[(((size_t)ci * 32 + co) * 4 + (3 - (a + 2 * s))) * 4 +
                 (3 - (b + 2 * t))];
    bf16_split(v, g_B5h[idx], g_B5l[idx]);
  }
}

// ---------------------------------------------------------------------------
// 3x3 s1 conv (scalar, conv1 factorization)
// ---------------------------------------------------------------------------
template <int TW, int H, int W, int WP>
__global__ void __launch_bounds__(8 * TW)
conv3x3_s1_k(const float* __restrict__ in, const float* __restrict__ w,
             float* __restrict__ out, int Cin, int Cout) {
  constexpr int PXG = TW / 4;
  constexpr int NT  = 8 * TW;
  constexpr int RS  = 37;
  constexpr int PLS = 10 * RS;
  constexpr int F4  = (TW + 4) / 4;
  constexpr int PLANE = (H + 2) * WP;

  __shared__ float s_in[8 * PLS];
  __shared__ __align__(16) float s_w[8 * 9 * 16];

  const int tid = threadIdx.x;
  const int cg  = tid / (8 * PXG);
  const int pid = tid % (8 * PXG);
  const int py  = pid / PXG;
  const int pxg = pid % PXG;

  const int tilesX = W / TW;
  const int tx = blockIdx.x % tilesX;
  const int ty = blockIdx.x / tilesX;
  const int n  = blockIdx.z;
  const int coB = blockIdx.y * 16;
  const int y0 = ty * 8, x0 = tx * TW;

  const float* inN = in + (size_t)n * Cin * PLANE;

  float acc[4][4];
#pragma unroll
  for (int q = 0; q < 4; q++)
#pragma unroll
    for (int p = 0; p < 4; p++) acc[q][p] = 0.f;

  for (int cb = 0; cb < Cin; cb += 8) {
    __syncthreads();
#pragma unroll
    for (int t = tid; t < 8 * 10 * F4; t += NT) {
      int c   = t / (10 * F4);
      int rem = t - c * (10 * F4);
      int r   = rem / F4;
      int q   = rem - r * F4;
      const float4 v = *reinterpret_cast<const float4*>(
          inN + (size_t)(cb + c) * PLANE + (y0 + r) * WP + x0 + 4 * q);
      float* dst = &s_in[c * PLS + r * RS + 4 * q];
      dst[0] = v.x; dst[1] = v.y; dst[2] = v.z; dst[3] = v.w;
    }
    for (int t = tid; t < 16 * 8 * 9; t += NT) {
      int lco = t & 15;
      int rem = t >> 4;
      int k   = rem % 9;
      int lci = rem / 9;
      s_w[(lci * 9 + k) * 16 + lco] =
          w[((size_t)(coB + lco) * Cin + (cb + lci)) * 9 + k];
    }
    __syncthreads();

#pragma unroll
    for (int ci = 0; ci < 8; ci++) {
#pragma unroll
      for (int ky = 0; ky < 3; ky++) {
        float r[6];
#pragma unroll
        for (int j = 0; j < 6; j++)
          r[j] = s_in[ci * PLS + (py + ky) * RS + pxg * 4 + j];
#pragma unroll
        for (int kx = 0; kx < 3; kx++) {
          float4 wv =
              reinterpret_cast<const float4*>(s_w)[(ci * 9 + ky * 3 + kx) * 4 + cg];
#pragma unroll
          for (int p = 0; p < 4; p++) {
            float iv = r[p + kx];
            acc[0][p] += wv.x * iv;
            acc[1][p] += wv.y * iv;
            acc[2][p] += wv.z * iv;
            acc[3][p] += wv.w * iv;
          }
        }
      }
    }
  }

  float* outN = out + (size_t)n * Cout * PLANE;
  const int gy = y0 + py + 1;
#pragma unroll
  for (int q = 0; q < 4; q++) {
    int co = coB + cg * 4 + q;
#pragma unroll
    for (int p = 0; p < 4; p++)
      outN[(size_t)co * PLANE + gy * WP + x0 + pxg * 4 + p + 1] = acc[q][p];
  }
}

// ---------------------------------------------------------------------------
// V = conv3x3(zero-padded f2) on extended 72x112 grid
// ---------------------------------------------------------------------------
__global__ void __launch_bounds__(128)
conv_v_k(const float* __restrict__ in, const float* __restrict__ w,
         float* __restrict__ out) {
  constexpr int RS = 37, PLS = 10 * RS;
  __shared__ float s_in[8 * PLS];
  __shared__ __align__(16) float s_w[8 * 9 * 16];

  const int tid = threadIdx.x;
  const int cg  = tid >> 5;
  const int pid = tid & 31;
  const int py  = pid >> 2;
  const int pxg = pid & 3;

  const int tx = blockIdx.x % 7;
  const int ty = blockIdx.x / 7;
  const int n  = blockIdx.z;
  const int coB = blockIdx.y * 16;
  const int y0 = ty * 8, x0 = tx * 16;

  const float* inN = in + (size_t)n * 32 * PLC;

  float acc[4][4];
#pragma unroll
  for (int q = 0; q < 4; q++)
#pragma unroll
    for (int p = 0; p < 4; p++) acc[q][p] = 0.f;

  for (int cb = 0; cb < 32; cb += 8) {
    __syncthreads();
#pragma unroll
    for (int t = tid; t < 8 * 10 * 5; t += 128) {
      int c   = t / 50;
      int rem = t - c * 50;
      int r   = rem / 5;
      int q   = rem - r * 5;
      const float4 v = *reinterpret_cast<const float4*>(
          inN + (size_t)(cb + c) * PLC + (y0 + r + 4) * 120 + x0 + 4 * q + 4);
      float* dst = &s_in[c * PLS + r * RS + 4 * q];
      dst[0] = v.x; dst[1] = v.y; dst[2] = v.z; dst[3] = v.w;
    }
    for (int t = tid; t < 16 * 8 * 9; t += 128) {
      int lco = t & 15;
      int rem = t >> 4;
      int k   = rem % 9;
      int lci = rem / 9;
      s_w[(lci * 9 + k) * 16 + lco] =
          w[((coB + lco) * 32 + cb + lci) * 9 + k];
    }
    __syncthreads();

#pragma unroll
    for (int ci = 0; ci < 8; ci++) {
#pragma unroll
      for (int ky = 0; ky < 3; ky++) {
        float r[6];
#pragma unroll
        for (int j = 0; j < 6; j++)
          r[j] = s_in[ci * PLS + (py + ky) * RS + pxg * 4 + j];
#pragma unroll
        for (int kx = 0; kx < 3; kx++) {
          float4 wv =
              reinterpret_cast<const float4*>(s_w)[(ci * 9 + ky * 3 + kx) * 4 + cg];
#pragma unroll
          for (int p = 0; p < 4; p++) {
            float iv = r[p + kx];
            acc[0][p] += wv.x * iv;
            acc[1][p] += wv.y * iv;
            acc[2][p] += wv.z * iv;
            acc[3][p] += wv.w * iv;
          }
        }
      }
    }
  }

  float* outN = out + (size_t)n * 96 * PLV;
  const int gy = y0 + py;
#pragma unroll
  for (int q = 0; q < 4; q++) {
    int co = coB + cg * 4 + q;
#pragma unroll
    for (int p = 0; p < 4; p++)
      outN[(size_t)co * PLV + gy * 112 + x0 + pxg * 4 + p] = acc[q][p];
  }
}

// ---------------------------------------------------------------------------
// combine: x1 = U + shift(V) on ALL pixels; also produces raw stats sums.
// ---------------------------------------------------------------------------
__global__ void __launch_bounds__(256) combine_k() {
  const int bid = blockIdx.x;
  const int co = bid % 96, n = bid / 96;
  const int b = n / 49, d = n % 49;
  const int di = d / 7 - 3, dj = d % 7 - 3;

  const float* U = g_U + ((size_t)(b * 96 + co)) * PL1;
  const float* V = g_V + ((size_t)(b * 96 + co)) * PLV + (dj + 3) * 112 + (di + 3);
  float* X = g_x1 + ((size_t)(n * 96 + co)) * PL1;

  const int wid = threadIdx.x >> 5, xl = threadIdx.x & 31;
  float s = 0.f, q = 0.f;
  for (int y = wid; y < 64; y += 8) {
    const int ro = (y + 1) * 100 + 1;
    const int rv = y * 112;
#pragma unroll
    for (int x = xl; x < 96; x += 32) {
      float v = U[ro + x] + V[rv + x];
      X[ro + x] = v;
      s += v; q += v * v;
    }
  }
#pragma unroll
  for (int o = 16; o > 0; o >>= 1) {
    s += __shfl_xor_sync(0xffffffffu, s, o);
    q += __shfl_xor_sync(0xffffffffu, q, o);
  }
  __shared__ float ss[8], sq[8];
  if (xl == 0) { ss[wid] = s; sq[wid] = q; }
  __syncthreads();
  if (threadIdx.x == 0) {
    float S = 0.f, Q = 0.f;
#pragma unroll
    for (int i = 0; i < 8; i++) { S += ss[i]; Q += sq[i]; }
    g_r1S[bid] = S;
    g_r1Q[bid] = Q;
  }
}

// ---------------------------------------------------------------------------
// stripdelta: subtract BOTH border corrections from x1 on the 4-px frame and
// emit per-segment stat deltas (deterministic slots; zeros if inactive).
// ---------------------------------------------------------------------------
__global__ void __launch_bounds__(128)
stripdelta_k(const float* __restrict__ f1, const float* __restrict__ f2,
             const float* __restrict__ w1) {
  const int sid = blockIdx.x;   // 0..9
  const int n   = blockIdx.y;
  const int y0 = d_segy[sid], x0 = d_segx[sid];
  const int h  = d_segh[sid], w = d_segw[sid];
  const int b = n / 49, d = n % 49;
  const int di = d / 7 - 3;
  const int dj = d % 7 - 3;

  const int tid = threadIdx.x;
  float* dS = g_d1S + (size_t)(n * 10 + sid) * 96;
  float* dQ = g_d1Q + (size_t)(n * 10 + sid) * 96;

  // per-half activity
  bool af1, af2;
  {
    int rlo = y0 > 0 ? y0 - 1 : 0;
    int rhi = (y0 + h < 64) ? y0 + h : 63;
    int clo = x0 > 0 ? x0 - 1 : 0;
    int chi = (x0 + w < 96) ? x0 + w : 95;
    af1 = (dj < 0 && rlo < -dj) || (dj > 0 && rhi >= 64 - dj) ||
          (di < 0 && clo < -di) || (di > 0 && chi >= 96 - di);
    af2 = (y0 == 0 && dj > 0) || (y0 + h == 64 && dj < 0) ||
          (x0 == 0 && di > 0) || (x0 + w == 96 && di < 0);
    if (!af1 && !af2) {
      if (tid < 96) { dS[tid] = 0.f; dQ[tid] = 0.f; }
      return;
    }
  }
  const int cbLo = af1 ? 0 : 32;
  const int cbHi = af2 ? 64 : 32;

  const int H2 = h + 2, W2 = w + 2;

  __shared__ float s_in[8 * 204];                  // max H2*W2 = 6*34 = 204
  __shared__ __align__(16) float s_w[8 * 9 * 32];
  __shared__ float sredS[4][32], sredQ[4][32];

  const bool pact = tid < h * w;
  const int py = pact ? tid / w : 0;
  const int px = pact ? tid % w : 0;
  const int wwid = tid >> 5, lane = tid & 31;

  const float* f1b = f1 + (size_t)b * 32 * 6144;
  const float* f2b = f2 + (size_t)b * 32 * 6144;

  for (int coc = 0; coc < 3; coc++) {
    float acc[32];
#pragma unroll
    for (int c = 0; c < 32; c++) acc[c] = 0.f;

    for (int cb = cbLo; cb < cbHi; cb += 8) {
      __syncthreads();
      for (int t = tid; t < 8 * H2 * W2; t += 128) {
        int ci  = t / (H2 * W2);
        int rem = t - ci * (H2 * W2);
        int r   = rem / W2;
        int c   = rem - r * W2;
        int yy = y0 - 1 + r, xx = x0 - 1 + c;
        int cic = cb + ci;
        float v = 0.f;
        bool inimg  = (unsigned)yy < 64u && (unsigned)xx < 96u;
        if (cic < 32) {
          bool inmask = (unsigned)(yy + dj) < 64u && (unsigned)(xx + di) < 96u;
          if (inimg && !inmask)
            v = f1b[cic * 6144 + yy * 96 + xx];
        } else {
          int sy = yy + dj, sx = xx + di;
          if (!inimg && (unsigned)sy < 64u && (unsigned)sx < 96u)
            v = f2b[(cic - 32) * 6144 + sy * 96 + sx];
        }
        s_in[ci * 204 + r * W2 + c] = v;
      }
      for (int t = tid; t < 32 * 8 * 9; t += 128) {
        int co  = t & 31;
        int rem = t >> 5;
        int k   = rem % 9;
        int ci  = rem / 9;
        s_w[(ci * 9 + k) * 32 + co] =
            w1[((coc * 32 + co) * 64 + cb + ci) * 9 + k];
      }
      __syncthreads();

      if (pact) {
#pragma unroll
        for (int ci = 0; ci < 8; ci++)
#pragma unroll
          for (int ky = 0; ky < 3; ky++)
#pragma unroll
            for (int kx = 0; kx < 3; kx++) {
              float v = s_in[ci * 204 + (py + ky) * W2 + (px + kx)];
              const float4* wv = reinterpret_cast<const float4*>(
                  &s_w[(ci * 9 + ky * 3 + kx) * 32]);
#pragma unroll
              for (int q = 0; q < 8; q++) {
                float4 ww = wv[q];
                acc[4 * q + 0] += ww.x * v;
                acc[4 * q + 1] += ww.y * v;
                acc[4 * q + 2] += ww.z * v;
                acc[4 * q + 3] += ww.w * v;
              }
            }
      }
    }
    // subtract + per-channel stat deltas (deterministic reduce)
#pragma unroll 4
    for (int c = 0; c < 32; c++) {
      float a = acc[c];
      float old = 0.f;
      if (pact) {
        float* p = &g_x1[((size_t)n * 96 + coc * 32 + c) * PL1 +
                         (y0 + py + 1) * 100 + (x0 + px + 1)];
        old = *p;
        *p = old - a;
      }
      float ds = -a;
      float dq = a * a - 2.f * old * a;
#pragma unroll
      for (int o = 16; o > 0; o >>= 1) {
        ds += __shfl_xor_sync(0xffffffffu, ds, o);
        dq += __shfl_xor_sync(0xffffffffu, dq, o);
      }
      if (lane == 0) { sredS[wwid][c] = ds; sredQ[wwid][c] = dq; }
    }
    __syncthreads();
    if (tid < 32) {
      float S = sredS[0][tid] + sredS[1][tid] + sredS[2][tid] + sredS[3][tid];
      float Q = sredQ[0][tid] + sredQ[1][tid] + sredQ[2][tid] + sredQ[3][tid];
      dS[coc * 32 + tid] = S;
      dQ[coc * 32 + tid] = Q;
    }
    __syncthreads();
  }
}

// ---------------------------------------------------------------------------
// finalize1: per-(n,co<96) combine raw sums + 10 segment deltas -> mean/rsqrt
// ---------------------------------------------------------------------------
__global__ void __launch_bounds__(256)
finalize1_k() {
  int idx = blockIdx.x * blockDim.x + threadIdx.x;
  if (idx >= NIMG * 96) return;
  int n = idx / 96, co = idx % 96;
  float S = g_r1S[idx], Q = g_r1Q[idx];
#pragma unroll
  for (int s = 0; s < 10; s++) {
    S += g_d1S[(size_t)(n * 10 + s) * 96 + co];
    Q += g_d1Q[(size_t)(n * 10 + s) * 96 + co];
  }
  float m = S / 6144.f;
  float var = Q / 6144.f - m * m;
  g_stm[n * 96 + co] = m;
  g_sti[n * 96 + co] = rsqrtf(var + 1e-5f);
}

// ---------------------------------------------------------------------------
// apply norm+leaky to planar x1, transpose to ch-last, split bf16 hi/lo
// ---------------------------------------------------------------------------
__global__ void __launch_bounds__(256)
apply_x1cl_k() {
  __shared__ float s[96 * 97];
  const int y = blockIdx.x;   // 0..63
  const int n = blockIdx.y;
  const int tid = threadIdx.x;
  const int wid = tid >> 5, ln = tid & 31;

  for (int ci = wid; ci < 96; ci += 8) {
    const float* src = g_x1 + ((size_t)(n * 96 + ci)) * PL1 + (y + 1) * 100 + 1;
    for (int x = ln; x < 96; x += 32) s[x * 97 + ci] = src[x];
  }
  __syncthreads();
  for (int idx = tid; idx < 96 * 96; idx += 256) {
    int x = idx / 96, ci = idx % 96;
    float m = g_stm[n * 96 + ci], iv = g_sti[n * 96 + ci];
    float v = (s[x * 97 + ci] - m) * iv;
    v = v >= 0.f ? v : 0.01f * v;
    size_t o = ((size_t)(n * 6600 + (y + 1) * 100 + (x + 1))) * 96 + ci;
    bf16_split(v, g_X1h[o], g_X1l[o]);
  }
}

// ---------------------------------------------------------------------------
// finalizeG: per-(n,ci<C) sum NB gemm-block partial slots -> mean/rsqrt
// ---------------------------------------------------------------------------
template <int C, int NB, int NPX>
__global__ void finalizeG_k() {
  const int n = blockIdx.x;
  const int ci = threadIdx.x;   // blockDim = C
  float S = 0.f, Q = 0.f;
#pragma unroll 4
  for (int k = 0; k < NB; k++) {
    size_t base = ((size_t)n * 48 + k) * 256 + ci * 2;
    S += g_gp[base];
    Q += g_gp[base + 1];
  }
  float m = S / (float)NPX;
  float var = Q / (float)NPX - m * m;
  g_stm[n * 128 + ci] = m;
  g_sti[n * 128 + ci] = rsqrtf(var + 1e-5f);
}

// ---------------------------------------------------------------------------
// apply norm+leaky (C=128) -> bf16 hi/lo padded ch-last (g_Xh/g_Xl)
// ---------------------------------------------------------------------------
__global__ void __launch_bounds__(256)
apply_cl128_k(const float* __restrict__ xcl) {
  const int y = blockIdx.x;   // 0..31
  const int n = blockIdx.y;
  const int tid = threadIdx.x;
  for (int idx = tid; idx < 48 * 128; idx += 256) {
    int x = idx >> 7, ci = idx & 127;
    float m = g_stm[n * 128 + ci], iv = g_sti[n * 128 + ci];
    float v = (xcl[((size_t)(n * 1536 + y * 48 + x)) * 128 + ci] - m) * iv;
    v = v >= 0.f ? v : 0.01f * v;
    size_t o = ((size_t)(n * 1768 + (y + 1) * 52 + (x + 1))) * 128 + ci;
    bf16_split(v, g_Xh[o], g_Xl[o]);
  }
}

// ---------------------------------------------------------------------------
// apply norm+leaky (C=64) -> bf16 hi/lo padded ch-last (g_X4h/g_X4l)
// ---------------------------------------------------------------------------
__global__ void __launch_bounds__(256)
apply_cl64_k(const float* __restrict__ xcl) {
  const int y = blockIdx.x;   // 0..31
  const int n = blockIdx.y;
  const int tid = threadIdx.x;
  for (int idx = tid; idx < 48 * 64; idx += 256) {
    int x = idx >> 6, ci = idx & 63;
    float m = g_stm[n * 128 + ci], iv = g_sti[n * 128 + ci];
    float v = (xcl[((size_t)(n * 1536 + y * 48 + x)) * 64 + ci] - m) * iv;
    v = v >= 0.f ? v : 0.01f * v;
    size_t o = ((size_t)(n * 1768 + (y + 1) * 52 + (x + 1))) * 64 + ci;
    bf16_split(v, g_X4h[o], g_X4l[o]);
  }
}

// ---------------------------------------------------------------------------
// apply norm+leaky to x5cl [n][par][1536][32] -> planar padded g_x5
// ---------------------------------------------------------------------------
__global__ void __launch_bounds__(256)
apply_x5_planar_k() {
  const int yq = blockIdx.x;  // 0..31 (y')
  const int n  = blockIdx.y;
  const int tid = threadIdx.x;
  float* outN = g_x5 + (size_t)n * 32 * PL1;

  for (int par = 0; par < 4; par++) {
    const int a = par >> 1, b = par & 1;
    const float* src = g_x5cl + ((size_t)(n * 4 + par) * 1536 + yq * 48) * 32;
    const int oy = 2 * yq + a + 1;
    for (int idx = tid; idx < 48 * 32; idx += 256) {
      int x = idx >> 5, co = idx & 31;
      float m = g_stm[n * 128 + co], iv = g_sti[n * 128 + co];
      float v = (src[x * 32 + co] - m) * iv;
      v = v >= 0.f ? v : 0.01f * v;
      outN[(size_t)co * PL1 + oy * 100 + 2 * x + b + 1] = v;
    }
  }
}

// ---------------------------------------------------------------------------
// gemm2: conv2 (stride 2), M-tile 96, N=128, Cin=96. cp.async 2-stage.
// dyn smem: A 2*15360 + B 2*20480 = 71680 B.  Epilogue emits stats partials.
// ---------------------------------------------------------------------------
__global__ void __launch_bounds__(256)
gemm2_k(float* __restrict__ xcl) {
  extern __shared__ __align__(16) unsigned short dynsm[];
  const int tid  = threadIdx.x;
  const int wid  = tid >> 5, lane = tid & 31;
  const int warp_m = wid & 1;
  const int warp_n = wid >> 1;
  const int tile = blockIdx.x;
  const int n    = blockIdx.y;
  const int px0  = tile * 96;

  const uint32_t aB = smem_u32(dynsm);
  const uint32_t bB = aB + 30720;

  float acc[3][4][4];
#pragma unroll
  for (int mi = 0; mi < 3; mi++)
#pragma unroll
    for (int ni = 0; ni < 4; ni++)
#pragma unroll
      for (int j = 0; j < 4; j++) acc[mi][ni][j] = 0.f;

  auto load_chunk = [&](int t, int stg) {
    int tap = t / 3, cc = t - tap * 3;
    int dy = tap / 3, dx = tap % 3, ci0 = cc * 32;
#pragma unroll
    for (int i = 0; i < 3; i++) {
      int id  = tid + i * 256;
      int hl  = id / 384;
      int rem = id - hl * 384;
      int r = rem >> 2, q = rem & 3;
      int px = px0 + r;
      int y = px / 48, x = px - y * 48;
      int pos = (2 * y + dy) * 100 + (2 * x + dx);
      const unsigned short* src =
          (hl ? g_X1l : g_X1h) + ((size_t)(n * 6600 + pos)) * 96 + ci0 + q * 8;
      cp_async16(aB + (uint32_t)(stg * 15360 + hl * 7680 + (r * 40 + q * 8) * 2), src);
    }
#pragma unroll
    for (int i = 0; i < 4; i++) {
      int id  = tid + i * 256;
      int hl  = id >> 9;
      int rem = id & 511;
      int r = rem >> 2, q = rem & 3;
      const unsigned short* src =
          (hl ? g_B2l : g_B2h) + ((size_t)(tap * 128 + r)) * 96 + ci0 + q * 8;
      cp_async16(bB + (uint32_t)(stg * 20480 + hl * 10240 + (r * 40 + q * 8) * 2), src);
    }
  };

  load_chunk(0, 0); CP_COMMIT();
  for (int t = 0; t < 27; t++) {
    int stg = t & 1;
    if (t + 1 < 27) { load_chunk(t + 1, stg ^ 1); CP_COMMIT(); CP_WAIT(1); }
    else CP_WAIT(0);
    __syncthreads();

    const uint32_t aH = aB + stg * 15360, aL = aH + 7680;
    const uint32_t bH = bB + stg * 20480, bL = bH + 10240;
#pragma unroll
    for (int ks = 0; ks < 2; ks++) {
      unsigned ah[3][4], al[3][4], bh[4][2], bl[4][2];
      const int arow = warp_m * 48 + (lane & 7) + ((lane >> 3) & 1) * 8;
      const int acol = ks * 16 + ((lane >> 4) & 1) * 8;
#pragma unroll
      for (int mi = 0; mi < 3; mi++) {
        uint32_t off = (uint32_t)(((arow + mi * 16) * 40 + acol) * 2);
        ldsm_x4(ah[mi], aH + off);
        ldsm_x4(al[mi], aL + off);
      }
      const int brow = warp_n * 32 + (lane & 7);
      const int bcol = ks * 16 + ((lane >> 3) & 1) * 8;
#pragma unroll
      for (int ni = 0; ni < 4; ni++) {
        uint32_t off = (uint32_t)(((brow + ni * 8) * 40 + bcol) * 2);
        ldsm_x2(bh[ni], bH + off);
        ldsm_x2(bl[ni], bL + off);
      }
#pragma unroll
      for (int mi = 0; mi < 3; mi++)
#pragma unroll
        for (int ni = 0; ni < 4; ni++) {
          mma_bf16(acc[mi][ni], ah[mi], bh[ni]);
          mma_bf16(acc[mi][ni], ah[mi], bl[ni]);
          mma_bf16(acc[mi][ni], al[mi], bh[ni]);
        }
    }
    __syncthreads();
  }

  const int g = lane >> 2, tg = lane & 3;
#pragma unroll
  for (int mi = 0; mi < 3; mi++)
#pragma unroll
    for (int ni = 0; ni < 4; ni++) {
      int row = px0 + warp_m * 48 + mi * 16 + g;
      int co  = warp_n * 32 + ni * 8 + tg * 2;
      float* d0 = xcl + ((size_t)(n * 1536 + row)) * 128 + co;
      float* d1 = xcl + ((size_t)(n * 1536 + row + 8)) * 128 + co;
      *reinterpret_cast<float2*>(d0) = make_float2(acc[mi][ni][0], acc[mi][ni][1]);
      *reinterpret_cast<float2*>(d1) = make_float2(acc[mi][ni][2], acc[mi][ni][3]);
    }

  // stats epilogue (deterministic): scratch = dynsm reused as float
  float* sS = reinterpret_cast<float*>(dynsm);    // 128*16
  float* sQ = sS + 2048;
  const int contrib = warp_m * 8 + g;
#pragma unroll
  for (int ni = 0; ni < 4; ni++) {
    float se = 0, so = 0, qe = 0, qo = 0;
#pragma unroll
    for (int mi = 0; mi < 3; mi++) {
      float a0 = acc[mi][ni][0], a1 = acc[mi][ni][1];
      float a2 = acc[mi][ni][2], a3 = acc[mi][ni][3];
      se += a0 + a2; so += a1 + a3;
      qe += a0 * a0 + a2 * a2; qo += a1 * a1 + a3 * a3;
    }
    int co = warp_n * 32 + ni * 8 + tg * 2;
    sS[co * 16 + contrib] = se; sS[(co + 1) * 16 + contrib] = so;
    sQ[co * 16 + contrib] = qe; sQ[(co + 1) * 16 + contrib] = qo;
  }
  __syncthreads();
  if (tid < 128) {
    float S = 0, Q = 0;
#pragma unroll
    for (int k = 0; k < 16; k++) { S += sS[tid * 16 + k]; Q += sQ[tid * 16 + k]; }
    size_t slot = ((size_t)n * 48 + tile) * 256 + tid * 2;
    g_gp[slot] = S; g_gp[slot + 1] = Q;
  }
}

// ---------------------------------------------------------------------------
// gemm3: conv3, N=128, Cin=128. cp.async 2-stage + stats epilogue.
// ---------------------------------------------------------------------------
__global__ void __launch_bounds__(256)
gemm3_k(float* __restrict__ xcl) {
  extern __shared__ __align__(16) unsigned short dynsm[];
  const int tid  = threadIdx.x;
  const int wid  = tid >> 5, lane = tid & 31;
  const int warp_m = wid & 1;
  const int warp_n = wid >> 1;
  const int tile = blockIdx.x;
  const int n    = blockIdx.y;
  const int px0  = tile * 96;

  const uint32_t aB = smem_u32(dynsm);
  const uint32_t bB = aB + 30720;

  float acc[3][4][4];
#pragma unroll
  for (int mi = 0; mi < 3; mi++)
#pragma unroll
    for (int ni = 0; ni < 4; ni++)
#pragma unroll
      for (int j = 0; j < 4; j++) acc[mi][ni][j] = 0.f;

  auto load_chunk = [&](int t, int stg) {
    int tap = t >> 2, cc = t & 3;
    int dy = tap / 3, dx = tap % 3, ci0 = cc * 32;
#pragma unroll
    for (int i = 0; i < 3; i++) {
      int id  = tid + i * 256;
      int hl  = id / 384;
      int rem = id - hl * 384;
      int r = rem >> 2, q = rem & 3;
      int px = px0 + r;
      int y = px / 48, x = px - y * 48;
      int pos = (y + dy) * 52 + (x + dx);
      const unsigned short* src =
          (hl ? g_Xl : g_Xh) + ((size_t)(n * 1768 + pos)) * 128 + ci0 + q * 8;
      cp_async16(aB + (uint32_t)(stg * 15360 + hl * 7680 + (r * 40 + q * 8) * 2), src);
    }
#pragma unroll
    for (int i = 0; i < 4; i++) {
      int id  = tid + i * 256;
      int hl  = id >> 9;
      int rem = id & 511;
      int r = rem >> 2, q = rem & 3;
      const unsigned short* src =
          (hl ? g_B3l : g_B3h) + ((size_t)(tap * 128 + r)) * 128 + ci0 + q * 8;
      cp_async16(bB + (uint32_t)(stg * 20480 + hl * 10240 + (r * 40 + q * 8) * 2), src);
    }
  };

  load_chunk(0, 0); CP_COMMIT();
  for (int t = 0; t < 36; t++) {
    int stg = t & 1;
    if (t + 1 < 36) { load_chunk(t + 1, stg ^ 1); CP_COMMIT(); CP_WAIT(1); }
    else CP_WAIT(0);
    __syncthreads();

    const uint32_t aH = aB + stg * 15360, aL = aH + 7680;
    const uint32_t bH = bB + stg * 20480, bL = bH + 10240;
#pragma unroll
    for (int ks = 0; ks < 2; ks++) {
      unsigned ah[3][4], al[3][4], bh[4][2], bl[4][2];
      const int arow = warp_m * 48 + (lane & 7) + ((lane >> 3) & 1) * 8;
      const int acol = ks * 16 + ((lane >> 4) & 1) * 8;
#pragma unroll
      for (int mi = 0; mi < 3; mi++) {
        uint32_t off = (uint32_t)(((arow + mi * 16) * 40 + acol) * 2);
        ldsm_x4(ah[mi], aH + off);
        ldsm_x4(al[mi], aL + off);
      }
      const int brow = warp_n * 32 + (lane & 7);
      const int bcol = ks * 16 + ((lane >> 3) & 1) * 8;
#pragma unroll
      for (int ni = 0; ni < 4; ni++) {
        uint32_t off = (uint32_t)(((brow + ni * 8) * 40 + bcol) * 2);
        ldsm_x2(bh[ni], bH + off);
        ldsm_x2(bl[ni], bL + off);
      }
#pragma unroll
      for (int mi = 0; mi < 3; mi++)
#pragma unroll
        for (int ni = 0; ni < 4; ni++) {
          mma_bf16(acc[mi][ni], ah[mi], bh[ni]);
          mma_bf16(acc[mi][ni], ah[mi], bl[ni]);
          mma_bf16(acc[mi][ni], al[mi], bh[ni]);
        }
    }
    __syncthreads();
  }

  const int g = lane >> 2, tg = lane & 3;
#pragma unroll
  for (int mi = 0; mi < 3; mi++)
#pragma unroll
    for (int ni = 0; ni < 4; ni++) {
      int row = px0 + warp_m * 48 + mi * 16 + g;
      int co  = warp_n * 32 + ni * 8 + tg * 2;
      float* d0 = xcl + ((size_t)(n * 1536 + row)) * 128 + co;
      float* d1 = xcl + ((size_t)(n * 1536 + row + 8)) * 128 + co;
      *reinterpret_cast<float2*>(d0) = make_float2(acc[mi][ni][0], acc[mi][ni][1]);
      *reinterpret_cast<float2*>(d1) = make_float2(acc[mi][ni][2], acc[mi][ni][3]);
    }

  float* sS = reinterpret_cast<float*>(dynsm);
  float* sQ = sS + 2048;
  const int contrib = warp_m * 8 + g;
#pragma unroll
  for (int ni = 0; ni < 4; ni++) {
    float se = 0, so = 0, qe = 0, qo = 0;
#pragma unroll
    for (int mi = 0; mi < 3; mi++) {
      float a0 = acc[mi][ni][0], a1 = acc[mi][ni][1];
      float a2 = acc[mi][ni][2], a3 = acc[mi][ni][3];
      se += a0 + a2; so += a1 + a3;
      qe += a0 * a0 + a2 * a2; qo += a1 * a1 + a3 * a3;
    }
    int co = warp_n * 32 + ni * 8 + tg * 2;
    sS[co * 16 + contrib] = se; sS[(co + 1) * 16 + contrib] = so;
    sQ[co * 16 + contrib] = qe; sQ[(co + 1) * 16 + contrib] = qo;
  }
  __syncthreads();
  if (tid < 128) {
    float S = 0, Q = 0;
#pragma unroll
    for (int k = 0; k < 16; k++) { S += sS[tid * 16 + k]; Q += sQ[tid * 16 + k]; }
    size_t slot = ((size_t)n * 48 + tile) * 256 + tid * 2;
    g_gp[slot] = S; g_gp[slot + 1] = Q;
  }
}

// ---------------------------------------------------------------------------
// gemm4: conv4, N=64, Cin=128. cp.async 2-stage + stats epilogue.
// ---------------------------------------------------------------------------
__global__ void __launch_bounds__(256)
gemm4_k(float* __restrict__ xcl) {
  extern __shared__ __align__(16) unsigned short dynsm[];
  const int tid  = threadIdx.x;
  const int wid  = tid >> 5, lane = tid & 31;
  const int warp_m = wid & 1;
  const int warp_n = wid >> 1;
  const int tile = blockIdx.x;
  const int n    = blockIdx.y;
  const int px0  = tile * 96;

  const uint32_t aB = smem_u32(dynsm);
  const uint32_t bB = aB + 30720;

  float acc[3][2][4];
#pragma unroll
  for (int mi = 0; mi < 3; mi++)
#pragma unroll
    for (int ni = 0; ni < 2; ni++)
#pragma unroll
      for (int j = 0; j < 4; j++) acc[mi][ni][j] = 0.f;

  auto load_chunk = [&](int t, int stg) {
    int tap = t >> 2, cc = t & 3;
    int dy = tap / 3, dx = tap % 3, ci0 = cc * 32;
#pragma unroll
    for (int i = 0; i < 3; i++) {
      int id  = tid + i * 256;
      int hl  = id / 384;
      int rem = id - hl * 384;
      int r = rem >> 2, q = rem & 3;
      int px = px0 + r;
      int y = px / 48, x = px - y * 48;
      int pos = (y + dy) * 52 + (x + dx);
      const unsigned short* src =
          (hl ? g_Xl : g_Xh) + ((size_t)(n * 1768 + pos)) * 128 + ci0 + q * 8;
      cp_async16(aB + (uint32_t)(stg * 15360 + hl * 7680 + (r * 40 + q * 8) * 2), src);
    }
#pragma unroll
    for (int i = 0; i < 2; i++) {
      int id  = tid + i * 256;
      int hl  = id >> 8;
      int rem = id & 255;
      int r = rem >> 2, q = rem & 3;
      const unsigned short* src =
          (hl ? g_B4l : g_B4h) + ((size_t)(tap * 64 + r)) * 128 + ci0 + q * 8;
      cp_async16(bB + (uint32_t)(stg * 10240 + hl * 5120 + (r * 40 + q * 8) * 2), src);
    }
  };

  load_chunk(0, 0); CP_COMMIT();
  for (int t = 0; t < 36; t++) {
    int stg = t & 1;
    if (t + 1 < 36) { load_chunk(t + 1, stg ^ 1); CP_COMMIT(); CP_WAIT(1); }
    else CP_WAIT(0);
    __syncthreads();

    const uint32_t aH = aB + stg * 15360, aL = aH + 7680;
    const uint32_t bH = bB + stg * 10240, bL = bH + 5120;
#pragma unroll
    for (int ks = 0; ks < 2; ks++) {
      unsigned ah[3][4], al[3][4], bh[2][2], bl[2][2];
      const int arow = warp_m * 48 + (lane & 7) + ((lane >> 3) & 1) * 8;
      const int acol = ks * 16 + ((lane >> 4) & 1) * 8;
#pragma unroll
      for (int mi = 0; mi < 3; mi++) {
        uint32_t off = (uint32_t)(((arow + mi * 16) * 40 + acol) * 2);
        ldsm_x4(ah[mi], aH + off);
        ldsm_x4(al[mi], aL + off);
      }
      const int brow = warp_n * 16 + (lane & 7);
      const int bcol = ks * 16 + ((lane >> 3) & 1) * 8;
#pragma unroll
      for (int ni = 0; ni < 2; ni++) {
        uint32_t off = (uint32_t)(((brow + ni * 8) * 40 + bcol) * 2);
        ldsm_x2(bh[ni], bH + off);
        ldsm_x2(bl[ni], bL + off);
      }
#pragma unroll
      for (int mi = 0; mi < 3; mi++)
#pragma unroll
        for (int ni = 0; ni < 2; ni++) {
          mma_bf16(acc[mi][ni], ah[mi], bh[ni]);
          mma_bf16(acc[mi][ni], ah[mi], bl[ni]);
          mma_bf16(acc[mi][ni], al[mi], bh[ni]);
        }
    }
    __syncthreads();
  }

  const int g = lane >> 2, tg = lane & 3;
#pragma unroll
  for (int mi = 0; mi < 3; mi++)
#pragma unroll
    for (int ni = 0; ni < 2; ni++) {
      int row = px0 + warp_m * 48 + mi * 16 + g;
      int co  = warp_n * 16 + ni * 8 + tg * 2;
      float* d0 = xcl + ((size_t)(n * 1536 + row)) * 64 + co;
      float* d1 = xcl + ((size_t)(n * 1536 + row + 8)) * 64 + co;
      *reinterpret_cast<float2*>(d0) = make_float2(acc[mi][ni][0], acc[mi][ni][1]);
      *reinterpret_cast<float2*>(d1) = make_float2(acc[mi][ni][2], acc[mi][ni][3]);
    }

  float* sS = reinterpret_cast<float*>(dynsm);    // 64*16
  float* sQ = sS + 1024;
  const int contrib = warp_m * 8 + g;
#pragma unroll
  for (int ni = 0; ni < 2; ni++) {
    float se = 0, so = 0, qe = 0, qo = 0;
#pragma unroll
    for (int mi = 0; mi < 3; mi++) {
      float a0 = acc[mi][ni][0], a1 = acc[mi][ni][1];
      float a2 = acc[mi][ni][2], a3 = acc[mi][ni][3];
      se += a0 + a2; so += a1 + a3;
      qe += a0 * a0 + a2 * a2; qo += a1 * a1 + a3 * a3;
    }
    int co = warp_n * 16 + ni * 8 + tg * 2;
    sS[co * 16 + contrib] = se; sS[(co + 1) * 16 + contrib] = so;
    sQ[co * 16 + contrib] = qe; sQ[(co + 1) * 16 + contrib] = qo;
  }
  __syncthreads();
  if (tid < 64) {
    float S = 0, Q = 0;
#pragma unroll
    for (int k = 0; k < 16; k++) { S += sS[tid * 16 + k]; Q += sQ[tid * 16 + k]; }
    size_t slot = ((size_t)n * 48 + tile) * 256 + tid * 2;
    g_gp[slot] = S; g_gp[slot + 1] = Q;
  }
}

// ---------------------------------------------------------------------------
// gemm5: deconv per parity, M-tile 128, N=32, K=4x64. cp.async 2-stage +
// stats epilogue (slot = par*12+tile; 48 slots accumulate over parities).
// ---------------------------------------------------------------------------
__global__ void __launch_bounds__(256)
gemm5_k() {
  extern __shared__ __align__(16) unsigned short dynsm[];
  const int tid  = threadIdx.x;
  const int wid  = tid >> 5, lane = tid & 31;   // warp_m = wid (0..7)
  const int tile = blockIdx.x;                  // 0..11
  const int par  = blockIdx.y;                  // 0..3
  const int n    = blockIdx.z;
  const int a = par >> 1, b = par & 1;
  const int px0 = tile * 128;

  const uint32_t aB = smem_u32(dynsm);
  const uint32_t bB = aB + 40960;

  float acc[4][4];
#pragma unroll
  for (int ni = 0; ni < 4; ni++)
#pragma unroll
    for (int j = 0; j < 4; j++) acc[ni][j] = 0.f;

  auto load_chunk = [&](int t, int stg) {
    int tap = t >> 1, cc = t & 1;
    int s = tap >> 1, tt = tap & 1, ci0 = cc * 32;
#pragma unroll
    for (int i = 0; i < 4; i++) {
      int id  = tid + i * 256;
      int hl  = id >> 9;
      int rem = id & 511;
      int r = rem >> 2, q = rem & 3;
      int px = px0 + r;
      int y = px / 48, x = px - y * 48;
      int pos = (y + a + s) * 52 + (x + b + tt);
      const unsigned short* src =
          (hl ? g_X4l : g_X4h) + ((size_t)(n * 1768 + pos)) * 64 + ci0 + q * 8;
      cp_async16(aB + (uint32_t)(stg * 20480 + hl * 10240 + (r * 40 + q * 8) * 2), src);
    }
    {
      int hl  = tid >> 7;
      int rem = tid & 127;
      int r = rem >> 2, q = rem & 3;
      const unsigned short* src =
          (hl ? g_B5l : g_B5h) + ((size_t)((par * 4 + tap) * 32 + r)) * 64 + ci0 + q * 8;
      cp_async16(bB + (uint32_t)(stg * 5120 + hl * 2560 + (r * 40 + q * 8) * 2), src);
    }
  };

  load_chunk(0, 0); CP_COMMIT();
  for (int t = 0; t < 8; t++) {
    int stg = t & 1;
    if (t + 1 < 8) { load_chunk(t + 1, stg ^ 1); CP_COMMIT(); CP_WAIT(1); }
    else CP_WAIT(0);
    __syncthreads();

    const uint32_t aH = aB + stg * 20480, aL = aH + 10240;
    const uint32_t bH = bB + stg * 5120, bL = bH + 2560;
#pragma unroll
    for (int ks = 0; ks < 2; ks++) {
      unsigned ah[4], al[4], bh[4][2], bl[4][2];
      const int arow = wid * 16 + (lane & 7) + ((lane >> 3) & 1) * 8;
      const int acol = ks * 16 + ((lane >> 4) & 1) * 8;
      {
        uint32_t off = (uint32_t)((arow * 40 + acol) * 2);
        ldsm_x4(ah, aH + off);
        ldsm_x4(al, aL + off);
      }
      const int brow = lane & 7;
      const int bcol = ks * 16 + ((lane >> 3) & 1) * 8;
#pragma unroll
      for (int ni = 0; ni < 4; ni++) {
        uint32_t off = (uint32_t)(((brow + ni * 8) * 40 + bcol) * 2);
        ldsm_x2(bh[ni], bH + off);
        ldsm_x2(bl[ni], bL + off);
      }
#pragma unroll
      for (int ni = 0; ni < 4; ni++) {
        mma_bf16(acc[ni], ah, bh[ni]);
        mma_bf16(acc[ni], ah, bl[ni]);
        mma_bf16(acc[ni], al, bh[ni]);
      }
    }
    __syncthreads();
  }

  const int g = lane >> 2, tg = lane & 3;
  float* base = g_x5cl + ((size_t)(n * 4 + par)) * 1536 * 32;
#pragma unroll
  for (int ni = 0; ni < 4; ni++) {
    int row = px0 + wid * 16 + g;
    int co  = ni * 8 + tg * 2;
    *reinterpret_cast<float2*>(base + (size_t)row * 32 + co) =
        make_float2(acc[ni][0], acc[ni][1]);
    *reinterpret_cast<float2*>(base + (size_t)(row + 8) * 32 + co) =
        make_float2(acc[ni][2], acc[ni][3]);
  }

  // stats epilogue: 32 co x 64 contributors
  float* sS = reinterpret_cast<float*>(dynsm);    // 32*64
  float* sQ = sS + 2048;
  const int contrib = wid * 8 + g;
#pragma unroll
  for (int ni = 0; ni < 4; ni++) {
    float a0 = acc[ni][0], a1 = acc[ni][1], a2 = acc[ni][2], a3 = acc[ni][3];
    int co = ni * 8 + tg * 2;
    sS[co * 64 + contrib] = a0 + a2;
    sS[(co + 1) * 64 + contrib] = a1 + a3;
    sQ[co * 64 + contrib] = a0 * a0 + a2 * a2;
    sQ[(co + 1) * 64 + contrib] = a1 * a1 + a3 * a3;
  }
  __syncthreads();
  if (tid < 32) {
    float S = 0, Q = 0;
#pragma unroll 8
    for (int k = 0; k < 64; k++) { S += sS[tid * 64 + k]; Q += sQ[tid * 64 + k]; }
    size_t slot = ((size_t)n * 48 + par * 12 + tile) * 256 + tid * 2;
    g_gp[slot] = S; g_gp[slot + 1] = Q;
  }
}

// ---------------------------------------------------------------------------
// final conv 32->1 + bias (planar x5 -> d_out)
// ---------------------------------------------------------------------------
__global__ void __launch_bounds__(256)
conv_final_k(const float* __restrict__ in, const float* __restrict__ w6,
             const float* __restrict__ b6, float* __restrict__ out) {
  constexpr int RS = 37, PLS = 10 * RS;
  __shared__ float s_in[8 * PLS];
  __shared__ float sw[288];
  __shared__ float sb;

  const int tid = threadIdx.x;
  const int tx = blockIdx.x % 3;
  const int ty = blockIdx.x / 3;
  const int n  = blockIdx.y;
  const int y0 = ty * 8, x0 = tx * 32;
  const int px = tid & 31, py = tid >> 5;

  for (int t = tid; t < 288; t += 256) sw[t] = w6[t];
  if (tid == 0) sb = b6[0];

  const float* inN = in + (size_t)n * 32 * PL1;
  float acc = 0.f;

  for (int cb = 0; cb < 32; cb += 8) {
    __syncthreads();
#pragma unroll
    for (int t = tid; t < 8 * 10 * 9; t += 256) {
      int c   = t / 90;
      int rem = t - c * 90;
      int r   = rem / 9;
      int q   = rem - r * 9;
      const float4 v = *reinterpret_cast<const float4*>(
          inN + (size_t)(cb + c) * PL1 + (y0 + r) * 100 + x0 + 4 * q);
      float* dst = &s_in[c * PLS + r * RS + 4 * q];
      dst[0] = v.x; dst[1] = v.y; dst[2] = v.z; dst[3] = v.w;
    }
    __syncthreads();
#pragma unroll
    for (int c = 0; c < 8; c++)
#pragma unroll
      for (int ky = 0; ky < 3; ky++)
#pragma unroll
        for (int kx = 0; kx < 3; kx++)
          acc += sw[(cb + c) * 9 + ky * 3 + kx] *
                 s_in[c * PLS + (py + ky) * RS + px + kx];
  }

  out[(size_t)n * 6144 + (y0 + py) * 96 + x0 + px] = acc + sb;
}

// ---------------------------------------------------------------------------
// Launch
// ---------------------------------------------------------------------------
extern "C" void kernel_launch(void* const* d_in, const int* in_sizes, int n_in,
                              void* d_out, int out_size) {
  const float* f1 = (const float*)d_in[0];
  const float* f2 = (const float*)d_in[1];
  const float* w1 = (const float*)d_in[2];
  const float* w2 = (const float*)d_in[3];
  const float* w3 = (const float*)d_in[4];
  const float* w4 = (const float*)d_in[5];
  const float* w5 = (const float*)d_in[6];
  const float* w6 = (const float*)d_in[7];
  const float* b6 = (const float*)d_in[8];
  float* out = (float*)d_out;

  float *x5, *f1p, *f2c, *U, *V, *w1a, *w1b, *x2cl, *x3cl, *x4cl;
  cudaGetSymbolAddress((void**)&x5, g_x5);
  cudaGetSymbolAddress((void**)&f1p, g_f1p);
  cudaGetSymbolAddress((void**)&f2c, g_f2c);
  cudaGetSymbolAddress((void**)&U, g_U);
  cudaGetSymbolAddress((void**)&V, g_V);
  cudaGetSymbolAddress((void**)&w1a, g_w1a);
  cudaGetSymbolAddress((void**)&w1b, g_w1b);
  cudaGetSymbolAddress((void**)&x2cl, g_x2cl);
  cudaGetSymbolAddress((void**)&x3cl, g_x3cl);
  cudaGetSymbolAddress((void**)&x4cl, g_x4cl);

  // dyn smem opt-in (idempotent; safe each call)
  cudaFuncSetAttribute(gemm2_k, cudaFuncAttributeMaxDynamicSharedMemorySize, 71680);
  cudaFuncSetAttribute(gemm3_k, cudaFuncAttributeMaxDynamicSharedMemorySize, 71680);
  cudaFuncSetAttribute(gemm4_k, cudaFuncAttributeMaxDynamicSharedMemorySize, 51200);
  cudaFuncSetAttribute(gemm5_k, cudaFuncAttributeMaxDynamicSharedMemorySize, 51200);

  // merged prep
  prep_all_k<<<(2 * 32 * 6144 + 255) / 256, 256>>>(f1, f2, w1, w2, w3, w4, w5);

  // conv1 via factorization -> planar x1 + raw stats; border delta + deltas
  conv3x3_s1_k<32, 64, 96, 100><<<dim3(24, 6, 2), 256>>>(f1p, w1a, U, 32, 96);
  conv_v_k<<<dim3(63, 6, 2), 128>>>(f2c, w1b, V);
  combine_k<<<NIMG * 96, 256>>>();
  stripdelta_k<<<dim3(10, NIMG), 128>>>(f1, f2, w1);
  finalize1_k<<<(NIMG * 96 + 255) / 256, 256>>>();
  apply_x1cl_k<<<dim3(64, NIMG), 256>>>();

  // conv2 GEMM (+stats); finalize; apply
  gemm2_k<<<dim3(16, NIMG), 256, 71680>>>(x2cl);
  finalizeG_k<128, 16, 1536><<<NIMG, 128>>>();
  apply_cl128_k<<<dim3(32, NIMG), 256>>>(x2cl);

  // conv3 GEMM (+stats); finalize; apply
  gemm3_k<<<dim3(16, NIMG), 256, 71680>>>(x3cl);
  finalizeG_k<128, 16, 1536><<<NIMG, 128>>>();
  apply_cl128_k<<<dim3(32, NIMG), 256>>>(x3cl);

  // conv4 GEMM (+stats); finalize; apply
  gemm4_k<<<dim3(16, NIMG), 256, 51200>>>(x4cl);
  finalizeG_k<64, 16, 1536><<<NIMG, 64>>>();
  apply_cl64_k<<<dim3(32, NIMG), 256>>>(x4cl);

  // deconv GEMM (4 parities, +stats); finalize; apply -> planar x5
  gemm5_k<<<dim3(12, 4, NIMG), 256, 51200>>>();
  finalizeG_k<32, 48, 6144><<<NIMG, 32>>>();
  apply_x5_planar_k<<<dim3(32, NIMG), 256>>>();

  // final conv
  conv_final_k<<<dim3(24, NIMG), 256>>>(x5, w6, b6, out);
}